// round 10
// baseline (speedup 1.0000x reference)
#include <cuda_runtime.h>
#include <cuda_bf16.h>
#include <math.h>
#include <float.h>
#include <cstdint>

#define NN 50000
#define NE 800000
#define NBB 2000

// ---------------- scratch (static device globals; no allocation) ----------------
__device__ float g_feats [NN * 384];
__device__ float g_featsS[NN * 384];
__device__ float g_PQ [NN * 256];        // [P(128) | Q(128)] node stream
__device__ float g_PQs[NN * 256];        // super stream
__device__ float g_fusion[51200000];     // [NN, 1024]
__device__ float g_big[NBB * 2816];      // [pooled(1408) | fusionS(1024) | superFeats(384)]
__device__ float g_h1[NBB * 512];
__device__ float g_h2[NBB * 256];
__device__ float g_Wcn[8 * 256];         // layer0 combined weights [8, 256]
__device__ float g_Wcs[8 * 256];
__device__ float g_b256n[256];
__device__ float g_b256s[256];
__device__ int   g_hist[NN];
__device__ int   g_rowptr[NN + 1];
__device__ int   g_wcur[NN];
__device__ int   g_csr_src[NE];
__device__ int   g_csr_eid[NE];
__device__ int   g_bboxptr[NBB + 1];
__device__ int   g_bsum[256];
__device__ int   g_boff[256];
// bf16 split buffers
__device__ __align__(16) __nv_bfloat16 g_Ah[NN * 384];
__device__ __align__(16) __nv_bfloat16 g_Al[NN * 384];
__device__ __align__(16) __nv_bfloat16 g_Sh[NN * 384];
__device__ __align__(16) __nv_bfloat16 g_Sl[NN * 384];
__device__ __align__(16) __nv_bfloat16 g_Mh[NBB * 2816];
__device__ __align__(16) __nv_bfloat16 g_Ml[NBB * 2816];
__device__ __align__(16) __nv_bfloat16 g_Bfh[1024 * 384];
__device__ __align__(16) __nv_bfloat16 g_Bfl[1024 * 384];
__device__ __align__(16) __nv_bfloat16 g_Bfsh[1024 * 384];
__device__ __align__(16) __nv_bfloat16 g_Bfsl[1024 * 384];
__device__ __align__(16) __nv_bfloat16 g_B1h[512 * 2816];
__device__ __align__(16) __nv_bfloat16 g_B1l[512 * 2816];
__device__ __align__(16) __nv_bfloat16 g_wbh[2 * 256 * 128];
__device__ __align__(16) __nv_bfloat16 g_wbl[2 * 256 * 128];

// ---------------- CSR build ----------------
__global__ void k_count(const int* __restrict__ dst) {
    int e = blockIdx.x * blockDim.x + threadIdx.x;
    if (e < NE) atomicAdd(&g_hist[dst[e]], 1);
}

__device__ __forceinline__ int block_incl_scan256(int v, int tid) {
    __shared__ int ws[8];
    int x = v;
    #pragma unroll
    for (int o = 1; o < 32; o <<= 1) {
        int t = __shfl_up_sync(0xFFFFFFFFu, x, o);
        if ((tid & 31) >= o) x += t;
    }
    if ((tid & 31) == 31) ws[tid >> 5] = x;
    __syncthreads();
    if (tid < 8) {
        int w = ws[tid];
        #pragma unroll
        for (int o = 1; o < 8; o <<= 1) {
            int t = __shfl_up_sync(0xFFu, w, o);
            if (tid >= o) w += t;
        }
        ws[tid] = w;
    }
    __syncthreads();
    return x + ((tid >= 32) ? ws[(tid >> 5) - 1] : 0);
}

__global__ void k_scan1() {
    int tid = threadIdx.x;
    int i = blockIdx.x * 256 + tid;
    int v = (i < NN) ? g_hist[i] : 0;
    int incl = block_incl_scan256(v, tid);
    if (i < NN) g_rowptr[i + 1] = incl;
    if (tid == 255) g_bsum[blockIdx.x] = incl;
}
__global__ void k_scan2(int nblk) {
    int tid = threadIdx.x;
    int v = (tid < nblk) ? g_bsum[tid] : 0;
    int incl = block_incl_scan256(v, tid);
    if (tid < nblk) g_boff[tid] = incl - v;
}
__global__ void k_scan3() {
    int i = blockIdx.x * 256 + threadIdx.x;
    if (i < NN) {
        int r = g_rowptr[i + 1] + g_boff[blockIdx.x];
        g_rowptr[i + 1] = r;
        g_wcur[i] = r - g_hist[i];
    }
    if (i == 0) g_rowptr[0] = 0;
}

__global__ void k_fill(const int* __restrict__ src, const int* __restrict__ dst) {
    int e = blockIdx.x * blockDim.x + threadIdx.x;
    if (e < NE) {
        int d = dst[e];
        int pos = atomicAdd(&g_wcur[d], 1);
        g_csr_src[pos] = src[e];
        g_csr_eid[pos] = e;
    }
}

__global__ void k_bboxptr(const int* __restrict__ bbox_idx) {
    int b = blockIdx.x * blockDim.x + threadIdx.x;
    if (b <= NBB) {
        int lo = 0, hi = NN;
        while (lo < hi) {
            int mid = (lo + hi) >> 1;
            if (bbox_idx[mid] < b) lo = mid + 1; else hi = mid;
        }
        g_bboxptr[b] = lo;
    }
}

// layer0 combined weights: Wc[8,256] = [W1-W2 | W2], b256 = [0 | b]
__global__ void k_prep_head(const float* __restrict__ W, const float* __restrict__ bias,
                            float* __restrict__ Wc, float* __restrict__ b256) {
    int idx = blockIdx.x * blockDim.x + threadIdx.x;
    if (idx < 8 * 256) {
        int k = idx >> 8, n = idx & 255;
        float v = (n < 128) ? (W[k * 128 + n] - W[(8 + k) * 128 + n])
                            : W[(8 + k) * 128 + (n - 128)];
        Wc[idx] = v;
    }
    if (idx < 256) b256[idx] = (idx < 128) ? 0.f : bias[idx - 128];
}

// layer weight prep: W[262,128] -> split-transposed [256,128]
__global__ void k_prep_layerW(const float* __restrict__ W, const float* __restrict__ bias,
                              __nv_bfloat16* __restrict__ hi, __nv_bfloat16* __restrict__ lo,
                              float* __restrict__ bias256) {
    int idx = blockIdx.x * blockDim.x + threadIdx.x;
    if (idx < 256 * 128) {
        int n = idx >> 7, k = idx & 127;
        float v;
        if (n < 128) v = W[k * 128 + n] - W[(128 + k) * 128 + n];
        else         v = W[(128 + k) * 128 + (n - 128)];
        __nv_bfloat16 h = __float2bfloat16(v);
        hi[idx] = h;
        lo[idx] = __float2bfloat16(v - __bfloat162float(h));
    }
    if (idx < 256) bias256[idx] = (idx < 128) ? 0.f : bias[idx - 128];
}

// ---------------- bf16 split conversion ----------------
__global__ void k_split2(const float* __restrict__ A, int ldin,
                         __nv_bfloat16* __restrict__ hi, __nv_bfloat16* __restrict__ lo,
                         int M, int K) {
    int idx = blockIdx.x * blockDim.x + threadIdx.x;
    if (idx < M * K) {
        int row = idx / K, k = idx - row * K;
        float a = A[(size_t)row * ldin + k];
        __nv_bfloat16 h = __float2bfloat16(a);
        hi[idx] = h;
        lo[idx] = __float2bfloat16(a - __bfloat162float(h));
    }
}

// transpose+split: W[K,N] fp32 -> hi/lo [N,K] bf16
__global__ void k_wsplitT(const float* __restrict__ W,
                          __nv_bfloat16* __restrict__ hi, __nv_bfloat16* __restrict__ lo,
                          int K, int N) {
    int idx = blockIdx.x * blockDim.x + threadIdx.x;
    if (idx < K * N) {
        int nn = idx / K, kk = idx - nn * K;
        float a = W[(size_t)kk * N + nn];
        __nv_bfloat16 h = __float2bfloat16(a);
        hi[idx] = h;
        lo[idx] = __float2bfloat16(a - __bfloat162float(h));
    }
}

// ---------------- split-bf16 HMMA GEMM (cp.async pipeline + ldmatrix) ----------------
__device__ __forceinline__ void mma16816(float* c, const uint32_t* a, const uint32_t* b) {
    asm volatile(
        "mma.sync.aligned.m16n8k16.row.col.f32.bf16.bf16.f32 "
        "{%0,%1,%2,%3}, {%4,%5,%6,%7}, {%8,%9}, {%0,%1,%2,%3};"
        : "+f"(c[0]), "+f"(c[1]), "+f"(c[2]), "+f"(c[3])
        : "r"(a[0]), "r"(a[1]), "r"(a[2]), "r"(a[3]), "r"(b[0]), "r"(b[1]));
}
__device__ __forceinline__ void ldm4(uint32_t* r, uint32_t addr) {
    asm volatile("ldmatrix.sync.aligned.m8n8.x4.shared.b16 {%0,%1,%2,%3}, [%4];"
                 : "=r"(r[0]), "=r"(r[1]), "=r"(r[2]), "=r"(r[3]) : "r"(addr));
}
__device__ __forceinline__ void cp16(uint32_t dst, const void* src, int nbytes) {
    asm volatile("cp.async.cg.shared.global [%0], [%1], 16, %2;"
                 :: "r"(dst), "l"(src), "r"(nbytes));
}
__device__ __forceinline__ uint32_t smem_u32(const void* p) {
    uint32_t a;
    asm("{ .reg .u64 t; cvta.to.shared.u64 t, %1; cvt.u32.u64 %0, t; }" : "=r"(a) : "l"(p));
    return a;
}

#define SAS 40                   // smem row stride in halves
#define TILE_B (128 * SAS * 2)   // 10240 bytes per tile
#define STAGE_B (4 * TILE_B)     // 40960 bytes per stage
#define TCSM (2 * STAGE_B)       // 81920 dynamic smem

// GEMM core body (shared by single and dual variants)
template <bool BIAS, bool RELU>
__device__ __forceinline__ void mma_gemm_body(
    const __nv_bfloat16* __restrict__ Ahi, const __nv_bfloat16* __restrict__ Alo, int lda,
    const __nv_bfloat16* __restrict__ Bhi, const __nv_bfloat16* __restrict__ Blo,
    const float* __restrict__ bias, float* __restrict__ C, int ldc,
    int M, int K, char* smem)
{
    uint32_t sb = smem_u32(smem);
    int tid = threadIdx.x;
    int warp = tid >> 5, lane = tid & 31;
    int wm = warp & 1, wn = warp >> 1;
    int g = lane >> 2, q = lane & 3;
    int m0 = blockIdx.y * 128, n0 = blockIdx.x * 128;

    float acc[4][4][4];
    #pragma unroll
    for (int i = 0; i < 4; i++)
        #pragma unroll
        for (int j = 0; j < 4; j++)
            #pragma unroll
            for (int t = 0; t < 4; t++) acc[i][j][t] = 0.f;

    int nchunks = K >> 5;
    int lrow = tid >> 2, lseg = tid & 3;
    auto load_chunk = [&](int stg, int k0) {
        #pragma unroll
        for (int it = 0; it < 2; it++) {
            int row = lrow + it * 64;
            uint32_t soff = sb + stg * STAGE_B + (uint32_t)(row * SAS + lseg * 8) * 2;
            int gm = m0 + row;
            int pa = (gm < M) ? 16 : 0;
            int gmc = (gm < M) ? gm : (M - 1);
            cp16(soff,              Ahi + (size_t)gmc * lda + k0 + lseg * 8, pa);
            cp16(soff + TILE_B,     Alo + (size_t)gmc * lda + k0 + lseg * 8, pa);
            int gn = n0 + row;
            cp16(soff + 2 * TILE_B, Bhi + (size_t)gn * K + k0 + lseg * 8, 16);
            cp16(soff + 3 * TILE_B, Blo + (size_t)gn * K + k0 + lseg * 8, 16);
        }
        asm volatile("cp.async.commit_group;" ::: "memory");
    };

    uint32_t lm_off = (uint32_t)((wm * 64 + (lane & 15)) * SAS + (lane >> 4) * 8) * 2;

    load_chunk(0, 0);
    for (int c = 0; c < nchunks; c++) {
        if (c + 1 < nchunks) {
            load_chunk((c + 1) & 1, (c + 1) << 5);
            asm volatile("cp.async.wait_group 1;" ::: "memory");
        } else {
            asm volatile("cp.async.wait_group 0;" ::: "memory");
        }
        __syncthreads();

        uint32_t stage_u = sb + (c & 1) * STAGE_B;
        const __nv_bfloat16* sBh = (const __nv_bfloat16*)(smem + (c & 1) * STAGE_B + 2 * TILE_B);
        const __nv_bfloat16* sBl = sBh + 128 * SAS;

        #pragma unroll
        for (int ks = 0; ks < 2; ks++) {
            int kb = ks * 16;
            uint32_t a[4][4], bh[4][2], bl[2];
            #pragma unroll
            for (int mf = 0; mf < 4; mf++)
                ldm4(a[mf], stage_u + lm_off + (uint32_t)(mf * 16 * SAS + kb) * 2);
            #pragma unroll
            for (int nf = 0; nf < 4; nf++) {
                const __nv_bfloat16* bb = sBh + (wn * 32 + nf * 8 + g) * SAS + kb + q * 2;
                bh[nf][0] = *(const uint32_t*)bb;
                bh[nf][1] = *(const uint32_t*)(bb + 8);
            }
            #pragma unroll
            for (int nf = 0; nf < 4; nf++)
                #pragma unroll
                for (int mf = 0; mf < 4; mf++) mma16816(acc[mf][nf], a[mf], bh[nf]);
            #pragma unroll
            for (int nf = 0; nf < 4; nf++) {
                const __nv_bfloat16* bb = sBl + (wn * 32 + nf * 8 + g) * SAS + kb + q * 2;
                bl[0] = *(const uint32_t*)bb;
                bl[1] = *(const uint32_t*)(bb + 8);
                #pragma unroll
                for (int mf = 0; mf < 4; mf++) mma16816(acc[mf][nf], a[mf], bl);
            }
            #pragma unroll
            for (int mf = 0; mf < 4; mf++)
                ldm4(a[mf], stage_u + TILE_B + lm_off + (uint32_t)(mf * 16 * SAS + kb) * 2);
            #pragma unroll
            for (int nf = 0; nf < 4; nf++)
                #pragma unroll
                for (int mf = 0; mf < 4; mf++) mma16816(acc[mf][nf], a[mf], bh[nf]);
        }
        __syncthreads();
    }

    #pragma unroll
    for (int nf = 0; nf < 4; nf++) {
        int col = n0 + wn * 32 + nf * 8 + q * 2;
        float bv0 = 0.f, bv1 = 0.f;
        if (BIAS) { bv0 = __ldg(bias + col); bv1 = __ldg(bias + col + 1); }
        #pragma unroll
        for (int mf = 0; mf < 4; mf++) {
            int r = m0 + wm * 64 + mf * 16 + g;
            float v0 = acc[mf][nf][0] + bv0, v1 = acc[mf][nf][1] + bv1;
            float v2 = acc[mf][nf][2] + bv0, v3 = acc[mf][nf][3] + bv1;
            if (RELU) {
                v0 = fmaxf(v0, 0.f); v1 = fmaxf(v1, 0.f);
                v2 = fmaxf(v2, 0.f); v3 = fmaxf(v3, 0.f);
            }
            if (r < M)     *(float2*)&C[(size_t)r * ldc + col]       = make_float2(v0, v1);
            if (r + 8 < M) *(float2*)&C[(size_t)(r + 8) * ldc + col] = make_float2(v2, v3);
        }
    }
}

template <bool BIAS, bool RELU>
__global__ __launch_bounds__(256, 2) void k_mma_gemm(
    const __nv_bfloat16* __restrict__ Ahi, const __nv_bfloat16* __restrict__ Alo, int lda,
    const __nv_bfloat16* __restrict__ Bhi, const __nv_bfloat16* __restrict__ Blo,
    const float* __restrict__ bias, float* __restrict__ C, int ldc,
    int M, int K)
{
    extern __shared__ char smem[];
    mma_gemm_body<BIAS, RELU>(Ahi, Alo, lda, Bhi, Blo, bias, C, ldc, M, K, smem);
}

// dual-stream variant: blockIdx.z selects {node, super} pointer sets
__global__ __launch_bounds__(256, 2) void k_mma_gemm_dual(
    const __nv_bfloat16* __restrict__ Ahi0, const __nv_bfloat16* __restrict__ Alo0,
    const __nv_bfloat16* __restrict__ Ahi1, const __nv_bfloat16* __restrict__ Alo1, int lda,
    const __nv_bfloat16* __restrict__ Bhi0, const __nv_bfloat16* __restrict__ Blo0,
    const __nv_bfloat16* __restrict__ Bhi1, const __nv_bfloat16* __restrict__ Blo1,
    const float* __restrict__ bias0, const float* __restrict__ bias1,
    float* __restrict__ C0, float* __restrict__ C1, int ldc,
    int M, int K)
{
    extern __shared__ char smem[];
    if (blockIdx.z == 0)
        mma_gemm_body<true, false>(Ahi0, Alo0, lda, Bhi0, Blo0, bias0, C0, ldc, M, K, smem);
    else
        mma_gemm_body<true, false>(Ahi1, Alo1, lda, Bhi1, Blo1, bias1, C1, ldc, M, K, smem);
}

// ---------------- fp32 SIMT GEMMs ----------------
template <bool BIAS, bool RELU>
__global__ __launch_bounds__(256) void k_gemm128(
    const float* __restrict__ A, int lda, const float* __restrict__ B, int ldb,
    const float* __restrict__ bias, float* __restrict__ C, int ldc,
    int M, int N, int K)
{
    __shared__ float As[8][128];
    __shared__ float Bs[8][128];
    int tid = threadIdx.x;
    int m0 = blockIdx.y * 128, n0 = blockIdx.x * 128;
    int ar = tid >> 1, ac = (tid & 1) * 4;
    int bk = tid >> 5, bn = (tid & 31) * 4;
    int ty = tid >> 4, tx = tid & 15;
    float acc[8][8] = {};
    for (int k0 = 0; k0 < K; k0 += 8) {
        float4 av = make_float4(0.f, 0.f, 0.f, 0.f);
        if (m0 + ar < M) av = *(const float4*)&A[(size_t)(m0 + ar) * lda + k0 + ac];
        As[ac + 0][ar] = av.x; As[ac + 1][ar] = av.y; As[ac + 2][ar] = av.z; As[ac + 3][ar] = av.w;
        float4 bv = make_float4(0.f, 0.f, 0.f, 0.f);
        if (n0 + bn < N) bv = *(const float4*)&B[(size_t)(k0 + bk) * ldb + n0 + bn];
        *(float4*)&Bs[bk][bn] = bv;
        __syncthreads();
        #pragma unroll
        for (int kk = 0; kk < 8; kk++) {
            float a[8], b[8];
            #pragma unroll
            for (int i = 0; i < 8; i++) a[i] = As[kk][ty * 8 + i];
            #pragma unroll
            for (int j = 0; j < 8; j++) b[j] = Bs[kk][tx * 8 + j];
            #pragma unroll
            for (int i = 0; i < 8; i++)
                #pragma unroll
                for (int j = 0; j < 8; j++)
                    acc[i][j] += a[i] * b[j];
        }
        __syncthreads();
    }
    #pragma unroll
    for (int i = 0; i < 8; i++) {
        int m = m0 + ty * 8 + i;
        if (m < M) {
            #pragma unroll
            for (int j = 0; j < 8; j++) {
                int n = n0 + tx * 8 + j;
                if (n < N) {
                    float v = acc[i][j];
                    if (BIAS) v += bias[n];
                    if (RELU) v = fmaxf(v, 0.f);
                    C[(size_t)m * ldc + n] = v;
                }
            }
        }
    }
}

template <bool BIAS, bool RELU>
__global__ __launch_bounds__(256) void k_gemm64(
    const float* __restrict__ A, int lda, const float* __restrict__ B, int ldb,
    const float* __restrict__ bias, float* __restrict__ C, int ldc,
    int M, int N, int K)
{
    __shared__ float As[16][64];
    __shared__ float Bs[16][64];
    int tid = threadIdx.x;
    int m0 = blockIdx.y * 64, n0 = blockIdx.x * 64;
    int ar = tid >> 2, ac = (tid & 3) * 4;
    int bk = tid >> 4, bn = (tid & 15) * 4;
    int ty = tid >> 4, tx = tid & 15;
    float acc[4][4] = {};
    for (int k0 = 0; k0 < K; k0 += 16) {
        float4 av = make_float4(0.f, 0.f, 0.f, 0.f);
        if (m0 + ar < M) av = *(const float4*)&A[(size_t)(m0 + ar) * lda + k0 + ac];
        As[ac + 0][ar] = av.x; As[ac + 1][ar] = av.y; As[ac + 2][ar] = av.z; As[ac + 3][ar] = av.w;
        float4 bv = make_float4(0.f, 0.f, 0.f, 0.f);
        if (n0 + bn < N) bv = *(const float4*)&B[(size_t)(k0 + bk) * ldb + n0 + bn];
        *(float4*)&Bs[bk][bn] = bv;
        __syncthreads();
        #pragma unroll
        for (int kk = 0; kk < 16; kk++) {
            float a[4], b[4];
            #pragma unroll
            for (int i = 0; i < 4; i++) a[i] = As[kk][ty * 4 + i];
            #pragma unroll
            for (int j = 0; j < 4; j++) b[j] = Bs[kk][tx * 4 + j];
            #pragma unroll
            for (int i = 0; i < 4; i++)
                #pragma unroll
                for (int j = 0; j < 4; j++)
                    acc[i][j] += a[i] * b[j];
        }
        __syncthreads();
    }
    #pragma unroll
    for (int i = 0; i < 4; i++) {
        int m = m0 + ty * 4 + i;
        if (m < M) {
            #pragma unroll
            for (int j = 0; j < 4; j++) {
                int n = n0 + tx * 4 + j;
                if (n < N) {
                    float v = acc[i][j];
                    if (BIAS) v += bias[n];
                    if (RELU) v = fmaxf(v, 0.f);
                    C[(size_t)m * ldc + n] = v;
                }
            }
        }
    }
}

// ---------------- single-stream edge conv + residual + bf16 split ----------------
// MEAN=false: relu->max (node stream). MEAN=true: relu->mean (super stream).
__device__ __forceinline__ uint32_t bfpack(float a, float b) {
    return (uint32_t)__bfloat16_as_ushort(__float2bfloat16(a)) |
           ((uint32_t)__bfloat16_as_ushort(__float2bfloat16(b)) << 16);
}

template <bool MEAN>
__global__ __launch_bounds__(256) void k_edgeconv1(
    const float* __restrict__ e_attr,
    const float* __restrict__ W3,
    const float* __restrict__ PQ,
    const float* __restrict__ prev,
    float* __restrict__ outF,
    __nv_bfloat16* __restrict__ outH, __nv_bfloat16* __restrict__ outL)
{
    __shared__ float sW3[768];
    for (int i = threadIdx.x; i < 768; i += blockDim.x) sW3[i] = W3[i];
    __syncthreads();
    int warp = threadIdx.x >> 5, lane = threadIdx.x & 31;
    int node = blockIdx.x * (blockDim.x >> 5) + warp;
    if (node >= NN) return;
    int r0 = g_rowptr[node], r1 = g_rowptr[node + 1];
    int c = lane * 4;
    float4 qn = *(const float4*)(PQ + node * 256 + 128 + c);
    float ac0 = 0.f, ac1 = 0.f, ac2 = 0.f, ac3 = 0.f;
    for (int e = r0; e < r1; ++e) {
        int s  = g_csr_src[e];
        int id = g_csr_eid[e];
        float4 p = *(const float4*)(PQ + s * 256 + c);
        float a0 = p.x + qn.x, a1 = p.y + qn.y, a2 = p.z + qn.z, a3 = p.w + qn.w;
        #pragma unroll
        for (int k = 0; k < 6; k++) {
            float ev = __ldg(e_attr + (size_t)id * 6 + k);
            const float* wn = sW3 + k * 128 + c;
            a0 += ev * wn[0]; a1 += ev * wn[1]; a2 += ev * wn[2]; a3 += ev * wn[3];
        }
        a0 = fmaxf(a0, 0.f); a1 = fmaxf(a1, 0.f); a2 = fmaxf(a2, 0.f); a3 = fmaxf(a3, 0.f);
        if (MEAN) { ac0 += a0; ac1 += a1; ac2 += a2; ac3 += a3; }
        else { ac0 = fmaxf(ac0, a0); ac1 = fmaxf(ac1, a1); ac2 = fmaxf(ac2, a2); ac3 = fmaxf(ac3, a3); }
    }
    float f0 = ac0, f1 = ac1, f2 = ac2, f3 = ac3;
    if (MEAN) {
        int deg = r1 - r0;
        float inv = 1.f / (float)(deg > 0 ? deg : 1);
        f0 *= inv; f1 *= inv; f2 *= inv; f3 *= inv;
    }
    if (prev) {
        float4 pn = *(const float4*)(prev + node * 384 + c);
        f0 += pn.x; f1 += pn.y; f2 += pn.z; f3 += pn.w;
    }
    *(float4*)(outF + node * 384 + c) = make_float4(f0, f1, f2, f3);
    uint2 u;
    u.x = bfpack(f0, f1); u.y = bfpack(f2, f3);
    *(uint2*)(outH + node * 384 + c) = u;
    float r0f = f0 - __bfloat162float(__float2bfloat16(f0));
    float r1f = f1 - __bfloat162float(__float2bfloat16(f1));
    float r2f = f2 - __bfloat162float(__float2bfloat16(f2));
    float r3f = f3 - __bfloat162float(__float2bfloat16(f3));
    u.x = bfpack(r0f, r1f); u.y = bfpack(r2f, r3f);
    *(uint2*)(outL + node * 384 + c) = u;
}

// ---------------- bbox pooling ----------------
__global__ void k_pool_super() {   // mean + direct bf16 split for fusion_super input
    int b = blockIdx.x;
    int c = threadIdx.x;            // blockDim = 384
    int r0 = g_bboxptr[b], r1 = g_bboxptr[b + 1];
    float s = 0.f;
    for (int n = r0; n < r1; n++) s += g_featsS[n * 384 + c];
    int cnt = r1 - r0;
    float v = s / (float)(cnt > 0 ? cnt : 1);
    g_big[b * 2816 + 2432 + c] = v;
    __nv_bfloat16 h = __float2bfloat16(v);
    g_Mh[b * 384 + c] = h;
    g_Ml[b * 384 + c] = __float2bfloat16(v - __bfloat162float(h));
}

__global__ void k_pool_max() {
    int b = blockIdx.x;
    int r0 = g_bboxptr[b], r1 = g_bboxptr[b + 1];
    for (int c = threadIdx.x; c < 1408; c += blockDim.x) {
        float m = -FLT_MAX;
        if (c < 1024) {
            for (int n = r0; n < r1; n++) m = fmaxf(m, g_fusion[n * 1024 + c]);
        } else {
            int cc = c - 1024;
            for (int n = r0; n < r1; n++) m = fmaxf(m, g_feats[n * 384 + cc]);
        }
        if (r1 == r0) m = 0.f;
        g_big[b * 2816 + c] = m;
    }
}

// ---------------- launch ----------------
extern "C" void kernel_launch(void* const* d_in, const int* in_sizes, int n_in,
                              void* d_out, int out_size)
{
    const float* x     = (const float*)d_in[0];
    const float* eat   = (const float*)d_in[1];
    const float* W_h   = (const float*)d_in[2];
    const float* b_h   = (const float*)d_in[3];
    const float* Ws_h  = (const float*)d_in[4];
    const float* bs_h  = (const float*)d_in[5];
    const float* Wb    = (const float*)d_in[6];
    const float* bb    = (const float*)d_in[7];
    const float* Wbs   = (const float*)d_in[8];
    const float* bbs   = (const float*)d_in[9];
    const float* W_f   = (const float*)d_in[10];
    const float* b_f   = (const float*)d_in[11];
    const float* W_fs  = (const float*)d_in[12];
    const float* b_fs  = (const float*)d_in[13];
    const float* W1    = (const float*)d_in[14];
    const float* b1    = (const float*)d_in[15];
    const float* W2    = (const float*)d_in[16];
    const float* b2    = (const float*)d_in[17];
    const float* W3c   = (const float*)d_in[18];
    const float* b3    = (const float*)d_in[19];
    const int*   edge  = (const int*)d_in[20];
    const int*   bbox  = (const int*)d_in[21];
    const int* src = edge;
    const int* dst = edge + NE;
    float* out = (float*)d_out;

    float *pFeats, *pFeatsS, *pPQ, *pPQs, *pFus, *pBig, *pH1, *pH2, *pWcn, *pWcs, *pb256n, *pb256s;
    __nv_bfloat16 *pAh, *pAl, *pSh, *pSl, *pMh, *pMl;
    __nv_bfloat16 *pBfh, *pBfl, *pBfsh, *pBfsl, *pB1h, *pB1l, *pwbh, *pwbl;
    int *pHist;
    cudaGetSymbolAddress((void**)&pFeats,  g_feats);
    cudaGetSymbolAddress((void**)&pFeatsS, g_featsS);
    cudaGetSymbolAddress((void**)&pPQ,  g_PQ);
    cudaGetSymbolAddress((void**)&pPQs, g_PQs);
    cudaGetSymbolAddress((void**)&pFus, g_fusion);
    cudaGetSymbolAddress((void**)&pBig, g_big);
    cudaGetSymbolAddress((void**)&pH1,  g_h1);
    cudaGetSymbolAddress((void**)&pH2,  g_h2);
    cudaGetSymbolAddress((void**)&pWcn, g_Wcn);
    cudaGetSymbolAddress((void**)&pWcs, g_Wcs);
    cudaGetSymbolAddress((void**)&pb256n, g_b256n);
    cudaGetSymbolAddress((void**)&pb256s, g_b256s);
    cudaGetSymbolAddress((void**)&pHist, g_hist);
    cudaGetSymbolAddress((void**)&pAh, g_Ah);
    cudaGetSymbolAddress((void**)&pAl, g_Al);
    cudaGetSymbolAddress((void**)&pSh, g_Sh);
    cudaGetSymbolAddress((void**)&pSl, g_Sl);
    cudaGetSymbolAddress((void**)&pMh, g_Mh);
    cudaGetSymbolAddress((void**)&pMl, g_Ml);
    cudaGetSymbolAddress((void**)&pBfh, g_Bfh);
    cudaGetSymbolAddress((void**)&pBfl, g_Bfl);
    cudaGetSymbolAddress((void**)&pBfsh, g_Bfsh);
    cudaGetSymbolAddress((void**)&pBfsl, g_Bfsl);
    cudaGetSymbolAddress((void**)&pB1h, g_B1h);
    cudaGetSymbolAddress((void**)&pB1l, g_B1l);
    cudaGetSymbolAddress((void**)&pwbh, g_wbh);
    cudaGetSymbolAddress((void**)&pwbl, g_wbl);

    cudaFuncSetAttribute(k_mma_gemm<true, false>, cudaFuncAttributeMaxDynamicSharedMemorySize, TCSM);
    cudaFuncSetAttribute(k_mma_gemm<true, true>,  cudaFuncAttributeMaxDynamicSharedMemorySize, TCSM);
    cudaFuncSetAttribute(k_mma_gemm_dual,         cudaFuncAttributeMaxDynamicSharedMemorySize, TCSM);

    // CSR by dst + bbox ranges
    cudaMemsetAsync(pHist, 0, NN * sizeof(int), 0);
    k_count<<<(NE + 255) / 256, 256>>>(dst);
    int nblk = (NN + 255) / 256;
    k_scan1<<<nblk, 256>>>();
    k_scan2<<<1, 256>>>(nblk);
    k_scan3<<<nblk, 256>>>();
    k_fill<<<(NE + 255) / 256, 256>>>(src, dst);
    k_bboxptr<<<(NBB + 256) / 256, 256>>>(bbox);

    // big weight transpose+splits
    k_wsplitT<<<(1024 * 384 + 255) / 256, 256>>>(W_f,  pBfh,  pBfl,  384, 1024);
    k_wsplitT<<<(1024 * 384 + 255) / 256, 256>>>(W_fs, pBfsh, pBfsl, 384, 1024);
    k_wsplitT<<<(512 * 2816 + 255) / 256, 256>>>(W1,   pB1h,  pB1l,  2816, 512);

    const int EC_GRID = (NN + 7) / 8;

    // ---- layer 0 (inC=8): merged [8,256] fp32 SIMT GEMMs ----
    {
        k_prep_head<<<8, 256>>>(W_h,  b_h,  pWcn, pb256n);
        k_prep_head<<<8, 256>>>(Ws_h, bs_h, pWcs, pb256s);
        dim3 g1(2, (NN + 127) / 128);
        k_gemm128<true, false><<<g1, 256>>>(x, 8, pWcn, 256, pb256n, pPQ,  256, NN, 256, 8);
        k_gemm128<true, false><<<g1, 256>>>(x, 8, pWcs, 256, pb256s, pPQs, 256, NN, 256, 8);
        k_edgeconv1<false><<<EC_GRID, 256>>>(eat, W_h + 2048, pPQ, nullptr,
                                             pFeats, pAh, pAl);
        k_edgeconv1<true><<<EC_GRID, 256>>>(eat, Ws_h + 2048, pPQs, nullptr,
                                            pFeatsS, pSh, pSl);
    }

    // ---- layers 1,2: split-bf16 HMMA (node+super merged into one launch) ----
    for (int i = 1; i < 3; i++) {
        const float* W  = Wb  + (size_t)(i - 1) * 262 * 128;
        const float* b  = bb  + (i - 1) * 128;
        const float* Ws = Wbs + (size_t)(i - 1) * 262 * 128;
        const float* bs = bbs + (i - 1) * 128;
        const int nW = 256 * 128;

        k_prep_layerW<<<128, 256>>>(W,  b,  pwbh,      pwbl,      pb256n);
        k_prep_layerW<<<128, 256>>>(Ws, bs, pwbh + nW, pwbl + nW, pb256s);

        dim3 gl(2, (NN + 127) / 128, 2);
        k_mma_gemm_dual<<<gl, 256, TCSM>>>(
            pAh + (i - 1) * 128, pAl + (i - 1) * 128,
            pSh + (i - 1) * 128, pSl + (i - 1) * 128, 384,
            pwbh, pwbl, pwbh + nW, pwbl + nW,
            pb256n, pb256s, pPQ, pPQs, 256, NN, 128);

        k_edgeconv1<false><<<EC_GRID, 256>>>(eat, W + 2 * 128 * 128, pPQ,
                                             pFeats + (i - 1) * 128,
                                             pFeats + i * 128,
                                             pAh + i * 128, pAl + i * 128);
        k_edgeconv1<true><<<EC_GRID, 256>>>(eat, Ws + 2 * 128 * 128, pPQs,
                                            pFeatsS + (i - 1) * 128,
                                            pFeatsS + i * 128,
                                            pSh + i * 128, pSl + i * 128);
    }

    // ---- fusion: relu(feats @ W_f + b_f) -> [NN, 1024] ----
    {
        dim3 g(8, (NN + 127) / 128);
        k_mma_gemm<true, true><<<g, 256, TCSM>>>(pAh, pAl, 384, pBfh, pBfl, b_f, pFus, 1024, NN, 384);
    }

    // ---- bbox pooling (pool_super also emits split fusion_super input) ----
    k_pool_super<<<NBB, 384>>>();
    k_pool_max<<<NBB, 256>>>();

    // ---- fusion_super ----
    {
        dim3 g(8, (NBB + 127) / 128);
        k_mma_gemm<true, true><<<g, 256, TCSM>>>(pMh, pMl, 384, pBfsh, pBfsl, b_fs,
                                                 pBig + 1408, 2816, NBB, 384);
    }

    // ---- MLP head ----
    k_split2<<<(NBB * 2816 + 255) / 256, 256>>>(pBig, 2816, pMh, pMl, NBB, 2816);
    {
        dim3 g(4, (NBB + 127) / 128);
        k_mma_gemm<true, true><<<g, 256, TCSM>>>(pMh, pMl, 2816, pB1h, pB1l, b1, pH1, 512, NBB, 2816);
    }
    dim3 gm2(4, (NBB + 63) / 64);
    k_gemm64<true, true><<<gm2, 256>>>(pH1, 512, W2, 256, b2, pH2, 256, NBB, 256, 512);
    dim3 gm3(1, (NBB + 63) / 64);
    k_gemm64<true, false><<<gm3, 256>>>(pH2, 256, W3c, 32, b3, out, 32, NBB, 32, 256);
}

// round 11
// speedup vs baseline: 1.0622x; 1.0622x over previous
#include <cuda_runtime.h>
#include <cuda_bf16.h>
#include <math.h>
#include <float.h>
#include <cstdint>

#define NN 50000
#define NE 800000
#define NBB 2000

// ---------------- scratch (static device globals; no allocation) ----------------
__device__ float g_feats [NN * 384];
__device__ float g_featsS[NN * 384];
__device__ float g_PQ [NN * 256];        // [P(128) | Q(128)] node stream
__device__ float g_PQs[NN * 256];        // super stream
__device__ float g_fusion[51200000];     // [NN, 1024]
__device__ float g_big[NBB * 2816];      // [pooled(1408) | fusionS(1024) | superFeats(384)]
__device__ float g_h1[NBB * 512];
__device__ float g_h2[NBB * 256];
__device__ float g_Wcn[8 * 256];         // layer0 combined weights [8, 256]
__device__ float g_Wcs[8 * 256];
__device__ float g_b256n[256];
__device__ float g_b256s[256];
__device__ int   g_hist[NN];
__device__ int   g_rowptr[NN + 1];
__device__ int   g_wcur[NN];
__device__ int   g_csr_src[NE];
__device__ int   g_csr_eid[NE];
__device__ int   g_bboxptr[NBB + 1];
__device__ int   g_bsum[256];
__device__ int   g_boff[256];
// bf16 split buffers
__device__ __align__(16) __nv_bfloat16 g_Ah[NN * 384];
__device__ __align__(16) __nv_bfloat16 g_Al[NN * 384];
__device__ __align__(16) __nv_bfloat16 g_Sh[NN * 384];   // conv super splits; reused post-conv as fusion_super input
__device__ __align__(16) __nv_bfloat16 g_Sl[NN * 384];
__device__ __align__(16) __nv_bfloat16 g_Mh[NBB * 2816]; // MLP head split input
__device__ __align__(16) __nv_bfloat16 g_Ml[NBB * 2816];
__device__ __align__(16) __nv_bfloat16 g_Bfh[1024 * 384];
__device__ __align__(16) __nv_bfloat16 g_Bfl[1024 * 384];
__device__ __align__(16) __nv_bfloat16 g_Bfsh[1024 * 384];
__device__ __align__(16) __nv_bfloat16 g_Bfsl[1024 * 384];
__device__ __align__(16) __nv_bfloat16 g_B1h[512 * 2816];
__device__ __align__(16) __nv_bfloat16 g_B1l[512 * 2816];
__device__ __align__(16) __nv_bfloat16 g_wbh[2 * 256 * 128];
__device__ __align__(16) __nv_bfloat16 g_wbl[2 * 256 * 128];

// ---------------- CSR build ----------------
__global__ void k_count(const int* __restrict__ dst) {
    int e = blockIdx.x * blockDim.x + threadIdx.x;
    if (e < NE) atomicAdd(&g_hist[dst[e]], 1);
}

__device__ __forceinline__ int block_incl_scan256(int v, int tid) {
    __shared__ int ws[8];
    int x = v;
    #pragma unroll
    for (int o = 1; o < 32; o <<= 1) {
        int t = __shfl_up_sync(0xFFFFFFFFu, x, o);
        if ((tid & 31) >= o) x += t;
    }
    if ((tid & 31) == 31) ws[tid >> 5] = x;
    __syncthreads();
    if (tid < 8) {
        int w = ws[tid];
        #pragma unroll
        for (int o = 1; o < 8; o <<= 1) {
            int t = __shfl_up_sync(0xFFu, w, o);
            if (tid >= o) w += t;
        }
        ws[tid] = w;
    }
    __syncthreads();
    return x + ((tid >= 32) ? ws[(tid >> 5) - 1] : 0);
}

__global__ void k_scan1() {
    int tid = threadIdx.x;
    int i = blockIdx.x * 256 + tid;
    int v = (i < NN) ? g_hist[i] : 0;
    int incl = block_incl_scan256(v, tid);
    if (i < NN) g_rowptr[i + 1] = incl;
    if (tid == 255) g_bsum[blockIdx.x] = incl;
}
__global__ void k_scan2(int nblk) {
    int tid = threadIdx.x;
    int v = (tid < nblk) ? g_bsum[tid] : 0;
    int incl = block_incl_scan256(v, tid);
    if (tid < nblk) g_boff[tid] = incl - v;
}
__global__ void k_scan3() {
    int i = blockIdx.x * 256 + threadIdx.x;
    if (i < NN) {
        int r = g_rowptr[i + 1] + g_boff[blockIdx.x];
        g_rowptr[i + 1] = r;
        g_wcur[i] = r - g_hist[i];
    }
    if (i == 0) g_rowptr[0] = 0;
}

__global__ void k_fill(const int* __restrict__ src, const int* __restrict__ dst) {
    int e = blockIdx.x * blockDim.x + threadIdx.x;
    if (e < NE) {
        int d = dst[e];
        int pos = atomicAdd(&g_wcur[d], 1);
        g_csr_src[pos] = src[e];
        g_csr_eid[pos] = e;
    }
}

__global__ void k_bboxptr(const int* __restrict__ bbox_idx) {
    int b = blockIdx.x * blockDim.x + threadIdx.x;
    if (b <= NBB) {
        int lo = 0, hi = NN;
        while (lo < hi) {
            int mid = (lo + hi) >> 1;
            if (bbox_idx[mid] < b) lo = mid + 1; else hi = mid;
        }
        g_bboxptr[b] = lo;
    }
}

// layer0 combined weights: Wc[8,256] = [W1-W2 | W2], b256 = [0 | b]
__global__ void k_prep_head(const float* __restrict__ W, const float* __restrict__ bias,
                            float* __restrict__ Wc, float* __restrict__ b256) {
    int idx = blockIdx.x * blockDim.x + threadIdx.x;
    if (idx < 8 * 256) {
        int k = idx >> 8, n = idx & 255;
        float v = (n < 128) ? (W[k * 128 + n] - W[(8 + k) * 128 + n])
                            : W[(8 + k) * 128 + (n - 128)];
        Wc[idx] = v;
    }
    if (idx < 256) b256[idx] = (idx < 128) ? 0.f : bias[idx - 128];
}

// layer weight prep: W[262,128] -> split-transposed [256,128]
__global__ void k_prep_layerW(const float* __restrict__ W, const float* __restrict__ bias,
                              __nv_bfloat16* __restrict__ hi, __nv_bfloat16* __restrict__ lo,
                              float* __restrict__ bias256) {
    int idx = blockIdx.x * blockDim.x + threadIdx.x;
    if (idx < 256 * 128) {
        int n = idx >> 7, k = idx & 127;
        float v;
        if (n < 128) v = W[k * 128 + n] - W[(128 + k) * 128 + n];
        else         v = W[(128 + k) * 128 + (n - 128)];
        __nv_bfloat16 h = __float2bfloat16(v);
        hi[idx] = h;
        lo[idx] = __float2bfloat16(v - __bfloat162float(h));
    }
    if (idx < 256) bias256[idx] = (idx < 128) ? 0.f : bias[idx - 128];
}

// transpose+split: W[K,N] fp32 -> hi/lo [N,K] bf16
__global__ void k_wsplitT(const float* __restrict__ W,
                          __nv_bfloat16* __restrict__ hi, __nv_bfloat16* __restrict__ lo,
                          int K, int N) {
    int idx = blockIdx.x * blockDim.x + threadIdx.x;
    if (idx < K * N) {
        int nn = idx / K, kk = idx - nn * K;
        float a = W[(size_t)kk * N + nn];
        __nv_bfloat16 h = __float2bfloat16(a);
        hi[idx] = h;
        lo[idx] = __float2bfloat16(a - __bfloat162float(h));
    }
}

// ---------------- split-bf16 HMMA GEMM (cp.async pipeline + ldmatrix) ----------------
__device__ __forceinline__ void mma16816(float* c, const uint32_t* a, const uint32_t* b) {
    asm volatile(
        "mma.sync.aligned.m16n8k16.row.col.f32.bf16.bf16.f32 "
        "{%0,%1,%2,%3}, {%4,%5,%6,%7}, {%8,%9}, {%0,%1,%2,%3};"
        : "+f"(c[0]), "+f"(c[1]), "+f"(c[2]), "+f"(c[3])
        : "r"(a[0]), "r"(a[1]), "r"(a[2]), "r"(a[3]), "r"(b[0]), "r"(b[1]));
}
__device__ __forceinline__ void ldm4(uint32_t* r, uint32_t addr) {
    asm volatile("ldmatrix.sync.aligned.m8n8.x4.shared.b16 {%0,%1,%2,%3}, [%4];"
                 : "=r"(r[0]), "=r"(r[1]), "=r"(r[2]), "=r"(r[3]) : "r"(addr));
}
__device__ __forceinline__ void cp16(uint32_t dst, const void* src, int nbytes) {
    asm volatile("cp.async.cg.shared.global [%0], [%1], 16, %2;"
                 :: "r"(dst), "l"(src), "r"(nbytes));
}
__device__ __forceinline__ uint32_t smem_u32(const void* p) {
    uint32_t a;
    asm("{ .reg .u64 t; cvta.to.shared.u64 t, %1; cvt.u32.u64 %0, t; }" : "=r"(a) : "l"(p));
    return a;
}
__device__ __forceinline__ uint32_t bfpack(float a, float b) {
    return (uint32_t)__bfloat16_as_ushort(__float2bfloat16(a)) |
           ((uint32_t)__bfloat16_as_ushort(__float2bfloat16(b)) << 16);
}

#define SAS 40                   // smem row stride in halves
#define TILE_B (128 * SAS * 2)   // 10240 bytes per tile
#define STAGE_B (4 * TILE_B)     // 40960 bytes per stage
#define TCSM (2 * STAGE_B)       // 81920 dynamic smem

// GEMM core body; optional split-output epilogue (SplitH/SplitL at row*lds + scol + col)
template <bool BIAS, bool RELU, bool SPLIT>
__device__ __forceinline__ void mma_gemm_body(
    const __nv_bfloat16* __restrict__ Ahi, const __nv_bfloat16* __restrict__ Alo, int lda,
    const __nv_bfloat16* __restrict__ Bhi, const __nv_bfloat16* __restrict__ Blo,
    const float* __restrict__ bias, float* __restrict__ C, int ldc,
    int M, int K, char* smem,
    __nv_bfloat16* SplitH, __nv_bfloat16* SplitL, int lds, int scol)
{
    uint32_t sb = smem_u32(smem);
    int tid = threadIdx.x;
    int warp = tid >> 5, lane = tid & 31;
    int wm = warp & 1, wn = warp >> 1;
    int g = lane >> 2, q = lane & 3;
    int m0 = blockIdx.y * 128, n0 = blockIdx.x * 128;

    float acc[4][4][4];
    #pragma unroll
    for (int i = 0; i < 4; i++)
        #pragma unroll
        for (int j = 0; j < 4; j++)
            #pragma unroll
            for (int t = 0; t < 4; t++) acc[i][j][t] = 0.f;

    int nchunks = K >> 5;
    int lrow = tid >> 2, lseg = tid & 3;
    auto load_chunk = [&](int stg, int k0) {
        #pragma unroll
        for (int it = 0; it < 2; it++) {
            int row = lrow + it * 64;
            uint32_t soff = sb + stg * STAGE_B + (uint32_t)(row * SAS + lseg * 8) * 2;
            int gm = m0 + row;
            int pa = (gm < M) ? 16 : 0;
            int gmc = (gm < M) ? gm : (M - 1);
            cp16(soff,              Ahi + (size_t)gmc * lda + k0 + lseg * 8, pa);
            cp16(soff + TILE_B,     Alo + (size_t)gmc * lda + k0 + lseg * 8, pa);
            int gn = n0 + row;
            cp16(soff + 2 * TILE_B, Bhi + (size_t)gn * K + k0 + lseg * 8, 16);
            cp16(soff + 3 * TILE_B, Blo + (size_t)gn * K + k0 + lseg * 8, 16);
        }
        asm volatile("cp.async.commit_group;" ::: "memory");
    };

    uint32_t lm_off = (uint32_t)((wm * 64 + (lane & 15)) * SAS + (lane >> 4) * 8) * 2;

    load_chunk(0, 0);
    for (int c = 0; c < nchunks; c++) {
        if (c + 1 < nchunks) {
            load_chunk((c + 1) & 1, (c + 1) << 5);
            asm volatile("cp.async.wait_group 1;" ::: "memory");
        } else {
            asm volatile("cp.async.wait_group 0;" ::: "memory");
        }
        __syncthreads();

        uint32_t stage_u = sb + (c & 1) * STAGE_B;
        const __nv_bfloat16* sBh = (const __nv_bfloat16*)(smem + (c & 1) * STAGE_B + 2 * TILE_B);
        const __nv_bfloat16* sBl = sBh + 128 * SAS;

        #pragma unroll
        for (int ks = 0; ks < 2; ks++) {
            int kb = ks * 16;
            uint32_t a[4][4], bh[4][2], bl[2];
            #pragma unroll
            for (int mf = 0; mf < 4; mf++)
                ldm4(a[mf], stage_u + lm_off + (uint32_t)(mf * 16 * SAS + kb) * 2);
            #pragma unroll
            for (int nf = 0; nf < 4; nf++) {
                const __nv_bfloat16* bb = sBh + (wn * 32 + nf * 8 + g) * SAS + kb + q * 2;
                bh[nf][0] = *(const uint32_t*)bb;
                bh[nf][1] = *(const uint32_t*)(bb + 8);
            }
            #pragma unroll
            for (int nf = 0; nf < 4; nf++)
                #pragma unroll
                for (int mf = 0; mf < 4; mf++) mma16816(acc[mf][nf], a[mf], bh[nf]);
            #pragma unroll
            for (int nf = 0; nf < 4; nf++) {
                const __nv_bfloat16* bb = sBl + (wn * 32 + nf * 8 + g) * SAS + kb + q * 2;
                bl[0] = *(const uint32_t*)bb;
                bl[1] = *(const uint32_t*)(bb + 8);
                #pragma unroll
                for (int mf = 0; mf < 4; mf++) mma16816(acc[mf][nf], a[mf], bl);
            }
            #pragma unroll
            for (int mf = 0; mf < 4; mf++)
                ldm4(a[mf], stage_u + TILE_B + lm_off + (uint32_t)(mf * 16 * SAS + kb) * 2);
            #pragma unroll
            for (int nf = 0; nf < 4; nf++)
                #pragma unroll
                for (int mf = 0; mf < 4; mf++) mma16816(acc[mf][nf], a[mf], bh[nf]);
        }
        __syncthreads();
    }

    #pragma unroll
    for (int nf = 0; nf < 4; nf++) {
        int col = n0 + wn * 32 + nf * 8 + q * 2;
        float bv0 = 0.f, bv1 = 0.f;
        if (BIAS) { bv0 = __ldg(bias + col); bv1 = __ldg(bias + col + 1); }
        #pragma unroll
        for (int mf = 0; mf < 4; mf++) {
            int r = m0 + wm * 64 + mf * 16 + g;
            float v0 = acc[mf][nf][0] + bv0, v1 = acc[mf][nf][1] + bv1;
            float v2 = acc[mf][nf][2] + bv0, v3 = acc[mf][nf][3] + bv1;
            if (RELU) {
                v0 = fmaxf(v0, 0.f); v1 = fmaxf(v1, 0.f);
                v2 = fmaxf(v2, 0.f); v3 = fmaxf(v3, 0.f);
            }
            if (r < M) {
                *(float2*)&C[(size_t)r * ldc + col] = make_float2(v0, v1);
                if (SPLIT) {
                    SplitH[(size_t)r * lds + scol + col]     = __float2bfloat16(v0);
                    SplitH[(size_t)r * lds + scol + col + 1] = __float2bfloat16(v1);
                    float l0 = v0 - __bfloat162float(__float2bfloat16(v0));
                    float l1 = v1 - __bfloat162float(__float2bfloat16(v1));
                    SplitL[(size_t)r * lds + scol + col]     = __float2bfloat16(l0);
                    SplitL[(size_t)r * lds + scol + col + 1] = __float2bfloat16(l1);
                }
            }
            if (r + 8 < M) {
                *(float2*)&C[(size_t)(r + 8) * ldc + col] = make_float2(v2, v3);
                if (SPLIT) {
                    SplitH[(size_t)(r + 8) * lds + scol + col]     = __float2bfloat16(v2);
                    SplitH[(size_t)(r + 8) * lds + scol + col + 1] = __float2bfloat16(v3);
                    float l2 = v2 - __bfloat162float(__float2bfloat16(v2));
                    float l3 = v3 - __bfloat162float(__float2bfloat16(v3));
                    SplitL[(size_t)(r + 8) * lds + scol + col]     = __float2bfloat16(l2);
                    SplitL[(size_t)(r + 8) * lds + scol + col + 1] = __float2bfloat16(l3);
                }
            }
        }
    }
}

template <bool BIAS, bool RELU>
__global__ __launch_bounds__(256, 2) void k_mma_gemm(
    const __nv_bfloat16* __restrict__ Ahi, const __nv_bfloat16* __restrict__ Alo, int lda,
    const __nv_bfloat16* __restrict__ Bhi, const __nv_bfloat16* __restrict__ Blo,
    const float* __restrict__ bias, float* __restrict__ C, int ldc,
    int M, int K)
{
    extern __shared__ char smem[];
    mma_gemm_body<BIAS, RELU, false>(Ahi, Alo, lda, Bhi, Blo, bias, C, ldc, M, K, smem,
                                     nullptr, nullptr, 0, 0);
}

// GEMM + bf16 split output epilogue (for fusion_super feeding MLP head)
__global__ __launch_bounds__(256, 2) void k_mma_gemm_split(
    const __nv_bfloat16* __restrict__ Ahi, const __nv_bfloat16* __restrict__ Alo, int lda,
    const __nv_bfloat16* __restrict__ Bhi, const __nv_bfloat16* __restrict__ Blo,
    const float* __restrict__ bias, float* __restrict__ C, int ldc,
    int M, int K,
    __nv_bfloat16* SplitH, __nv_bfloat16* SplitL, int lds, int scol)
{
    extern __shared__ char smem[];
    mma_gemm_body<true, true, true>(Ahi, Alo, lda, Bhi, Blo, bias, C, ldc, M, K, smem,
                                    SplitH, SplitL, lds, scol);
}

// dual-stream variant: blockIdx.z selects {node, super} pointer sets
__global__ __launch_bounds__(256, 2) void k_mma_gemm_dual(
    const __nv_bfloat16* __restrict__ Ahi0, const __nv_bfloat16* __restrict__ Alo0,
    const __nv_bfloat16* __restrict__ Ahi1, const __nv_bfloat16* __restrict__ Alo1, int lda,
    const __nv_bfloat16* __restrict__ Bhi0, const __nv_bfloat16* __restrict__ Blo0,
    const __nv_bfloat16* __restrict__ Bhi1, const __nv_bfloat16* __restrict__ Blo1,
    const float* __restrict__ bias0, const float* __restrict__ bias1,
    float* __restrict__ C0, float* __restrict__ C1, int ldc,
    int M, int K)
{
    extern __shared__ char smem[];
    if (blockIdx.z == 0)
        mma_gemm_body<true, false, false>(Ahi0, Alo0, lda, Bhi0, Blo0, bias0, C0, ldc, M, K, smem,
                                          nullptr, nullptr, 0, 0);
    else
        mma_gemm_body<true, false, false>(Ahi1, Alo1, lda, Bhi1, Blo1, bias1, C1, ldc, M, K, smem,
                                          nullptr, nullptr, 0, 0);
}

// ---------------- fp32 SIMT GEMMs ----------------
template <bool BIAS, bool RELU>
__device__ __forceinline__ void gemm128_body(
    const float* __restrict__ A, int lda, const float* __restrict__ B, int ldb,
    const float* __restrict__ bias, float* __restrict__ C, int ldc,
    int M, int N, int K)
{
    __shared__ float As[8][128];
    __shared__ float Bs[8][128];
    int tid = threadIdx.x;
    int m0 = blockIdx.y * 128, n0 = blockIdx.x * 128;
    int ar = tid >> 1, ac = (tid & 1) * 4;
    int bk = tid >> 5, bn = (tid & 31) * 4;
    int ty = tid >> 4, tx = tid & 15;
    float acc[8][8] = {};
    for (int k0 = 0; k0 < K; k0 += 8) {
        float4 av = make_float4(0.f, 0.f, 0.f, 0.f);
        if (m0 + ar < M) av = *(const float4*)&A[(size_t)(m0 + ar) * lda + k0 + ac];
        As[ac + 0][ar] = av.x; As[ac + 1][ar] = av.y; As[ac + 2][ar] = av.z; As[ac + 3][ar] = av.w;
        float4 bv = make_float4(0.f, 0.f, 0.f, 0.f);
        if (n0 + bn < N) bv = *(const float4*)&B[(size_t)(k0 + bk) * ldb + n0 + bn];
        *(float4*)&Bs[bk][bn] = bv;
        __syncthreads();
        #pragma unroll
        for (int kk = 0; kk < 8; kk++) {
            float a[8], b[8];
            #pragma unroll
            for (int i = 0; i < 8; i++) a[i] = As[kk][ty * 8 + i];
            #pragma unroll
            for (int j = 0; j < 8; j++) b[j] = Bs[kk][tx * 8 + j];
            #pragma unroll
            for (int i = 0; i < 8; i++)
                #pragma unroll
                for (int j = 0; j < 8; j++)
                    acc[i][j] += a[i] * b[j];
        }
        __syncthreads();
    }
    #pragma unroll
    for (int i = 0; i < 8; i++) {
        int m = m0 + ty * 8 + i;
        if (m < M) {
            #pragma unroll
            for (int j = 0; j < 8; j++) {
                int n = n0 + tx * 8 + j;
                if (n < N) {
                    float v = acc[i][j];
                    if (BIAS) v += bias[n];
                    if (RELU) v = fmaxf(v, 0.f);
                    C[(size_t)m * ldc + n] = v;
                }
            }
        }
    }
}

template <bool BIAS, bool RELU>
__global__ __launch_bounds__(256) void k_gemm128(
    const float* __restrict__ A, int lda, const float* __restrict__ B, int ldb,
    const float* __restrict__ bias, float* __restrict__ C, int ldc,
    int M, int N, int K)
{
    gemm128_body<BIAS, RELU>(A, lda, B, ldb, bias, C, ldc, M, N, K);
}

// layer0 dual: z selects weight/bias/output set (same A)
__global__ __launch_bounds__(256) void k_gemm128_dual(
    const float* __restrict__ A, int lda,
    const float* __restrict__ B0, const float* __restrict__ B1, int ldb,
    const float* __restrict__ bias0, const float* __restrict__ bias1,
    float* __restrict__ C0, float* __restrict__ C1, int ldc,
    int M, int N, int K)
{
    if (blockIdx.z == 0)
        gemm128_body<true, false>(A, lda, B0, ldb, bias0, C0, ldc, M, N, K);
    else
        gemm128_body<true, false>(A, lda, B1, ldb, bias1, C1, ldc, M, N, K);
}

template <bool BIAS, bool RELU>
__global__ __launch_bounds__(256) void k_gemm64(
    const float* __restrict__ A, int lda, const float* __restrict__ B, int ldb,
    const float* __restrict__ bias, float* __restrict__ C, int ldc,
    int M, int N, int K)
{
    __shared__ float As[16][64];
    __shared__ float Bs[16][64];
    int tid = threadIdx.x;
    int m0 = blockIdx.y * 64, n0 = blockIdx.x * 64;
    int ar = tid >> 2, ac = (tid & 3) * 4;
    int bk = tid >> 4, bn = (tid & 15) * 4;
    int ty = tid >> 4, tx = tid & 15;
    float acc[4][4] = {};
    for (int k0 = 0; k0 < K; k0 += 16) {
        float4 av = make_float4(0.f, 0.f, 0.f, 0.f);
        if (m0 + ar < M) av = *(const float4*)&A[(size_t)(m0 + ar) * lda + k0 + ac];
        As[ac + 0][ar] = av.x; As[ac + 1][ar] = av.y; As[ac + 2][ar] = av.z; As[ac + 3][ar] = av.w;
        float4 bv = make_float4(0.f, 0.f, 0.f, 0.f);
        if (n0 + bn < N) bv = *(const float4*)&B[(size_t)(k0 + bk) * ldb + n0 + bn];
        *(float4*)&Bs[bk][bn] = bv;
        __syncthreads();
        #pragma unroll
        for (int kk = 0; kk < 16; kk++) {
            float a[4], b[4];
            #pragma unroll
            for (int i = 0; i < 4; i++) a[i] = As[kk][ty * 4 + i];
            #pragma unroll
            for (int j = 0; j < 4; j++) b[j] = Bs[kk][tx * 4 + j];
            #pragma unroll
            for (int i = 0; i < 4; i++)
                #pragma unroll
                for (int j = 0; j < 4; j++)
                    acc[i][j] += a[i] * b[j];
        }
        __syncthreads();
    }
    #pragma unroll
    for (int i = 0; i < 4; i++) {
        int m = m0 + ty * 4 + i;
        if (m < M) {
            #pragma unroll
            for (int j = 0; j < 4; j++) {
                int n = n0 + tx * 4 + j;
                if (n < N) {
                    float v = acc[i][j];
                    if (BIAS) v += bias[n];
                    if (RELU) v = fmaxf(v, 0.f);
                    C[(size_t)m * ldc + n] = v;
                }
            }
        }
    }
}

// ---------------- fused edge conv (R7/R9 body, frozen) + residual + bf16 split ----------------
__global__ __launch_bounds__(256) void k_edgeconv(
    const float* __restrict__ e_attr,
    const float* __restrict__ W3n, const float* __restrict__ W3s,
    const float* __restrict__ PQ, const float* __restrict__ PQs,
    const float* __restrict__ prevN, const float* __restrict__ prevS,
    float* __restrict__ outN, float* __restrict__ outS,
    __nv_bfloat16* __restrict__ outNh, __nv_bfloat16* __restrict__ outNl,
    __nv_bfloat16* __restrict__ outSh, __nv_bfloat16* __restrict__ outSl)
{
    __shared__ float sW3n[768];
    __shared__ float sW3s[768];
    for (int i = threadIdx.x; i < 768; i += blockDim.x) { sW3n[i] = W3n[i]; sW3s[i] = W3s[i]; }
    __syncthreads();
    int warp = threadIdx.x >> 5, lane = threadIdx.x & 31;
    int node = blockIdx.x * (blockDim.x >> 5) + warp;
    if (node >= NN) return;
    int r0 = g_rowptr[node], r1 = g_rowptr[node + 1];
    int c = lane * 4;
    float4 qn = *(const float4*)(PQ  + node * 256 + 128 + c);
    float4 qs = *(const float4*)(PQs + node * 256 + 128 + c);
    float mx0 = 0.f, mx1 = 0.f, mx2 = 0.f, mx3 = 0.f;
    float sm0 = 0.f, sm1 = 0.f, sm2 = 0.f, sm3 = 0.f;
    for (int e = r0; e < r1; ++e) {
        int s  = g_csr_src[e];
        int id = g_csr_eid[e];
        float4 p  = *(const float4*)(PQ  + s * 256 + c);
        float4 ps = *(const float4*)(PQs + s * 256 + c);
        float a0 = p.x + qn.x, a1 = p.y + qn.y, a2 = p.z + qn.z, a3 = p.w + qn.w;
        float b0 = ps.x + qs.x, b1 = ps.y + qs.y, b2 = ps.z + qs.z, b3 = ps.w + qs.w;
        #pragma unroll
        for (int k = 0; k < 6; k++) {
            float ev = __ldg(e_attr + (size_t)id * 6 + k);
            const float* wn = sW3n + k * 128 + c;
            const float* ws = sW3s + k * 128 + c;
            a0 += ev * wn[0]; a1 += ev * wn[1]; a2 += ev * wn[2]; a3 += ev * wn[3];
            b0 += ev * ws[0]; b1 += ev * ws[1]; b2 += ev * ws[2]; b3 += ev * ws[3];
        }
        a0 = fmaxf(a0, 0.f); a1 = fmaxf(a1, 0.f); a2 = fmaxf(a2, 0.f); a3 = fmaxf(a3, 0.f);
        mx0 = fmaxf(mx0, a0); mx1 = fmaxf(mx1, a1); mx2 = fmaxf(mx2, a2); mx3 = fmaxf(mx3, a3);
        b0 = fmaxf(b0, 0.f); b1 = fmaxf(b1, 0.f); b2 = fmaxf(b2, 0.f); b3 = fmaxf(b3, 0.f);
        sm0 += b0; sm1 += b1; sm2 += b2; sm3 += b3;
    }
    int deg = r1 - r0;
    float inv = 1.f / (float)(deg > 0 ? deg : 1);
    float f0 = mx0, f1 = mx1, f2 = mx2, f3 = mx3;
    float s0 = sm0 * inv, s1 = sm1 * inv, s2 = sm2 * inv, s3 = sm3 * inv;
    if (prevN) {
        float4 pn = *(const float4*)(prevN + node * 384 + c);
        f0 += pn.x; f1 += pn.y; f2 += pn.z; f3 += pn.w;
        float4 pv = *(const float4*)(prevS + node * 384 + c);
        s0 += pv.x; s1 += pv.y; s2 += pv.z; s3 += pv.w;
    }
    *(float4*)(outN + node * 384 + c) = make_float4(f0, f1, f2, f3);
    *(float4*)(outS + node * 384 + c) = make_float4(s0, s1, s2, s3);
    uint2 u;
    u.x = bfpack(f0, f1); u.y = bfpack(f2, f3);
    *(uint2*)(outNh + node * 384 + c) = u;
    float r0f = f0 - __bfloat162float(__float2bfloat16(f0));
    float r1f = f1 - __bfloat162float(__float2bfloat16(f1));
    float r2f = f2 - __bfloat162float(__float2bfloat16(f2));
    float r3f = f3 - __bfloat162float(__float2bfloat16(f3));
    u.x = bfpack(r0f, r1f); u.y = bfpack(r2f, r3f);
    *(uint2*)(outNl + node * 384 + c) = u;
    u.x = bfpack(s0, s1); u.y = bfpack(s2, s3);
    *(uint2*)(outSh + node * 384 + c) = u;
    r0f = s0 - __bfloat162float(__float2bfloat16(s0));
    r1f = s1 - __bfloat162float(__float2bfloat16(s1));
    r2f = s2 - __bfloat162float(__float2bfloat16(s2));
    r3f = s3 - __bfloat162float(__float2bfloat16(s3));
    u.x = bfpack(r0f, r1f); u.y = bfpack(r2f, r3f);
    *(uint2*)(outSl + node * 384 + c) = u;
}

// ---------------- bbox pooling ----------------
// mean of featsS; fp32 -> g_big[.,2432+], split -> Sh/Sl (fusion_super GEMM input, [NBB,384])
// and Mh/Ml at [., 2432+] (MLP head input)
__global__ void k_pool_super() {
    int b = blockIdx.x;
    int c = threadIdx.x;            // blockDim = 384
    int r0 = g_bboxptr[b], r1 = g_bboxptr[b + 1];
    float s = 0.f;
    for (int n = r0; n < r1; n++) s += g_featsS[n * 384 + c];
    int cnt = r1 - r0;
    float v = s / (float)(cnt > 0 ? cnt : 1);
    g_big[b * 2816 + 2432 + c] = v;
    __nv_bfloat16 h = __float2bfloat16(v);
    __nv_bfloat16 l = __float2bfloat16(v - __bfloat162float(h));
    g_Sh[b * 384 + c] = h;
    g_Sl[b * 384 + c] = l;
    g_Mh[b * 2816 + 2432 + c] = h;
    g_Ml[b * 2816 + 2432 + c] = l;
}

// max of [fusion | feats]; fp32 -> g_big[., 0..1408), split -> Mh/Ml same cols
__global__ void k_pool_max() {
    int b = blockIdx.x;
    int r0 = g_bboxptr[b], r1 = g_bboxptr[b + 1];
    for (int c = threadIdx.x; c < 1408; c += blockDim.x) {
        float m = -FLT_MAX;
        if (c < 1024) {
            for (int n = r0; n < r1; n++) m = fmaxf(m, g_fusion[n * 1024 + c]);
        } else {
            int cc = c - 1024;
            for (int n = r0; n < r1; n++) m = fmaxf(m, g_feats[n * 384 + cc]);
        }
        if (r1 == r0) m = 0.f;
        g_big[b * 2816 + c] = m;
        __nv_bfloat16 h = __float2bfloat16(m);
        g_Mh[b * 2816 + c] = h;
        g_Ml[b * 2816 + c] = __float2bfloat16(m - __bfloat162float(h));
    }
}

// ---------------- launch ----------------
extern "C" void kernel_launch(void* const* d_in, const int* in_sizes, int n_in,
                              void* d_out, int out_size)
{
    const float* x     = (const float*)d_in[0];
    const float* eat   = (const float*)d_in[1];
    const float* W_h   = (const float*)d_in[2];
    const float* b_h   = (const float*)d_in[3];
    const float* Ws_h  = (const float*)d_in[4];
    const float* bs_h  = (const float*)d_in[5];
    const float* Wb    = (const float*)d_in[6];
    const float* bb    = (const float*)d_in[7];
    const float* Wbs   = (const float*)d_in[8];
    const float* bbs   = (const float*)d_in[9];
    const float* W_f   = (const float*)d_in[10];
    const float* b_f   = (const float*)d_in[11];
    const float* W_fs  = (const float*)d_in[12];
    const float* b_fs  = (const float*)d_in[13];
    const float* W1    = (const float*)d_in[14];
    const float* b1    = (const float*)d_in[15];
    const float* W2    = (const float*)d_in[16];
    const float* b2    = (const float*)d_in[17];
    const float* W3c   = (const float*)d_in[18];
    const float* b3    = (const float*)d_in[19];
    const int*   edge  = (const int*)d_in[20];
    const int*   bbox  = (const int*)d_in[21];
    const int* src = edge;
    const int* dst = edge + NE;
    float* out = (float*)d_out;

    float *pFeats, *pFeatsS, *pPQ, *pPQs, *pFus, *pBig, *pH1, *pH2, *pWcn, *pWcs, *pb256n, *pb256s;
    __nv_bfloat16 *pAh, *pAl, *pSh, *pSl, *pMh, *pMl;
    __nv_bfloat16 *pBfh, *pBfl, *pBfsh, *pBfsl, *pB1h, *pB1l, *pwbh, *pwbl;
    int *pHist;
    cudaGetSymbolAddress((void**)&pFeats,  g_feats);
    cudaGetSymbolAddress((void**)&pFeatsS, g_featsS);
    cudaGetSymbolAddress((void**)&pPQ,  g_PQ);
    cudaGetSymbolAddress((void**)&pPQs, g_PQs);
    cudaGetSymbolAddress((void**)&pFus, g_fusion);
    cudaGetSymbolAddress((void**)&pBig, g_big);
    cudaGetSymbolAddress((void**)&pH1,  g_h1);
    cudaGetSymbolAddress((void**)&pH2,  g_h2);
    cudaGetSymbolAddress((void**)&pWcn, g_Wcn);
    cudaGetSymbolAddress((void**)&pWcs, g_Wcs);
    cudaGetSymbolAddress((void**)&pb256n, g_b256n);
    cudaGetSymbolAddress((void**)&pb256s, g_b256s);
    cudaGetSymbolAddress((void**)&pHist, g_hist);
    cudaGetSymbolAddress((void**)&pAh, g_Ah);
    cudaGetSymbolAddress((void**)&pAl, g_Al);
    cudaGetSymbolAddress((void**)&pSh, g_Sh);
    cudaGetSymbolAddress((void**)&pSl, g_Sl);
    cudaGetSymbolAddress((void**)&pMh, g_Mh);
    cudaGetSymbolAddress((void**)&pMl, g_Ml);
    cudaGetSymbolAddress((void**)&pBfh, g_Bfh);
    cudaGetSymbolAddress((void**)&pBfl, g_Bfl);
    cudaGetSymbolAddress((void**)&pBfsh, g_Bfsh);
    cudaGetSymbolAddress((void**)&pBfsl, g_Bfsl);
    cudaGetSymbolAddress((void**)&pB1h, g_B1h);
    cudaGetSymbolAddress((void**)&pB1l, g_B1l);
    cudaGetSymbolAddress((void**)&pwbh, g_wbh);
    cudaGetSymbolAddress((void**)&pwbl, g_wbl);

    cudaFuncSetAttribute(k_mma_gemm<true, false>, cudaFuncAttributeMaxDynamicSharedMemorySize, TCSM);
    cudaFuncSetAttribute(k_mma_gemm<true, true>,  cudaFuncAttributeMaxDynamicSharedMemorySize, TCSM);
    cudaFuncSetAttribute(k_mma_gemm_dual,         cudaFuncAttributeMaxDynamicSharedMemorySize, TCSM);
    cudaFuncSetAttribute(k_mma_gemm_split,        cudaFuncAttributeMaxDynamicSharedMemorySize, TCSM);

    // CSR by dst + bbox ranges
    cudaMemsetAsync(pHist, 0, NN * sizeof(int), 0);
    k_count<<<(NE + 255) / 256, 256>>>(dst);
    int nblk = (NN + 255) / 256;
    k_scan1<<<nblk, 256>>>();
    k_scan2<<<1, 256>>>(nblk);
    k_scan3<<<nblk, 256>>>();
    k_fill<<<(NE + 255) / 256, 256>>>(src, dst);
    k_bboxptr<<<(NBB + 256) / 256, 256>>>(bbox);

    // big weight transpose+splits
    k_wsplitT<<<(1024 * 384 + 255) / 256, 256>>>(W_f,  pBfh,  pBfl,  384, 1024);
    k_wsplitT<<<(1024 * 384 + 255) / 256, 256>>>(W_fs, pBfsh, pBfsl, 384, 1024);
    k_wsplitT<<<(512 * 2816 + 255) / 256, 256>>>(W1,   pB1h,  pB1l,  2816, 512);

    // ---- layer 0 (inC=8): merged [8,256] fp32 SIMT GEMMs, one dual launch ----
    {
        k_prep_head<<<8, 256>>>(W_h,  b_h,  pWcn, pb256n);
        k_prep_head<<<8, 256>>>(Ws_h, bs_h, pWcs, pb256s);
        dim3 g1(2, (NN + 127) / 128, 2);
        k_gemm128_dual<<<g1, 256>>>(x, 8, pWcn, pWcs, 256, pb256n, pb256s,
                                    pPQ, pPQs, 256, NN, 256, 8);
        k_edgeconv<<<(NN + 7) / 8, 256>>>(eat, W_h + 2048, Ws_h + 2048,
                                          pPQ, pPQs, nullptr, nullptr,
                                          pFeats, pFeatsS,
                                          pAh, pAl, pSh, pSl);
    }

    // ---- layers 1,2: split-bf16 HMMA (node+super merged into one launch) ----
    for (int i = 1; i < 3; i++) {
        const float* W  = Wb  + (size_t)(i - 1) * 262 * 128;
        const float* b  = bb  + (i - 1) * 128;
        const float* Ws = Wbs + (size_t)(i - 1) * 262 * 128;
        const float* bs = bbs + (i - 1) * 128;
        const int nW = 256 * 128;

        k_prep_layerW<<<128, 256>>>(W,  b,  pwbh,      pwbl,      pb256n);
        k_prep_layerW<<<128, 256>>>(Ws, bs, pwbh + nW, pwbl + nW, pb256s);

        dim3 gl(2, (NN + 127) / 128, 2);
        k_mma_gemm_dual<<<gl, 256, TCSM>>>(
            pAh + (i - 1) * 128, pAl + (i - 1) * 128,
            pSh + (i - 1) * 128, pSl + (i - 1) * 128, 384,
            pwbh, pwbl, pwbh + nW, pwbl + nW,
            pb256n, pb256s, pPQ, pPQs, 256, NN, 128);

        k_edgeconv<<<(NN + 7) / 8, 256>>>(eat, W + 2 * 128 * 128, Ws + 2 * 128 * 128,
                                          pPQ, pPQs,
                                          pFeats + (i - 1) * 128, pFeatsS + (i - 1) * 128,
                                          pFeats + i * 128, pFeatsS + i * 128,
                                          pAh + i * 128, pAl + i * 128,
                                          pSh + i * 128, pSl + i * 128);
    }

    // ---- fusion: relu(feats @ W_f + b_f) -> [NN, 1024] ----
    {
        dim3 g(8, (NN + 127) / 128);
        k_mma_gemm<true, true><<<g, 256, TCSM>>>(pAh, pAl, 384, pBfh, pBfl, b_f, pFus, 1024, NN, 384);
    }

    // ---- bbox pooling (both emit split MLP inputs; pool_super also emits fusion_super input) ----
    k_pool_super<<<NBB, 384>>>();
    k_pool_max<<<NBB, 256>>>();

    // ---- fusion_super (split epilogue feeds MLP input cols [1408, 2432)) ----
    {
        dim3 g(8, (NBB + 127) / 128);
        k_mma_gemm_split<<<g, 256, TCSM>>>(pSh, pSl, 384, pBfsh, pBfsl, b_fs,
                                           pBig + 1408, 2816, NBB, 384,
                                           pMh, pMl, 2816, 1408);
    }

    // ---- MLP head (split input assembled in-place; no k_split2) ----
    {
        dim3 g(4, (NBB + 127) / 128);
        k_mma_gemm<true, true><<<g, 256, TCSM>>>(pMh, pMl, 2816, pB1h, pB1l, b1, pH1, 512, NBB, 2816);
    }
    dim3 gm2(4, (NBB + 63) / 64);
    k_gemm64<true, true><<<gm2, 256>>>(pH1, 512, W2, 256, b2, pH2, 256, NBB, 256, 512);
    dim3 gm3(1, (NBB + 63) / 64);
    k_gemm64<true, false><<<gm3, 256>>>(pH2, 256, W3c, 32, b3, out, 32, NBB, 32, 256);
}

// round 13
// speedup vs baseline: 1.0738x; 1.0109x over previous
#include <cuda_runtime.h>
#include <cuda_bf16.h>
#include <math.h>
#include <float.h>
#include <cstdint>

#define NN 50000
#define NE 800000
#define NBB 2000

// ---------------- scratch (static device globals; no allocation) ----------------
__device__ float g_feats [NN * 384];
__device__ float g_featsS[NN * 384];
__device__ float g_PQ [NN * 256];        // [P(128) | Q(128)] node stream
__device__ float g_PQs[NN * 256];        // super stream
__device__ float g_fusion[51200000];     // [NN, 1024]
__device__ float g_big[NBB * 2816];      // [pooled(1408) | fusionS(1024) | superFeats(384)]
__device__ float g_h1[NBB * 512];
__device__ float g_h2[NBB * 256];
__device__ float g_Wcn[8 * 256];         // layer0 combined weights [8, 256]
__device__ float g_Wcs[8 * 256];
__device__ float g_b256h[512];           // layer0 biases [node | super]
__device__ float g_b256[4 * 256];        // layer1,2 biases [L1n, L1s, L2n, L2s]
__device__ int   g_hist[NN];
__device__ int   g_rowptr[NN + 1];
__device__ int   g_wcur[NN];
__device__ int   g_csr_src[NE];
__device__ int   g_csr_eid[NE];
__device__ int   g_bboxptr[NBB + 1];
__device__ int   g_bsum[256];
__device__ int   g_boff[256];
// bf16 split buffers
__device__ __align__(16) __nv_bfloat16 g_Ah[NN * 384];
__device__ __align__(16) __nv_bfloat16 g_Al[NN * 384];
__device__ __align__(16) __nv_bfloat16 g_Sh[NN * 384];   // conv super splits; reused post-conv as fusion_super input
__device__ __align__(16) __nv_bfloat16 g_Sl[NN * 384];
__device__ __align__(16) __nv_bfloat16 g_Mh[NBB * 2816]; // MLP head split input
__device__ __align__(16) __nv_bfloat16 g_Ml[NBB * 2816];
__device__ __align__(16) __nv_bfloat16 g_Bfh[1024 * 384];
__device__ __align__(16) __nv_bfloat16 g_Bfl[1024 * 384];
__device__ __align__(16) __nv_bfloat16 g_Bfsh[1024 * 384];
__device__ __align__(16) __nv_bfloat16 g_Bfsl[1024 * 384];
__device__ __align__(16) __nv_bfloat16 g_B1h[512 * 2816];
__device__ __align__(16) __nv_bfloat16 g_B1l[512 * 2816];
__device__ __align__(16) __nv_bfloat16 g_wbh[4 * 256 * 128];  // [L1n, L1s, L2n, L2s]
__device__ __align__(16) __nv_bfloat16 g_wbl[4 * 256 * 128];

// ---------------- CSR build ----------------
__global__ void k_count(const int* __restrict__ dst) {
    int e = blockIdx.x * blockDim.x + threadIdx.x;
    if (e < NE) atomicAdd(&g_hist[dst[e]], 1);
}

__device__ __forceinline__ int block_incl_scan256(int v, int tid) {
    __shared__ int ws[8];
    int x = v;
    #pragma unroll
    for (int o = 1; o < 32; o <<= 1) {
        int t = __shfl_up_sync(0xFFFFFFFFu, x, o);
        if ((tid & 31) >= o) x += t;
    }
    if ((tid & 31) == 31) ws[tid >> 5] = x;
    __syncthreads();
    if (tid < 8) {
        int w = ws[tid];
        #pragma unroll
        for (int o = 1; o < 8; o <<= 1) {
            int t = __shfl_up_sync(0xFFu, w, o);
            if (tid >= o) w += t;
        }
        ws[tid] = w;
    }
    __syncthreads();
    return x + ((tid >= 32) ? ws[(tid >> 5) - 1] : 0);
}

__global__ void k_scan1() {
    int tid = threadIdx.x;
    int i = blockIdx.x * 256 + tid;
    int v = (i < NN) ? g_hist[i] : 0;
    int incl = block_incl_scan256(v, tid);
    if (i < NN) g_rowptr[i + 1] = incl;
    if (tid == 255) g_bsum[blockIdx.x] = incl;
}
__global__ void k_scan2(int nblk) {
    int tid = threadIdx.x;
    int v = (tid < nblk) ? g_bsum[tid] : 0;
    int incl = block_incl_scan256(v, tid);
    if (tid < nblk) g_boff[tid] = incl - v;
}
// scan3 + bbox range search folded together
__global__ void k_scan3(const int* __restrict__ bbox_idx) {
    int i = blockIdx.x * 256 + threadIdx.x;
    if (i < NN) {
        int r = g_rowptr[i + 1] + g_boff[blockIdx.x];
        g_rowptr[i + 1] = r;
        g_wcur[i] = r - g_hist[i];
    }
    if (i == 0) g_rowptr[0] = 0;
    if (i <= NBB) {
        int lo = 0, hi = NN;
        while (lo < hi) {
            int mid = (lo + hi) >> 1;
            if (bbox_idx[mid] < i) lo = mid + 1; else hi = mid;
        }
        g_bboxptr[i] = lo;
    }
}

__global__ void k_fill(const int* __restrict__ src, const int* __restrict__ dst) {
    int e = blockIdx.x * blockDim.x + threadIdx.x;
    if (e < NE) {
        int d = dst[e];
        int pos = atomicAdd(&g_wcur[d], 1);
        g_csr_src[pos] = src[e];
        g_csr_eid[pos] = e;
    }
}

// layer0 combined weights, both streams in one launch (z selects)
__global__ void k_prep_head_dual(const float* __restrict__ Wn, const float* __restrict__ bn,
                                 const float* __restrict__ Ws, const float* __restrict__ bs) {
    const float* W    = blockIdx.z ? Ws : Wn;
    const float* bias = blockIdx.z ? bs : bn;
    float* Wc   = blockIdx.z ? g_Wcs : g_Wcn;
    float* b256 = g_b256h + blockIdx.z * 256;
    int idx = blockIdx.x * blockDim.x + threadIdx.x;
    if (idx < 8 * 256) {
        int k = idx >> 8, n = idx & 255;
        float v = (n < 128) ? (W[k * 128 + n] - W[(8 + k) * 128 + n])
                            : W[(8 + k) * 128 + (n - 128)];
        Wc[idx] = v;
    }
    if (idx < 256) b256[idx] = (idx < 128) ? 0.f : bias[idx - 128];
}

// all 4 layer-weight preps in one launch: z = 2*(layer-1) + stream
__global__ void k_prep_layerW_all(const float* __restrict__ Wb, const float* __restrict__ bb,
                                  const float* __restrict__ Wbs, const float* __restrict__ bbs) {
    int z = blockIdx.z;
    int li = z >> 1, st = z & 1;
    const float* W    = (st ? Wbs : Wb)  + (size_t)li * 262 * 128;
    const float* bias = (st ? bbs : bb)  + li * 128;
    __nv_bfloat16* hi = g_wbh + (size_t)z * 256 * 128;
    __nv_bfloat16* lo = g_wbl + (size_t)z * 256 * 128;
    float* bias256 = g_b256 + z * 256;
    int idx = blockIdx.x * blockDim.x + threadIdx.x;
    if (idx < 256 * 128) {
        int n = idx >> 7, k = idx & 127;
        float v;
        if (n < 128) v = W[k * 128 + n] - W[(128 + k) * 128 + n];
        else         v = W[(128 + k) * 128 + (n - 128)];
        __nv_bfloat16 h = __float2bfloat16(v);
        hi[idx] = h;
        lo[idx] = __float2bfloat16(v - __bfloat162float(h));
    }
    if (idx < 256) bias256[idx] = (idx < 128) ? 0.f : bias[idx - 128];
}

// 3 big weight transpose+splits in one launch: z = {W_f, W_fs, W1}
__global__ void k_wsplit3(const float* __restrict__ W_f,
                          const float* __restrict__ W_fs,
                          const float* __restrict__ W1) {
    int z = blockIdx.z;
    const float* W;
    __nv_bfloat16 *hi, *lo;
    int K, N;
    if (z == 0)      { W = W_f;  hi = g_Bfh;  lo = g_Bfl;  K = 384;  N = 1024; }
    else if (z == 1) { W = W_fs; hi = g_Bfsh; lo = g_Bfsl; K = 384;  N = 1024; }
    else             { W = W1;   hi = g_B1h;  lo = g_B1l;  K = 2816; N = 512; }
    int idx = blockIdx.x * blockDim.x + threadIdx.x;
    if (idx < K * N) {
        int nn = idx / K, kk = idx - nn * K;
        float a = W[(size_t)kk * N + nn];
        __nv_bfloat16 h = __float2bfloat16(a);
        hi[idx] = h;
        lo[idx] = __float2bfloat16(a - __bfloat162float(h));
    }
}

// ---------------- split-bf16 HMMA GEMM (cp.async pipeline + ldmatrix) ----------------
__device__ __forceinline__ void mma16816(float* c, const uint32_t* a, const uint32_t* b) {
    asm volatile(
        "mma.sync.aligned.m16n8k16.row.col.f32.bf16.bf16.f32 "
        "{%0,%1,%2,%3}, {%4,%5,%6,%7}, {%8,%9}, {%0,%1,%2,%3};"
        : "+f"(c[0]), "+f"(c[1]), "+f"(c[2]), "+f"(c[3])
        : "r"(a[0]), "r"(a[1]), "r"(a[2]), "r"(a[3]), "r"(b[0]), "r"(b[1]));
}
__device__ __forceinline__ void ldm4(uint32_t* r, uint32_t addr) {
    asm volatile("ldmatrix.sync.aligned.m8n8.x4.shared.b16 {%0,%1,%2,%3}, [%4];"
                 : "=r"(r[0]), "=r"(r[1]), "=r"(r[2]), "=r"(r[3]) : "r"(addr));
}
__device__ __forceinline__ void cp16(uint32_t dst, const void* src, int nbytes) {
    asm volatile("cp.async.cg.shared.global [%0], [%1], 16, %2;"
                 :: "r"(dst), "l"(src), "r"(nbytes));
}
__device__ __forceinline__ uint32_t smem_u32(const void* p) {
    uint32_t a;
    asm("{ .reg .u64 t; cvta.to.shared.u64 t, %1; cvt.u32.u64 %0, t; }" : "=r"(a) : "l"(p));
    return a;
}
__device__ __forceinline__ uint32_t bfpack(float a, float b) {
    return (uint32_t)__bfloat16_as_ushort(__float2bfloat16(a)) |
           ((uint32_t)__bfloat16_as_ushort(__float2bfloat16(b)) << 16);
}

#define SAS 40                   // smem row stride in halves
#define TILE_B (128 * SAS * 2)   // 10240 bytes per tile
#define STAGE_B (4 * TILE_B)     // 40960 bytes per stage
#define TCSM (2 * STAGE_B)       // 81920 dynamic smem

// GEMM core body; optional split-output epilogue
template <bool BIAS, bool RELU, bool SPLIT>
__device__ __forceinline__ void mma_gemm_body(
    const __nv_bfloat16* __restrict__ Ahi, const __nv_bfloat16* __restrict__ Alo, int lda,
    const __nv_bfloat16* __restrict__ Bhi, const __nv_bfloat16* __restrict__ Blo,
    const float* __restrict__ bias, float* __restrict__ C, int ldc,
    int M, int K, char* smem,
    __nv_bfloat16* SplitH, __nv_bfloat16* SplitL, int lds, int scol)
{
    uint32_t sb = smem_u32(smem);
    int tid = threadIdx.x;
    int warp = tid >> 5, lane = tid & 31;
    int wm = warp & 1, wn = warp >> 1;
    int g = lane >> 2, q = lane & 3;
    int m0 = blockIdx.y * 128, n0 = blockIdx.x * 128;

    float acc[4][4][4];
    #pragma unroll
    for (int i = 0; i < 4; i++)
        #pragma unroll
        for (int j = 0; j < 4; j++)
            #pragma unroll
            for (int t = 0; t < 4; t++) acc[i][j][t] = 0.f;

    int nchunks = K >> 5;
    int lrow = tid >> 2, lseg = tid & 3;
    auto load_chunk = [&](int stg, int k0) {
        #pragma unroll
        for (int it = 0; it < 2; it++) {
            int row = lrow + it * 64;
            uint32_t soff = sb + stg * STAGE_B + (uint32_t)(row * SAS + lseg * 8) * 2;
            int gm = m0 + row;
            int pa = (gm < M) ? 16 : 0;
            int gmc = (gm < M) ? gm : (M - 1);
            cp16(soff,              Ahi + (size_t)gmc * lda + k0 + lseg * 8, pa);
            cp16(soff + TILE_B,     Alo + (size_t)gmc * lda + k0 + lseg * 8, pa);
            int gn = n0 + row;
            cp16(soff + 2 * TILE_B, Bhi + (size_t)gn * K + k0 + lseg * 8, 16);
            cp16(soff + 3 * TILE_B, Blo + (size_t)gn * K + k0 + lseg * 8, 16);
        }
        asm volatile("cp.async.commit_group;" ::: "memory");
    };

    uint32_t lm_off = (uint32_t)((wm * 64 + (lane & 15)) * SAS + (lane >> 4) * 8) * 2;

    load_chunk(0, 0);
    for (int c = 0; c < nchunks; c++) {
        if (c + 1 < nchunks) {
            load_chunk((c + 1) & 1, (c + 1) << 5);
            asm volatile("cp.async.wait_group 1;" ::: "memory");
        } else {
            asm volatile("cp.async.wait_group 0;" ::: "memory");
        }
        __syncthreads();

        uint32_t stage_u = sb + (c & 1) * STAGE_B;
        const __nv_bfloat16* sBh = (const __nv_bfloat16*)(smem + (c & 1) * STAGE_B + 2 * TILE_B);
        const __nv_bfloat16* sBl = sBh + 128 * SAS;

        #pragma unroll
        for (int ks = 0; ks < 2; ks++) {
            int kb = ks * 16;
            uint32_t a[4][4], bh[4][2], bl[2];
            #pragma unroll
            for (int mf = 0; mf < 4; mf++)
                ldm4(a[mf], stage_u + lm_off + (uint32_t)(mf * 16 * SAS + kb) * 2);
            #pragma unroll
            for (int nf = 0; nf < 4; nf++) {
                const __nv_bfloat16* bb = sBh + (wn * 32 + nf * 8 + g) * SAS + kb + q * 2;
                bh[nf][0] = *(const uint32_t*)bb;
                bh[nf][1] = *(const uint32_t*)(bb + 8);
            }
            #pragma unroll
            for (int nf = 0; nf < 4; nf++)
                #pragma unroll
                for (int mf = 0; mf < 4; mf++) mma16816(acc[mf][nf], a[mf], bh[nf]);
            #pragma unroll
            for (int nf = 0; nf < 4; nf++) {
                const __nv_bfloat16* bb = sBl + (wn * 32 + nf * 8 + g) * SAS + kb + q * 2;
                bl[0] = *(const uint32_t*)bb;
                bl[1] = *(const uint32_t*)(bb + 8);
                #pragma unroll
                for (int mf = 0; mf < 4; mf++) mma16816(acc[mf][nf], a[mf], bl);
            }
            #pragma unroll
            for (int mf = 0; mf < 4; mf++)
                ldm4(a[mf], stage_u + TILE_B + lm_off + (uint32_t)(mf * 16 * SAS + kb) * 2);
            #pragma unroll
            for (int nf = 0; nf < 4; nf++)
                #pragma unroll
                for (int mf = 0; mf < 4; mf++) mma16816(acc[mf][nf], a[mf], bh[nf]);
        }
        __syncthreads();
    }

    #pragma unroll
    for (int nf = 0; nf < 4; nf++) {
        int col = n0 + wn * 32 + nf * 8 + q * 2;
        float bv0 = 0.f, bv1 = 0.f;
        if (BIAS) { bv0 = __ldg(bias + col); bv1 = __ldg(bias + col + 1); }
        #pragma unroll
        for (int mf = 0; mf < 4; mf++) {
            int r = m0 + wm * 64 + mf * 16 + g;
            float v0 = acc[mf][nf][0] + bv0, v1 = acc[mf][nf][1] + bv1;
            float v2 = acc[mf][nf][2] + bv0, v3 = acc[mf][nf][3] + bv1;
            if (RELU) {
                v0 = fmaxf(v0, 0.f); v1 = fmaxf(v1, 0.f);
                v2 = fmaxf(v2, 0.f); v3 = fmaxf(v3, 0.f);
            }
            if (r < M) {
                *(float2*)&C[(size_t)r * ldc + col] = make_float2(v0, v1);
                if (SPLIT) {
                    SplitH[(size_t)r * lds + scol + col]     = __float2bfloat16(v0);
                    SplitH[(size_t)r * lds + scol + col + 1] = __float2bfloat16(v1);
                    float l0 = v0 - __bfloat162float(__float2bfloat16(v0));
                    float l1 = v1 - __bfloat162float(__float2bfloat16(v1));
                    SplitL[(size_t)r * lds + scol + col]     = __float2bfloat16(l0);
                    SplitL[(size_t)r * lds + scol + col + 1] = __float2bfloat16(l1);
                }
            }
            if (r + 8 < M) {
                *(float2*)&C[(size_t)(r + 8) * ldc + col] = make_float2(v2, v3);
                if (SPLIT) {
                    SplitH[(size_t)(r + 8) * lds + scol + col]     = __float2bfloat16(v2);
                    SplitH[(size_t)(r + 8) * lds + scol + col + 1] = __float2bfloat16(v3);
                    float l2 = v2 - __bfloat162float(__float2bfloat16(v2));
                    float l3 = v3 - __bfloat162float(__float2bfloat16(v3));
                    SplitL[(size_t)(r + 8) * lds + scol + col]     = __float2bfloat16(l2);
                    SplitL[(size_t)(r + 8) * lds + scol + col + 1] = __float2bfloat16(l3);
                }
            }
        }
    }
}

template <bool BIAS, bool RELU>
__global__ __launch_bounds__(256, 2) void k_mma_gemm(
    const __nv_bfloat16* __restrict__ Ahi, const __nv_bfloat16* __restrict__ Alo, int lda,
    const __nv_bfloat16* __restrict__ Bhi, const __nv_bfloat16* __restrict__ Blo,
    const float* __restrict__ bias, float* __restrict__ C, int ldc,
    int M, int K)
{
    extern __shared__ char smem[];
    mma_gemm_body<BIAS, RELU, false>(Ahi, Alo, lda, Bhi, Blo, bias, C, ldc, M, K, smem,
                                     nullptr, nullptr, 0, 0);
}

__global__ __launch_bounds__(256, 2) void k_mma_gemm_split(
    const __nv_bfloat16* __restrict__ Ahi, const __nv_bfloat16* __restrict__ Alo, int lda,
    const __nv_bfloat16* __restrict__ Bhi, const __nv_bfloat16* __restrict__ Blo,
    const float* __restrict__ bias, float* __restrict__ C, int ldc,
    int M, int K,
    __nv_bfloat16* SplitH, __nv_bfloat16* SplitL, int lds, int scol)
{
    extern __shared__ char smem[];
    mma_gemm_body<true, true, true>(Ahi, Alo, lda, Bhi, Blo, bias, C, ldc, M, K, smem,
                                    SplitH, SplitL, lds, scol);
}

__global__ __launch_bounds__(256, 2) void k_mma_gemm_dual(
    const __nv_bfloat16* __restrict__ Ahi0, const __nv_bfloat16* __restrict__ Alo0,
    const __nv_bfloat16* __restrict__ Ahi1, const __nv_bfloat16* __restrict__ Alo1, int lda,
    const __nv_bfloat16* __restrict__ Bhi0, const __nv_bfloat16* __restrict__ Blo0,
    const __nv_bfloat16* __restrict__ Bhi1, const __nv_bfloat16* __restrict__ Blo1,
    const float* __restrict__ bias0, const float* __restrict__ bias1,
    float* __restrict__ C0, float* __restrict__ C1, int ldc,
    int M, int K)
{
    extern __shared__ char smem[];
    if (blockIdx.z == 0)
        mma_gemm_body<true, false, false>(Ahi0, Alo0, lda, Bhi0, Blo0, bias0, C0, ldc, M, K, smem,
                                          nullptr, nullptr, 0, 0);
    else
        mma_gemm_body<true, false, false>(Ahi1, Alo1, lda, Bhi1, Blo1, bias1, C1, ldc, M, K, smem,
                                          nullptr, nullptr, 0, 0);
}

// ---------------- fp32 SIMT GEMMs ----------------
template <bool BIAS, bool RELU>
__device__ __forceinline__ void gemm128_body(
    const float* __restrict__ A, int lda, const float* __restrict__ B, int ldb,
    const float* __restrict__ bias, float* __restrict__ C, int ldc,
    int M, int N, int K)
{
    __shared__ float As[8][128];
    __shared__ float Bs[8][128];
    int tid = threadIdx.x;
    int m0 = blockIdx.y * 128, n0 = blockIdx.x * 128;
    int ar = tid >> 1, ac = (tid & 1) * 4;
    int bk = tid >> 5, bn = (tid & 31) * 4;
    int ty = tid >> 4, tx = tid & 15;
    float acc[8][8] = {};
    for (int k0 = 0; k0 < K; k0 += 8) {
        float4 av = make_float4(0.f, 0.f, 0.f, 0.f);
        if (m0 + ar < M) av = *(const float4*)&A[(size_t)(m0 + ar) * lda + k0 + ac];
        As[ac + 0][ar] = av.x; As[ac + 1][ar] = av.y; As[ac + 2][ar] = av.z; As[ac + 3][ar] = av.w;
        float4 bv = make_float4(0.f, 0.f, 0.f, 0.f);
        if (n0 + bn < N) bv = *(const float4*)&B[(size_t)(k0 + bk) * ldb + n0 + bn];
        *(float4*)&Bs[bk][bn] = bv;
        __syncthreads();
        #pragma unroll
        for (int kk = 0; kk < 8; kk++) {
            float a[8], b[8];
            #pragma unroll
            for (int i = 0; i < 8; i++) a[i] = As[kk][ty * 8 + i];
            #pragma unroll
            for (int j = 0; j < 8; j++) b[j] = Bs[kk][tx * 8 + j];
            #pragma unroll
            for (int i = 0; i < 8; i++)
                #pragma unroll
                for (int j = 0; j < 8; j++)
                    acc[i][j] += a[i] * b[j];
        }
        __syncthreads();
    }
    #pragma unroll
    for (int i = 0; i < 8; i++) {
        int m = m0 + ty * 8 + i;
        if (m < M) {
            #pragma unroll
            for (int j = 0; j < 8; j++) {
                int n = n0 + tx * 8 + j;
                if (n < N) {
                    float v = acc[i][j];
                    if (BIAS) v += bias[n];
                    if (RELU) v = fmaxf(v, 0.f);
                    C[(size_t)m * ldc + n] = v;
                }
            }
        }
    }
}

// layer0 dual: z selects weight/bias/output set (same A)
__global__ __launch_bounds__(256) void k_gemm128_dual(
    const float* __restrict__ A, int lda,
    const float* __restrict__ B0, const float* __restrict__ B1, int ldb,
    const float* __restrict__ bias0, const float* __restrict__ bias1,
    float* __restrict__ C0, float* __restrict__ C1, int ldc,
    int M, int N, int K)
{
    if (blockIdx.z == 0)
        gemm128_body<true, false>(A, lda, B0, ldb, bias0, C0, ldc, M, N, K);
    else
        gemm128_body<true, false>(A, lda, B1, ldb, bias1, C1, ldc, M, N, K);
}

template <bool BIAS, bool RELU>
__global__ __launch_bounds__(256) void k_gemm64(
    const float* __restrict__ A, int lda, const float* __restrict__ B, int ldb,
    const float* __restrict__ bias, float* __restrict__ C, int ldc,
    int M, int N, int K)
{
    __shared__ float As[16][64];
    __shared__ float Bs[16][64];
    int tid = threadIdx.x;
    int m0 = blockIdx.y * 64, n0 = blockIdx.x * 64;
    int ar = tid >> 2, ac = (tid & 3) * 4;
    int bk = tid >> 4, bn = (tid & 15) * 4;
    int ty = tid >> 4, tx = tid & 15;
    float acc[4][4] = {};
    for (int k0 = 0; k0 < K; k0 += 16) {
        float4 av = make_float4(0.f, 0.f, 0.f, 0.f);
        if (m0 + ar < M) av = *(const float4*)&A[(size_t)(m0 + ar) * lda + k0 + ac];
        As[ac + 0][ar] = av.x; As[ac + 1][ar] = av.y; As[ac + 2][ar] = av.z; As[ac + 3][ar] = av.w;
        float4 bv = make_float4(0.f, 0.f, 0.f, 0.f);
        if (n0 + bn < N) bv = *(const float4*)&B[(size_t)(k0 + bk) * ldb + n0 + bn];
        *(float4*)&Bs[bk][bn] = bv;
        __syncthreads();
        #pragma unroll
        for (int kk = 0; kk < 16; kk++) {
            float a[4], b[4];
            #pragma unroll
            for (int i = 0; i < 4; i++) a[i] = As[kk][ty * 4 + i];
            #pragma unroll
            for (int j = 0; j < 4; j++) b[j] = Bs[kk][tx * 4 + j];
            #pragma unroll
            for (int i = 0; i < 4; i++)
                #pragma unroll
                for (int j = 0; j < 4; j++)
                    acc[i][j] += a[i] * b[j];
        }
        __syncthreads();
    }
    #pragma unroll
    for (int i = 0; i < 4; i++) {
        int m = m0 + ty * 4 + i;
        if (m < M) {
            #pragma unroll
            for (int j = 0; j < 4; j++) {
                int n = n0 + tx * 4 + j;
                if (n < N) {
                    float v = acc[i][j];
                    if (BIAS) v += bias[n];
                    if (RELU) v = fmaxf(v, 0.f);
                    C[(size_t)m * ldc + n] = v;
                }
            }
        }
    }
}

// ---------------- fused edge conv (frozen body) + residual + bf16 split ----------------
__global__ __launch_bounds__(256) void k_edgeconv(
    const float* __restrict__ e_attr,
    const float* __restrict__ W3n, const float* __restrict__ W3s,
    const float* __restrict__ PQ, const float* __restrict__ PQs,
    const float* __restrict__ prevN, const float* __restrict__ prevS,
    float* __restrict__ outN, float* __restrict__ outS,
    __nv_bfloat16* __restrict__ outNh, __nv_bfloat16* __restrict__ outNl,
    __nv_bfloat16* __restrict__ outSh, __nv_bfloat16* __restrict__ outSl)
{
    __shared__ float sW3n[768];
    __shared__ float sW3s[768];
    for (int i = threadIdx.x; i < 768; i += blockDim.x) { sW3n[i] = W3n[i]; sW3s[i] = W3s[i]; }
    __syncthreads();
    int warp = threadIdx.x >> 5, lane = threadIdx.x & 31;
    int node = blockIdx.x * (blockDim.x >> 5) + warp;
    if (node >= NN) return;
    int r0 = g_rowptr[node], r1 = g_rowptr[node + 1];
    int c = lane * 4;
    float4 qn = *(const float4*)(PQ  + node * 256 + 128 + c);
    float4 qs = *(const float4*)(PQs + node * 256 + 128 + c);
    float mx0 = 0.f, mx1 = 0.f, mx2 = 0.f, mx3 = 0.f;
    float sm0 = 0.f, sm1 = 0.f, sm2 = 0.f, sm3 = 0.f;
    for (int e = r0; e < r1; ++e) {
        int s  = g_csr_src[e];
        int id = g_csr_eid[e];
        float4 p  = *(const float4*)(PQ  + s * 256 + c);
        float4 ps = *(const float4*)(PQs + s * 256 + c);
        float a0 = p.x + qn.x, a1 = p.y + qn.y, a2 = p.z + qn.z, a3 = p.w + qn.w;
        float b0 = ps.x + qs.x, b1 = ps.y + qs.y, b2 = ps.z + qs.z, b3 = ps.w + qs.w;
        #pragma unroll
        for (int k = 0; k < 6; k++) {
            float ev = __ldg(e_attr + (size_t)id * 6 + k);
            const float* wn = sW3n + k * 128 + c;
            const float* ws = sW3s + k * 128 + c;
            a0 += ev * wn[0]; a1 += ev * wn[1]; a2 += ev * wn[2]; a3 += ev * wn[3];
            b0 += ev * ws[0]; b1 += ev * ws[1]; b2 += ev * ws[2]; b3 += ev * ws[3];
        }
        a0 = fmaxf(a0, 0.f); a1 = fmaxf(a1, 0.f); a2 = fmaxf(a2, 0.f); a3 = fmaxf(a3, 0.f);
        mx0 = fmaxf(mx0, a0); mx1 = fmaxf(mx1, a1); mx2 = fmaxf(mx2, a2); mx3 = fmaxf(mx3, a3);
        b0 = fmaxf(b0, 0.f); b1 = fmaxf(b1, 0.f); b2 = fmaxf(b2, 0.f); b3 = fmaxf(b3, 0.f);
        sm0 += b0; sm1 += b1; sm2 += b2; sm3 += b3;
    }
    int deg = r1 - r0;
    float inv = 1.f / (float)(deg > 0 ? deg : 1);
    float f0 = mx0, f1 = mx1, f2 = mx2, f3 = mx3;
    float s0 = sm0 * inv, s1 = sm1 * inv, s2 = sm2 * inv, s3 = sm3 * inv;
    if (prevN) {
        float4 pn = *(const float4*)(prevN + node * 384 + c);
        f0 += pn.x; f1 += pn.y; f2 += pn.z; f3 += pn.w;
        float4 pv = *(const float4*)(prevS + node * 384 + c);
        s0 += pv.x; s1 += pv.y; s2 += pv.z; s3 += pv.w;
    }
    *(float4*)(outN + node * 384 + c) = make_float4(f0, f1, f2, f3);
    *(float4*)(outS + node * 384 + c) = make_float4(s0, s1, s2, s3);
    uint2 u;
    u.x = bfpack(f0, f1); u.y = bfpack(f2, f3);
    *(uint2*)(outNh + node * 384 + c) = u;
    float r0f = f0 - __bfloat162float(__float2bfloat16(f0));
    float r1f = f1 - __bfloat162float(__float2bfloat16(f1));
    float r2f = f2 - __bfloat162float(__float2bfloat16(f2));
    float r3f = f3 - __bfloat162float(__float2bfloat16(f3));
    u.x = bfpack(r0f, r1f); u.y = bfpack(r2f, r3f);
    *(uint2*)(outNl + node * 384 + c) = u;
    u.x = bfpack(s0, s1); u.y = bfpack(s2, s3);
    *(uint2*)(outSh + node * 384 + c) = u;
    r0f = s0 - __bfloat162float(__float2bfloat16(s0));
    r1f = s1 - __bfloat162float(__float2bfloat16(s1));
    r2f = s2 - __bfloat162float(__float2bfloat16(s2));
    r3f = s3 - __bfloat162float(__float2bfloat16(s3));
    u.x = bfpack(r0f, r1f); u.y = bfpack(r2f, r3f);
    *(uint2*)(outSl + node * 384 + c) = u;
}

// ---------------- combined bbox pooling: blocks [0,NBB) = super mean, [NBB,2*NBB) = max ----------------
__global__ void k_pool_both() {
    int blk = blockIdx.x;
    if (blk < NBB) {
        int b = blk;
        int c = threadIdx.x;            // blockDim = 384
        int r0 = g_bboxptr[b], r1 = g_bboxptr[b + 1];
        float s = 0.f;
        for (int n = r0; n < r1; n++) s += g_featsS[n * 384 + c];
        int cnt = r1 - r0;
        float v = s / (float)(cnt > 0 ? cnt : 1);
        g_big[b * 2816 + 2432 + c] = v;
        __nv_bfloat16 h = __float2bfloat16(v);
        __nv_bfloat16 l = __float2bfloat16(v - __bfloat162float(h));
        g_Sh[b * 384 + c] = h;
        g_Sl[b * 384 + c] = l;
        g_Mh[b * 2816 + 2432 + c] = h;
        g_Ml[b * 2816 + 2432 + c] = l;
    } else {
        int b = blk - NBB;
        int r0 = g_bboxptr[b], r1 = g_bboxptr[b + 1];
        for (int c = threadIdx.x; c < 1408; c += blockDim.x) {
            float m = -FLT_MAX;
            if (c < 1024) {
                for (int n = r0; n < r1; n++) m = fmaxf(m, g_fusion[n * 1024 + c]);
            } else {
                int cc = c - 1024;
                for (int n = r0; n < r1; n++) m = fmaxf(m, g_feats[n * 384 + cc]);
            }
            if (r1 == r0) m = 0.f;
            g_big[b * 2816 + c] = m;
            __nv_bfloat16 h = __float2bfloat16(m);
            g_Mh[b * 2816 + c] = h;
            g_Ml[b * 2816 + c] = __float2bfloat16(m - __bfloat162float(h));
        }
    }
}

// ---------------- launch ----------------
extern "C" void kernel_launch(void* const* d_in, const int* in_sizes, int n_in,
                              void* d_out, int out_size)
{
    const float* x     = (const float*)d_in[0];
    const float* eat   = (const float*)d_in[1];
    const float* W_h   = (const float*)d_in[2];
    const float* b_h   = (const float*)d_in[3];
    const float* Ws_h  = (const float*)d_in[4];
    const float* bs_h  = (const float*)d_in[5];
    const float* Wb    = (const float*)d_in[6];
    const float* bb    = (const float*)d_in[7];
    const float* Wbs   = (const float*)d_in[8];
    const float* bbs   = (const float*)d_in[9];
    const float* W_f   = (const float*)d_in[10];
    const float* b_f   = (const float*)d_in[11];
    const float* W_fs  = (const float*)d_in[12];
    const float* b_fs  = (const float*)d_in[13];
    const float* W1    = (const float*)d_in[14];
    const float* b1    = (const float*)d_in[15];
    const float* W2    = (const float*)d_in[16];
    const float* b2    = (const float*)d_in[17];
    const float* W3c   = (const float*)d_in[18];
    const float* b3    = (const float*)d_in[19];
    const int*   edge  = (const int*)d_in[20];
    const int*   bbox  = (const int*)d_in[21];
    const int* src = edge;
    const int* dst = edge + NE;
    float* out = (float*)d_out;

    float *pFeats, *pFeatsS, *pPQ, *pPQs, *pFus, *pBig, *pH1, *pH2, *pWcn, *pWcs, *pb256h, *pb256;
    __nv_bfloat16 *pAh, *pAl, *pSh, *pSl, *pMh, *pMl;
    __nv_bfloat16 *pBfh, *pBfl, *pBfsh, *pBfsl, *pB1h, *pB1l, *pwbh, *pwbl;
    int *pHist;
    cudaGetSymbolAddress((void**)&pFeats,  g_feats);
    cudaGetSymbolAddress((void**)&pFeatsS, g_featsS);
    cudaGetSymbolAddress((void**)&pPQ,  g_PQ);
    cudaGetSymbolAddress((void**)&pPQs, g_PQs);
    cudaGetSymbolAddress((void**)&pFus, g_fusion);
    cudaGetSymbolAddress((void**)&pBig, g_big);
    cudaGetSymbolAddress((void**)&pH1,  g_h1);
    cudaGetSymbolAddress((void**)&pH2,  g_h2);
    cudaGetSymbolAddress((void**)&pWcn, g_Wcn);
    cudaGetSymbolAddress((void**)&pWcs, g_Wcs);
    cudaGetSymbolAddress((void**)&pb256h, g_b256h);
    cudaGetSymbolAddress((void**)&pb256, g_b256);
    cudaGetSymbolAddress((void**)&pHist, g_hist);
    cudaGetSymbolAddress((void**)&pAh, g_Ah);
    cudaGetSymbolAddress((void**)&pAl, g_Al);
    cudaGetSymbolAddress((void**)&pSh, g_Sh);
    cudaGetSymbolAddress((void**)&pSl, g_Sl);
    cudaGetSymbolAddress((void**)&pMh, g_Mh);
    cudaGetSymbolAddress((void**)&pMl, g_Ml);
    cudaGetSymbolAddress((void**)&pBfh, g_Bfh);
    cudaGetSymbolAddress((void**)&pBfl, g_Bfl);
    cudaGetSymbolAddress((void**)&pBfsh, g_Bfsh);
    cudaGetSymbolAddress((void**)&pBfsl, g_Bfsl);
    cudaGetSymbolAddress((void**)&pB1h, g_B1h);
    cudaGetSymbolAddress((void**)&pB1l, g_B1l);
    cudaGetSymbolAddress((void**)&pwbh, g_wbh);
    cudaGetSymbolAddress((void**)&pwbl, g_wbl);

    cudaFuncSetAttribute(k_mma_gemm<true, false>, cudaFuncAttributeMaxDynamicSharedMemorySize, TCSM);
    cudaFuncSetAttribute(k_mma_gemm<true, true>,  cudaFuncAttributeMaxDynamicSharedMemorySize, TCSM);
    cudaFuncSetAttribute(k_mma_gemm_dual,         cudaFuncAttributeMaxDynamicSharedMemorySize, TCSM);
    cudaFuncSetAttribute(k_mma_gemm_split,        cudaFuncAttributeMaxDynamicSharedMemorySize, TCSM);

    // CSR by dst + bbox ranges (bboxptr folded into scan3)
    cudaMemsetAsync(pHist, 0, NN * sizeof(int), 0);
    k_count<<<(NE + 255) / 256, 256>>>(dst);
    int nblk = (NN + 255) / 256;
    k_scan1<<<nblk, 256>>>();
    k_scan2<<<1, 256>>>(nblk);
    k_scan3<<<nblk, 256>>>(bbox);
    k_fill<<<(NE + 255) / 256, 256>>>(src, dst);

    // merged weight preps (3 launches total)
    {
        dim3 gw(5632, 1, 3);
        k_wsplit3<<<gw, 256>>>(W_f, W_fs, W1);
        dim3 gp(128, 1, 4);
        k_prep_layerW_all<<<gp, 256>>>(Wb, bb, Wbs, bbs);
        dim3 gh(8, 1, 2);
        k_prep_head_dual<<<gh, 256>>>(W_h, b_h, Ws_h, bs_h);
    }

    // ---- layer 0 (inC=8) ----
    {
        dim3 g1(2, (NN + 127) / 128, 2);
        k_gemm128_dual<<<g1, 256>>>(x, 8, pWcn, pWcs, 256, pb256h, pb256h + 256,
                                    pPQ, pPQs, 256, NN, 256, 8);
        k_edgeconv<<<(NN + 7) / 8, 256>>>(eat, W_h + 2048, Ws_h + 2048,
                                          pPQ, pPQs, nullptr, nullptr,
                                          pFeats, pFeatsS,
                                          pAh, pAl, pSh, pSl);
    }

    // ---- layers 1,2: split-bf16 HMMA (node+super merged) ----
    for (int i = 1; i < 3; i++) {
        const float* W  = Wb  + (size_t)(i - 1) * 262 * 128;
        const float* Ws = Wbs + (size_t)(i - 1) * 262 * 128;
        const int nW = 256 * 128;
        int z0 = 2 * (i - 1);

        dim3 gl(2, (NN + 127) / 128, 2);
        k_mma_gemm_dual<<<gl, 256, TCSM>>>(
            pAh + (i - 1) * 128, pAl + (i - 1) * 128,
            pSh + (i - 1) * 128, pSl + (i - 1) * 128, 384,
            pwbh + (size_t)z0 * nW, pwbl + (size_t)z0 * nW,
            pwbh + (size_t)(z0 + 1) * nW, pwbl + (size_t)(z0 + 1) * nW,
            pb256 + z0 * 256, pb256 + (z0 + 1) * 256,
            pPQ, pPQs, 256, NN, 128);

        k_edgeconv<<<(NN + 7) / 8, 256>>>(eat, W + 2 * 128 * 128, Ws + 2 * 128 * 128,
                                          pPQ, pPQs,
                                          pFeats + (i - 1) * 128, pFeatsS + (i - 1) * 128,
                                          pFeats + i * 128, pFeatsS + i * 128,
                                          pAh + i * 128, pAl + i * 128,
                                          pSh + i * 128, pSl + i * 128);
    }

    // ---- fusion: relu(feats @ W_f + b_f) -> [NN, 1024] ----
    {
        dim3 g(8, (NN + 127) / 128);
        k_mma_gemm<true, true><<<g, 256, TCSM>>>(pAh, pAl, 384, pBfh, pBfl, b_f, pFus, 1024, NN, 384);
    }

    // ---- bbox pooling (both pools in one launch) ----
    k_pool_both<<<2 * NBB, 384>>>();

    // ---- fusion_super (split epilogue feeds MLP input cols [1408, 2432)) ----
    {
        dim3 g(8, (NBB + 127) / 128);
        k_mma_gemm_split<<<g, 256, TCSM>>>(pSh, pSl, 384, pBfsh, pBfsl, b_fs,
                                           pBig + 1408, 2816, NBB, 384,
                                           pMh, pMl, 2816, 1408);
    }

    // ---- MLP head ----
    {
        dim3 g(4, (NBB + 127) / 128);
        k_mma_gemm<true, true><<<g, 256, TCSM>>>(pMh, pMl, 2816, pB1h, pB1l, b1, pH1, 512, NBB, 2816);
    }
    dim3 gm2(4, (NBB + 63) / 64);
    k_gemm64<true, true><<<gm2, 256>>>(pH1, 512, W2, 256, b2, pH2, 256, NBB, 256, 512);
    dim3 gm3(1, (NBB + 63) / 64);
    k_gemm64<true, false><<<gm3, 256>>>(pH2, 256, W3c, 32, b3, out, 32, NBB, 32, 256);
}

// round 14
// speedup vs baseline: 1.1027x; 1.0269x over previous
#include <cuda_runtime.h>
#include <cuda_bf16.h>
#include <math.h>
#include <float.h>
#include <cstdint>

#define NN 50000
#define NE 800000
#define NBB 2000

// ---------------- scratch (static device globals; no allocation) ----------------
__device__ float g_feats [NN * 384];
__device__ float g_featsS[NN * 384];
__device__ float g_PQ [NN * 256];        // [P(128) | Q(128)] node stream
__device__ float g_PQs[NN * 256];        // super stream
__device__ float g_big[NBB * 2816];      // [pooled(1408) | fusionS(1024) | superFeats(384)]
__device__ float g_h1[NBB * 512];
__device__ float g_h2[NBB * 256];
__device__ float g_Wcn[8 * 256];         // layer0 combined weights [8, 256]
__device__ float g_Wcs[8 * 256];
__device__ float g_b256h[512];           // layer0 biases [node | super]
__device__ float g_b256[4 * 256];        // layer1,2 biases [L1n, L1s, L2n, L2s]
__device__ int   g_hist[NN];
__device__ int   g_rowptr[NN + 1];
__device__ int   g_wcur[NN];
__device__ int   g_csr_src[NE];
__device__ int   g_csr_eid[NE];
__device__ int   g_bboxptr[NBB + 1];
__device__ int   g_bsum[256];
__device__ int   g_boff[256];
// bf16 split buffers
__device__ __align__(16) __nv_bfloat16 g_Ah[NN * 384];
__device__ __align__(16) __nv_bfloat16 g_Al[NN * 384];
__device__ __align__(16) __nv_bfloat16 g_Sh[NN * 384];   // conv super splits; reused post-conv as fusion_super input
__device__ __align__(16) __nv_bfloat16 g_Sl[NN * 384];
__device__ __align__(16) __nv_bfloat16 g_Mh[NBB * 2816]; // MLP head split input
__device__ __align__(16) __nv_bfloat16 g_Ml[NBB * 2816];
__device__ __align__(16) __nv_bfloat16 g_Bfh[1024 * 384];
__device__ __align__(16) __nv_bfloat16 g_Bfl[1024 * 384];
__device__ __align__(16) __nv_bfloat16 g_Bfsh[1024 * 384];
__device__ __align__(16) __nv_bfloat16 g_Bfsl[1024 * 384];
__device__ __align__(16) __nv_bfloat16 g_B1h[512 * 2816];
__device__ __align__(16) __nv_bfloat16 g_B1l[512 * 2816];
__device__ __align__(16) __nv_bfloat16 g_wbh[4 * 256 * 128];  // [L1n, L1s, L2n, L2s]
__device__ __align__(16) __nv_bfloat16 g_wbl[4 * 256 * 128];

// ---------------- CSR build ----------------
__global__ void k_count(const int* __restrict__ dst) {
    int e = blockIdx.x * blockDim.x + threadIdx.x;
    if (e < NE) atomicAdd(&g_hist[dst[e]], 1);
}

__device__ __forceinline__ int block_incl_scan256(int v, int tid) {
    __shared__ int ws[8];
    int x = v;
    #pragma unroll
    for (int o = 1; o < 32; o <<= 1) {
        int t = __shfl_up_sync(0xFFFFFFFFu, x, o);
        if ((tid & 31) >= o) x += t;
    }
    if ((tid & 31) == 31) ws[tid >> 5] = x;
    __syncthreads();
    if (tid < 8) {
        int w = ws[tid];
        #pragma unroll
        for (int o = 1; o < 8; o <<= 1) {
            int t = __shfl_up_sync(0xFFu, w, o);
            if (tid >= o) w += t;
        }
        ws[tid] = w;
    }
    __syncthreads();
    return x + ((tid >= 32) ? ws[(tid >> 5) - 1] : 0);
}

__global__ void k_scan1() {
    int tid = threadIdx.x;
    int i = blockIdx.x * 256 + tid;
    int v = (i < NN) ? g_hist[i] : 0;
    int incl = block_incl_scan256(v, tid);
    if (i < NN) g_rowptr[i + 1] = incl;
    if (tid == 255) g_bsum[blockIdx.x] = incl;
}
__global__ void k_scan2(int nblk) {
    int tid = threadIdx.x;
    int v = (tid < nblk) ? g_bsum[tid] : 0;
    int incl = block_incl_scan256(v, tid);
    if (tid < nblk) g_boff[tid] = incl - v;
}
// scan3 + bbox range search folded together
__global__ void k_scan3(const int* __restrict__ bbox_idx) {
    int i = blockIdx.x * 256 + threadIdx.x;
    if (i < NN) {
        int r = g_rowptr[i + 1] + g_boff[blockIdx.x];
        g_rowptr[i + 1] = r;
        g_wcur[i] = r - g_hist[i];
    }
    if (i == 0) g_rowptr[0] = 0;
    if (i <= NBB) {
        int lo = 0, hi = NN;
        while (lo < hi) {
            int mid = (lo + hi) >> 1;
            if (bbox_idx[mid] < i) lo = mid + 1; else hi = mid;
        }
        g_bboxptr[i] = lo;
    }
}

__global__ void k_fill(const int* __restrict__ src, const int* __restrict__ dst) {
    int e = blockIdx.x * blockDim.x + threadIdx.x;
    if (e < NE) {
        int d = dst[e];
        int pos = atomicAdd(&g_wcur[d], 1);
        g_csr_src[pos] = src[e];
        g_csr_eid[pos] = e;
    }
}

// layer0 combined weights, both streams in one launch (z selects)
__global__ void k_prep_head_dual(const float* __restrict__ Wn, const float* __restrict__ bn,
                                 const float* __restrict__ Ws, const float* __restrict__ bs) {
    const float* W    = blockIdx.z ? Ws : Wn;
    const float* bias = blockIdx.z ? bs : bn;
    float* Wc   = blockIdx.z ? g_Wcs : g_Wcn;
    float* b256 = g_b256h + blockIdx.z * 256;
    int idx = blockIdx.x * blockDim.x + threadIdx.x;
    if (idx < 8 * 256) {
        int k = idx >> 8, n = idx & 255;
        float v = (n < 128) ? (W[k * 128 + n] - W[(8 + k) * 128 + n])
                            : W[(8 + k) * 128 + (n - 128)];
        Wc[idx] = v;
    }
    if (idx < 256) b256[idx] = (idx < 128) ? 0.f : bias[idx - 128];
}

// all 4 layer-weight preps in one launch: z = 2*(layer-1) + stream
__global__ void k_prep_layerW_all(const float* __restrict__ Wb, const float* __restrict__ bb,
                                  const float* __restrict__ Wbs, const float* __restrict__ bbs) {
    int z = blockIdx.z;
    int li = z >> 1, st = z & 1;
    const float* W    = (st ? Wbs : Wb)  + (size_t)li * 262 * 128;
    const float* bias = (st ? bbs : bb)  + li * 128;
    __nv_bfloat16* hi = g_wbh + (size_t)z * 256 * 128;
    __nv_bfloat16* lo = g_wbl + (size_t)z * 256 * 128;
    float* bias256 = g_b256 + z * 256;
    int idx = blockIdx.x * blockDim.x + threadIdx.x;
    if (idx < 256 * 128) {
        int n = idx >> 7, k = idx & 127;
        float v;
        if (n < 128) v = W[k * 128 + n] - W[(128 + k) * 128 + n];
        else         v = W[(128 + k) * 128 + (n - 128)];
        __nv_bfloat16 h = __float2bfloat16(v);
        hi[idx] = h;
        lo[idx] = __float2bfloat16(v - __bfloat162float(h));
    }
    if (idx < 256) bias256[idx] = (idx < 128) ? 0.f : bias[idx - 128];
}

// 3 big weight transpose+splits in one launch: z = {W_f, W_fs, W1}
__global__ void k_wsplit3(const float* __restrict__ W_f,
                          const float* __restrict__ W_fs,
                          const float* __restrict__ W1) {
    int z = blockIdx.z;
    const float* W;
    __nv_bfloat16 *hi, *lo;
    int K, N;
    if (z == 0)      { W = W_f;  hi = g_Bfh;  lo = g_Bfl;  K = 384;  N = 1024; }
    else if (z == 1) { W = W_fs; hi = g_Bfsh; lo = g_Bfsl; K = 384;  N = 1024; }
    else             { W = W1;   hi = g_B1h;  lo = g_B1l;  K = 2816; N = 512; }
    int idx = blockIdx.x * blockDim.x + threadIdx.x;
    if (idx < K * N) {
        int nn = idx / K, kk = idx - nn * K;
        float a = W[(size_t)kk * N + nn];
        __nv_bfloat16 h = __float2bfloat16(a);
        hi[idx] = h;
        lo[idx] = __float2bfloat16(a - __bfloat162float(h));
    }
}

// ---------------- split-bf16 HMMA GEMM (cp.async pipeline + ldmatrix) ----------------
__device__ __forceinline__ void mma16816(float* c, const uint32_t* a, const uint32_t* b) {
    asm volatile(
        "mma.sync.aligned.m16n8k16.row.col.f32.bf16.bf16.f32 "
        "{%0,%1,%2,%3}, {%4,%5,%6,%7}, {%8,%9}, {%0,%1,%2,%3};"
        : "+f"(c[0]), "+f"(c[1]), "+f"(c[2]), "+f"(c[3])
        : "r"(a[0]), "r"(a[1]), "r"(a[2]), "r"(a[3]), "r"(b[0]), "r"(b[1]));
}
__device__ __forceinline__ void ldm4(uint32_t* r, uint32_t addr) {
    asm volatile("ldmatrix.sync.aligned.m8n8.x4.shared.b16 {%0,%1,%2,%3}, [%4];"
                 : "=r"(r[0]), "=r"(r[1]), "=r"(r[2]), "=r"(r[3]) : "r"(addr));
}
__device__ __forceinline__ void cp16(uint32_t dst, const void* src, int nbytes) {
    asm volatile("cp.async.cg.shared.global [%0], [%1], 16, %2;"
                 :: "r"(dst), "l"(src), "r"(nbytes));
}
__device__ __forceinline__ uint32_t smem_u32(const void* p) {
    uint32_t a;
    asm("{ .reg .u64 t; cvta.to.shared.u64 t, %1; cvt.u32.u64 %0, t; }" : "=r"(a) : "l"(p));
    return a;
}
__device__ __forceinline__ uint32_t bfpack(float a, float b) {
    return (uint32_t)__bfloat16_as_ushort(__float2bfloat16(a)) |
           ((uint32_t)__bfloat16_as_ushort(__float2bfloat16(b)) << 16);
}

#define SAS 40                   // smem row stride in halves
#define TILE_B (128 * SAS * 2)   // 10240 bytes per tile
#define STAGE_B (4 * TILE_B)     // 40960 bytes per stage
#define TCSM (2 * STAGE_B)       // 81920 dynamic smem

// shared mainloop: accumulates the 128x128 tile into acc
__device__ __forceinline__ void mma_mainloop(
    const __nv_bfloat16* __restrict__ Ahi, const __nv_bfloat16* __restrict__ Alo, int lda,
    const __nv_bfloat16* __restrict__ Bhi, const __nv_bfloat16* __restrict__ Blo,
    int M, int K, char* smem, int m0, int n0, float acc[4][4][4])
{
    uint32_t sb = smem_u32(smem);
    int tid = threadIdx.x;
    int warp = tid >> 5, lane = tid & 31;
    int wm = warp & 1, wn = warp >> 1;
    int g = lane >> 2, q = lane & 3;

    int nchunks = K >> 5;
    int lrow = tid >> 2, lseg = tid & 3;
    auto load_chunk = [&](int stg, int k0) {
        #pragma unroll
        for (int it = 0; it < 2; it++) {
            int row = lrow + it * 64;
            uint32_t soff = sb + stg * STAGE_B + (uint32_t)(row * SAS + lseg * 8) * 2;
            int gm = m0 + row;
            int pa = (gm < M) ? 16 : 0;
            int gmc = (gm < M) ? gm : (M - 1);
            cp16(soff,              Ahi + (size_t)gmc * lda + k0 + lseg * 8, pa);
            cp16(soff + TILE_B,     Alo + (size_t)gmc * lda + k0 + lseg * 8, pa);
            int gn = n0 + row;
            cp16(soff + 2 * TILE_B, Bhi + (size_t)gn * K + k0 + lseg * 8, 16);
            cp16(soff + 3 * TILE_B, Blo + (size_t)gn * K + k0 + lseg * 8, 16);
        }
        asm volatile("cp.async.commit_group;" ::: "memory");
    };

    uint32_t lm_off = (uint32_t)((wm * 64 + (lane & 15)) * SAS + (lane >> 4) * 8) * 2;

    load_chunk(0, 0);
    for (int c = 0; c < nchunks; c++) {
        if (c + 1 < nchunks) {
            load_chunk((c + 1) & 1, (c + 1) << 5);
            asm volatile("cp.async.wait_group 1;" ::: "memory");
        } else {
            asm volatile("cp.async.wait_group 0;" ::: "memory");
        }
        __syncthreads();

        uint32_t stage_u = sb + (c & 1) * STAGE_B;
        const __nv_bfloat16* sBh = (const __nv_bfloat16*)(smem + (c & 1) * STAGE_B + 2 * TILE_B);
        const __nv_bfloat16* sBl = sBh + 128 * SAS;

        #pragma unroll
        for (int ks = 0; ks < 2; ks++) {
            int kb = ks * 16;
            uint32_t a[4][4], bh[4][2], bl[2];
            #pragma unroll
            for (int mf = 0; mf < 4; mf++)
                ldm4(a[mf], stage_u + lm_off + (uint32_t)(mf * 16 * SAS + kb) * 2);
            #pragma unroll
            for (int nf = 0; nf < 4; nf++) {
                const __nv_bfloat16* bb = sBh + (wn * 32 + nf * 8 + g) * SAS + kb + q * 2;
                bh[nf][0] = *(const uint32_t*)bb;
                bh[nf][1] = *(const uint32_t*)(bb + 8);
            }
            #pragma unroll
            for (int nf = 0; nf < 4; nf++)
                #pragma unroll
                for (int mf = 0; mf < 4; mf++) mma16816(acc[mf][nf], a[mf], bh[nf]);
            #pragma unroll
            for (int nf = 0; nf < 4; nf++) {
                const __nv_bfloat16* bb = sBl + (wn * 32 + nf * 8 + g) * SAS + kb + q * 2;
                bl[0] = *(const uint32_t*)bb;
                bl[1] = *(const uint32_t*)(bb + 8);
                #pragma unroll
                for (int mf = 0; mf < 4; mf++) mma16816(acc[mf][nf], a[mf], bl);
            }
            #pragma unroll
            for (int mf = 0; mf < 4; mf++)
                ldm4(a[mf], stage_u + TILE_B + lm_off + (uint32_t)(mf * 16 * SAS + kb) * 2);
            #pragma unroll
            for (int nf = 0; nf < 4; nf++)
                #pragma unroll
                for (int mf = 0; mf < 4; mf++) mma16816(acc[mf][nf], a[mf], bh[nf]);
        }
        __syncthreads();
    }
}

// GEMM body with store epilogue; optional split output
template <bool BIAS, bool RELU, bool SPLIT>
__device__ __forceinline__ void mma_gemm_body(
    const __nv_bfloat16* __restrict__ Ahi, const __nv_bfloat16* __restrict__ Alo, int lda,
    const __nv_bfloat16* __restrict__ Bhi, const __nv_bfloat16* __restrict__ Blo,
    const float* __restrict__ bias, float* __restrict__ C, int ldc,
    int M, int K, char* smem,
    __nv_bfloat16* SplitH, __nv_bfloat16* SplitL, int lds, int scol)
{
    int tid = threadIdx.x;
    int warp = tid >> 5, lane = tid & 31;
    int wm = warp & 1, wn = warp >> 1;
    int g = lane >> 2, q = lane & 3;
    int m0 = blockIdx.y * 128, n0 = blockIdx.x * 128;

    float acc[4][4][4];
    #pragma unroll
    for (int i = 0; i < 4; i++)
        #pragma unroll
        for (int j = 0; j < 4; j++)
            #pragma unroll
            for (int t = 0; t < 4; t++) acc[i][j][t] = 0.f;

    mma_mainloop(Ahi, Alo, lda, Bhi, Blo, M, K, smem, m0, n0, acc);

    #pragma unroll
    for (int nf = 0; nf < 4; nf++) {
        int col = n0 + wn * 32 + nf * 8 + q * 2;
        float bv0 = 0.f, bv1 = 0.f;
        if (BIAS) { bv0 = __ldg(bias + col); bv1 = __ldg(bias + col + 1); }
        #pragma unroll
        for (int mf = 0; mf < 4; mf++) {
            int r = m0 + wm * 64 + mf * 16 + g;
            float v0 = acc[mf][nf][0] + bv0, v1 = acc[mf][nf][1] + bv1;
            float v2 = acc[mf][nf][2] + bv0, v3 = acc[mf][nf][3] + bv1;
            if (RELU) {
                v0 = fmaxf(v0, 0.f); v1 = fmaxf(v1, 0.f);
                v2 = fmaxf(v2, 0.f); v3 = fmaxf(v3, 0.f);
            }
            if (r < M) {
                *(float2*)&C[(size_t)r * ldc + col] = make_float2(v0, v1);
                if (SPLIT) {
                    SplitH[(size_t)r * lds + scol + col]     = __float2bfloat16(v0);
                    SplitH[(size_t)r * lds + scol + col + 1] = __float2bfloat16(v1);
                    float l0 = v0 - __bfloat162float(__float2bfloat16(v0));
                    float l1 = v1 - __bfloat162float(__float2bfloat16(v1));
                    SplitL[(size_t)r * lds + scol + col]     = __float2bfloat16(l0);
                    SplitL[(size_t)r * lds + scol + col + 1] = __float2bfloat16(l1);
                }
            }
            if (r + 8 < M) {
                *(float2*)&C[(size_t)(r + 8) * ldc + col] = make_float2(v2, v3);
                if (SPLIT) {
                    SplitH[(size_t)(r + 8) * lds + scol + col]     = __float2bfloat16(v2);
                    SplitH[(size_t)(r + 8) * lds + scol + col + 1] = __float2bfloat16(v3);
                    float l2 = v2 - __bfloat162float(__float2bfloat16(v2));
                    float l3 = v3 - __bfloat162float(__float2bfloat16(v3));
                    SplitL[(size_t)(r + 8) * lds + scol + col]     = __float2bfloat16(l2);
                    SplitL[(size_t)(r + 8) * lds + scol + col + 1] = __float2bfloat16(l3);
                }
            }
        }
    }
}

template <bool BIAS, bool RELU>
__global__ __launch_bounds__(256, 2) void k_mma_gemm(
    const __nv_bfloat16* __restrict__ Ahi, const __nv_bfloat16* __restrict__ Alo, int lda,
    const __nv_bfloat16* __restrict__ Bhi, const __nv_bfloat16* __restrict__ Blo,
    const float* __restrict__ bias, float* __restrict__ C, int ldc,
    int M, int K)
{
    extern __shared__ char smem[];
    mma_gemm_body<BIAS, RELU, false>(Ahi, Alo, lda, Bhi, Blo, bias, C, ldc, M, K, smem,
                                     nullptr, nullptr, 0, 0);
}

__global__ __launch_bounds__(256, 2) void k_mma_gemm_split(
    const __nv_bfloat16* __restrict__ Ahi, const __nv_bfloat16* __restrict__ Alo, int lda,
    const __nv_bfloat16* __restrict__ Bhi, const __nv_bfloat16* __restrict__ Blo,
    const float* __restrict__ bias, float* __restrict__ C, int ldc,
    int M, int K,
    __nv_bfloat16* SplitH, __nv_bfloat16* SplitL, int lds, int scol)
{
    extern __shared__ char smem[];
    mma_gemm_body<true, true, true>(Ahi, Alo, lda, Bhi, Blo, bias, C, ldc, M, K, smem,
                                    SplitH, SplitL, lds, scol);
}

__global__ __launch_bounds__(256, 2) void k_mma_gemm_dual(
    const __nv_bfloat16* __restrict__ Ahi0, const __nv_bfloat16* __restrict__ Alo0,
    const __nv_bfloat16* __restrict__ Ahi1, const __nv_bfloat16* __restrict__ Alo1, int lda,
    const __nv_bfloat16* __restrict__ Bhi0, const __nv_bfloat16* __restrict__ Blo0,
    const __nv_bfloat16* __restrict__ Bhi1, const __nv_bfloat16* __restrict__ Blo1,
    const float* __restrict__ bias0, const float* __restrict__ bias1,
    float* __restrict__ C0, float* __restrict__ C1, int ldc,
    int M, int K)
{
    extern __shared__ char smem[];
    if (blockIdx.z == 0)
        mma_gemm_body<true, false, false>(Ahi0, Alo0, lda, Bhi0, Blo0, bias0, C0, ldc, M, K, smem,
                                          nullptr, nullptr, 0, 0);
    else
        mma_gemm_body<true, false, false>(Ahi1, Alo1, lda, Bhi1, Blo1, bias1, C1, ldc, M, K, smem,
                                          nullptr, nullptr, 0, 0);
}

// fusion GEMM with fused per-bbox max epilogue (no [NN,1024] materialization).
// relu values >= 0 -> uint-reinterpret atomicMax is exact. g_big[:,0:1024) must be 0-init.
__global__ __launch_bounds__(256, 2) void k_mma_gemm_pool(
    const __nv_bfloat16* __restrict__ Ahi, const __nv_bfloat16* __restrict__ Alo, int lda,
    const __nv_bfloat16* __restrict__ Bhi, const __nv_bfloat16* __restrict__ Blo,
    const float* __restrict__ bias, const int* __restrict__ bbox_idx,
    int M, int K)
{
    extern __shared__ char smem[];
    int tid = threadIdx.x;
    int warp = tid >> 5, lane = tid & 31;
    int wm = warp & 1, wn = warp >> 1;
    int g = lane >> 2, q = lane & 3;
    int m0 = blockIdx.y * 128, n0 = blockIdx.x * 128;

    float acc[4][4][4];
    #pragma unroll
    for (int i = 0; i < 4; i++)
        #pragma unroll
        for (int j = 0; j < 4; j++)
            #pragma unroll
            for (int t = 0; t < 4; t++) acc[i][j][t] = 0.f;

    mma_mainloop(Ahi, Alo, lda, Bhi, Blo, M, K, smem, m0, n0, acc);

    // bias + relu into registers
    float v[4][4][4];
    #pragma unroll
    for (int nf = 0; nf < 4; nf++) {
        int col = n0 + wn * 32 + nf * 8 + q * 2;
        float bv0 = __ldg(bias + col), bv1 = __ldg(bias + col + 1);
        #pragma unroll
        for (int mf = 0; mf < 4; mf++) {
            v[mf][nf][0] = fmaxf(acc[mf][nf][0] + bv0, 0.f);
            v[mf][nf][1] = fmaxf(acc[mf][nf][1] + bv1, 0.f);
            v[mf][nf][2] = fmaxf(acc[mf][nf][2] + bv0, 0.f);
            v[mf][nf][3] = fmaxf(acc[mf][nf][3] + bv1, 0.f);
        }
    }

    // segment-max epilogue: smem segbuf [<=128 segs][128 cols], reuse pipeline smem
    int* segbuf = (int*)smem;      // fp32 bits, values >= 0 -> int compare OK
    __shared__ int s_blo, s_bhi;
    int mmax = min(m0 + 127, M - 1);
    if (tid == 0) { s_blo = bbox_idx[m0]; s_bhi = bbox_idx[mmax]; }
    __syncthreads();
    int blo = s_blo, bhi = s_bhi;

    // per-thread row bbox ids (8 rows)
    int rb[4][2];
    #pragma unroll
    for (int mf = 0; mf < 4; mf++) {
        int r = m0 + wm * 64 + mf * 16 + g;
        rb[mf][0] = (r < M) ? bbox_idx[r] : -1;
        rb[mf][1] = (r + 8 < M) ? bbox_idx[r + 8] : -1;
    }

    for (int base = blo; base <= bhi; base += 128) {
        int wlen = min(128, bhi - base + 1);
        for (int i = tid; i < wlen * 128; i += 256) segbuf[i] = 0;
        __syncthreads();
        #pragma unroll
        for (int mf = 0; mf < 4; mf++) {
            #pragma unroll
            for (int half = 0; half < 2; half++) {
                int s = rb[mf][half] - base;
                if (s >= 0 && s < wlen) {
                    #pragma unroll
                    for (int nf = 0; nf < 4; nf++) {
                        int j = wn * 32 + nf * 8 + q * 2;
                        atomicMax(&segbuf[s * 128 + j],     __float_as_int(v[mf][nf][half * 2]));
                        atomicMax(&segbuf[s * 128 + j + 1], __float_as_int(v[mf][nf][half * 2 + 1]));
                    }
                }
            }
        }
        __syncthreads();
        for (int i = tid; i < wlen * 128; i += 256) {
            int bits = segbuf[i];
            if (bits != 0) {
                int b = base + (i >> 7);
                int col = n0 + (i & 127);
                atomicMax((unsigned int*)&g_big[(size_t)b * 2816 + col], (unsigned int)bits);
            }
        }
        __syncthreads();
    }
}

// ---------------- fp32 SIMT GEMMs ----------------
template <bool BIAS, bool RELU>
__device__ __forceinline__ void gemm128_body(
    const float* __restrict__ A, int lda, const float* __restrict__ B, int ldb,
    const float* __restrict__ bias, float* __restrict__ C, int ldc,
    int M, int N, int K)
{
    __shared__ float As[8][128];
    __shared__ float Bs[8][128];
    int tid = threadIdx.x;
    int m0 = blockIdx.y * 128, n0 = blockIdx.x * 128;
    int ar = tid >> 1, ac = (tid & 1) * 4;
    int bk = tid >> 5, bn = (tid & 31) * 4;
    int ty = tid >> 4, tx = tid & 15;
    float acc[8][8] = {};
    for (int k0 = 0; k0 < K; k0 += 8) {
        float4 av = make_float4(0.f, 0.f, 0.f, 0.f);
        if (m0 + ar < M) av = *(const float4*)&A[(size_t)(m0 + ar) * lda + k0 + ac];
        As[ac + 0][ar] = av.x; As[ac + 1][ar] = av.y; As[ac + 2][ar] = av.z; As[ac + 3][ar] = av.w;
        float4 bv = make_float4(0.f, 0.f, 0.f, 0.f);
        if (n0 + bn < N) bv = *(const float4*)&B[(size_t)(k0 + bk) * ldb + n0 + bn];
        *(float4*)&Bs[bk][bn] = bv;
        __syncthreads();
        #pragma unroll
        for (int kk = 0; kk < 8; kk++) {
            float a[8], b[8];
            #pragma unroll
            for (int i = 0; i < 8; i++) a[i] = As[kk][ty * 8 + i];
            #pragma unroll
            for (int j = 0; j < 8; j++) b[j] = Bs[kk][tx * 8 + j];
            #pragma unroll
            for (int i = 0; i < 8; i++)
                #pragma unroll
                for (int j = 0; j < 8; j++)
                    acc[i][j] += a[i] * b[j];
        }
        __syncthreads();
    }
    #pragma unroll
    for (int i = 0; i < 8; i++) {
        int m = m0 + ty * 8 + i;
        if (m < M) {
            #pragma unroll
            for (int j = 0; j < 8; j++) {
                int n = n0 + tx * 8 + j;
                if (n < N) {
                    float v = acc[i][j];
                    if (BIAS) v += bias[n];
                    if (RELU) v = fmaxf(v, 0.f);
                    C[(size_t)m * ldc + n] = v;
                }
            }
        }
    }
}

// layer0 dual: z selects weight/bias/output set (same A)
__global__ __launch_bounds__(256) void k_gemm128_dual(
    const float* __restrict__ A, int lda,
    const float* __restrict__ B0, const float* __restrict__ B1, int ldb,
    const float* __restrict__ bias0, const float* __restrict__ bias1,
    float* __restrict__ C0, float* __restrict__ C1, int ldc,
    int M, int N, int K)
{
    if (blockIdx.z == 0)
        gemm128_body<true, false>(A, lda, B0, ldb, bias0, C0, ldc, M, N, K);
    else
        gemm128_body<true, false>(A, lda, B1, ldb, bias1, C1, ldc, M, N, K);
}

template <bool BIAS, bool RELU>
__global__ __launch_bounds__(256) void k_gemm64(
    const float* __restrict__ A, int lda, const float* __restrict__ B, int ldb,
    const float* __restrict__ bias, float* __restrict__ C, int ldc,
    int M, int N, int K)
{
    __shared__ float As[16][64];
    __shared__ float Bs[16][64];
    int tid = threadIdx.x;
    int m0 = blockIdx.y * 64, n0 = blockIdx.x * 64;
    int ar = tid >> 2, ac = (tid & 3) * 4;
    int bk = tid >> 4, bn = (tid & 15) * 4;
    int ty = tid >> 4, tx = tid & 15;
    float acc[4][4] = {};
    for (int k0 = 0; k0 < K; k0 += 16) {
        float4 av = make_float4(0.f, 0.f, 0.f, 0.f);
        if (m0 + ar < M) av = *(const float4*)&A[(size_t)(m0 + ar) * lda + k0 + ac];
        As[ac + 0][ar] = av.x; As[ac + 1][ar] = av.y; As[ac + 2][ar] = av.z; As[ac + 3][ar] = av.w;
        float4 bv = make_float4(0.f, 0.f, 0.f, 0.f);
        if (n0 + bn < N) bv = *(const float4*)&B[(size_t)(k0 + bk) * ldb + n0 + bn];
        *(float4*)&Bs[bk][bn] = bv;
        __syncthreads();
        #pragma unroll
        for (int kk = 0; kk < 16; kk++) {
            float a[4], b[4];
            #pragma unroll
            for (int i = 0; i < 4; i++) a[i] = As[kk][ty * 4 + i];
            #pragma unroll
            for (int j = 0; j < 4; j++) b[j] = Bs[kk][tx * 4 + j];
            #pragma unroll
            for (int i = 0; i < 4; i++)
                #pragma unroll
                for (int j = 0; j < 4; j++)
                    acc[i][j] += a[i] * b[j];
        }
        __syncthreads();
    }
    #pragma unroll
    for (int i = 0; i < 4; i++) {
        int m = m0 + ty * 4 + i;
        if (m < M) {
            #pragma unroll
            for (int j = 0; j < 4; j++) {
                int n = n0 + tx * 4 + j;
                if (n < N) {
                    float v = acc[i][j];
                    if (BIAS) v += bias[n];
                    if (RELU) v = fmaxf(v, 0.f);
                    C[(size_t)m * ldc + n] = v;
                }
            }
        }
    }
}

// ---------------- fused edge conv (frozen body) + residual + bf16 split ----------------
__global__ __launch_bounds__(256) void k_edgeconv(
    const float* __restrict__ e_attr,
    const float* __restrict__ W3n, const float* __restrict__ W3s,
    const float* __restrict__ PQ, const float* __restrict__ PQs,
    const float* __restrict__ prevN, const float* __restrict__ prevS,
    float* __restrict__ outN, float* __restrict__ outS,
    __nv_bfloat16* __restrict__ outNh, __nv_bfloat16* __restrict__ outNl,
    __nv_bfloat16* __restrict__ outSh, __nv_bfloat16* __restrict__ outSl)
{
    __shared__ float sW3n[768];
    __shared__ float sW3s[768];
    for (int i = threadIdx.x; i < 768; i += blockDim.x) { sW3n[i] = W3n[i]; sW3s[i] = W3s[i]; }
    __syncthreads();
    int warp = threadIdx.x >> 5, lane = threadIdx.x & 31;
    int node = blockIdx.x * (blockDim.x >> 5) + warp;
    if (node >= NN) return;
    int r0 = g_rowptr[node], r1 = g_rowptr[node + 1];
    int c = lane * 4;
    float4 qn = *(const float4*)(PQ  + node * 256 + 128 + c);
    float4 qs = *(const float4*)(PQs + node * 256 + 128 + c);
    float mx0 = 0.f, mx1 = 0.f, mx2 = 0.f, mx3 = 0.f;
    float sm0 = 0.f, sm1 = 0.f, sm2 = 0.f, sm3 = 0.f;
    for (int e = r0; e < r1; ++e) {
        int s  = g_csr_src[e];
        int id = g_csr_eid[e];
        float4 p  = *(const float4*)(PQ  + s * 256 + c);
        float4 ps = *(const float4*)(PQs + s * 256 + c);
        float a0 = p.x + qn.x, a1 = p.y + qn.y, a2 = p.z + qn.z, a3 = p.w + qn.w;
        float b0 = ps.x + qs.x, b1 = ps.y + qs.y, b2 = ps.z + qs.z, b3 = ps.w + qs.w;
        #pragma unroll
        for (int k = 0; k < 6; k++) {
            float ev = __ldg(e_attr + (size_t)id * 6 + k);
            const float* wn = sW3n + k * 128 + c;
            const float* ws = sW3s + k * 128 + c;
            a0 += ev * wn[0]; a1 += ev * wn[1]; a2 += ev * wn[2]; a3 += ev * wn[3];
            b0 += ev * ws[0]; b1 += ev * ws[1]; b2 += ev * ws[2]; b3 += ev * ws[3];
        }
        a0 = fmaxf(a0, 0.f); a1 = fmaxf(a1, 0.f); a2 = fmaxf(a2, 0.f); a3 = fmaxf(a3, 0.f);
        mx0 = fmaxf(mx0, a0); mx1 = fmaxf(mx1, a1); mx2 = fmaxf(mx2, a2); mx3 = fmaxf(mx3, a3);
        b0 = fmaxf(b0, 0.f); b1 = fmaxf(b1, 0.f); b2 = fmaxf(b2, 0.f); b3 = fmaxf(b3, 0.f);
        sm0 += b0; sm1 += b1; sm2 += b2; sm3 += b3;
    }
    int deg = r1 - r0;
    float inv = 1.f / (float)(deg > 0 ? deg : 1);
    float f0 = mx0, f1 = mx1, f2 = mx2, f3 = mx3;
    float s0 = sm0 * inv, s1 = sm1 * inv, s2 = sm2 * inv, s3 = sm3 * inv;
    if (prevN) {
        float4 pn = *(const float4*)(prevN + node * 384 + c);
        f0 += pn.x; f1 += pn.y; f2 += pn.z; f3 += pn.w;
        float4 pv = *(const float4*)(prevS + node * 384 + c);
        s0 += pv.x; s1 += pv.y; s2 += pv.z; s3 += pv.w;
    }
    *(float4*)(outN + node * 384 + c) = make_float4(f0, f1, f2, f3);
    *(float4*)(outS + node * 384 + c) = make_float4(s0, s1, s2, s3);
    uint2 u;
    u.x = bfpack(f0, f1); u.y = bfpack(f2, f3);
    *(uint2*)(outNh + node * 384 + c) = u;
    float r0f = f0 - __bfloat162float(__float2bfloat16(f0));
    float r1f = f1 - __bfloat162float(__float2bfloat16(f1));
    float r2f = f2 - __bfloat162float(__float2bfloat16(f2));
    float r3f = f3 - __bfloat162float(__float2bfloat16(f3));
    u.x = bfpack(r0f, r1f); u.y = bfpack(r2f, r3f);
    *(uint2*)(outNl + node * 384 + c) = u;
    u.x = bfpack(s0, s1); u.y = bfpack(s2, s3);
    *(uint2*)(outSh + node * 384 + c) = u;
    r0f = s0 - __bfloat162float(__float2bfloat16(s0));
    r1f = s1 - __bfloat162float(__float2bfloat16(s1));
    r2f = s2 - __bfloat162float(__float2bfloat16(s2));
    r3f = s3 - __bfloat162float(__float2bfloat16(s3));
    u.x = bfpack(r0f, r1f); u.y = bfpack(r2f, r3f);
    *(uint2*)(outSl + node * 384 + c) = u;
}

// ---------------- combined bbox pooling ----------------
// blocks [0,NBB): super mean (+ splits). blocks [NBB,2NBB): fusion-max convert (cols<1024,
// reading atomicMax results in g_big) + feats max (cols 1024-1408), + splits.
__global__ void k_pool_both() {
    int blk = blockIdx.x;
    if (blk < NBB) {
        int b = blk;
        int c = threadIdx.x;            // blockDim = 384
        int r0 = g_bboxptr[b], r1 = g_bboxptr[b + 1];
        float s = 0.f;
        for (int n = r0; n < r1; n++) s += g_featsS[n * 384 + c];
        int cnt = r1 - r0;
        float v = s / (float)(cnt > 0 ? cnt : 1);
        g_big[b * 2816 + 2432 + c] = v;
        __nv_bfloat16 h = __float2bfloat16(v);
        __nv_bfloat16 l = __float2bfloat16(v - __bfloat162float(h));
        g_Sh[b * 384 + c] = h;
        g_Sl[b * 384 + c] = l;
        g_Mh[b * 2816 + 2432 + c] = h;
        g_Ml[b * 2816 + 2432 + c] = l;
    } else {
        int b = blk - NBB;
        int r0 = g_bboxptr[b], r1 = g_bboxptr[b + 1];
        for (int c = threadIdx.x; c < 1408; c += blockDim.x) {
            float m;
            if (c < 1024) {
                m = g_big[b * 2816 + c];    // atomicMax result (0 if empty)
            } else {
                m = -FLT_MAX;
                int cc = c - 1024;
                for (int n = r0; n < r1; n++) m = fmaxf(m, g_feats[n * 384 + cc]);
                if (r1 == r0) m = 0.f;
                g_big[b * 2816 + c] = m;
            }
            __nv_bfloat16 h = __float2bfloat16(m);
            g_Mh[b * 2816 + c] = h;
            g_Ml[b * 2816 + c] = __float2bfloat16(m - __bfloat162float(h));
        }
    }
}

// ---------------- launch ----------------
extern "C" void kernel_launch(void* const* d_in, const int* in_sizes, int n_in,
                              void* d_out, int out_size)
{
    const float* x     = (const float*)d_in[0];
    const float* eat   = (const float*)d_in[1];
    const float* W_h   = (const float*)d_in[2];
    const float* b_h   = (const float*)d_in[3];
    const float* Ws_h  = (const float*)d_in[4];
    const float* bs_h  = (const float*)d_in[5];
    const float* Wb    = (const float*)d_in[6];
    const float* bb    = (const float*)d_in[7];
    const float* Wbs   = (const float*)d_in[8];
    const float* bbs   = (const float*)d_in[9];
    const float* W_f   = (const float*)d_in[10];
    const float* b_f   = (const float*)d_in[11];
    const float* W_fs  = (const float*)d_in[12];
    const float* b_fs  = (const float*)d_in[13];
    const float* W1    = (const float*)d_in[14];
    const float* b1    = (const float*)d_in[15];
    const float* W2    = (const float*)d_in[16];
    const float* b2    = (const float*)d_in[17];
    const float* W3c   = (const float*)d_in[18];
    const float* b3    = (const float*)d_in[19];
    const int*   edge  = (const int*)d_in[20];
    const int*   bbox  = (const int*)d_in[21];
    const int* src = edge;
    const int* dst = edge + NE;
    float* out = (float*)d_out;

    float *pFeats, *pFeatsS, *pPQ, *pPQs, *pBig, *pH1, *pH2, *pWcn, *pWcs, *pb256h, *pb256;
    __nv_bfloat16 *pAh, *pAl, *pSh, *pSl, *pMh, *pMl;
    __nv_bfloat16 *pBfh, *pBfl, *pBfsh, *pBfsl, *pB1h, *pB1l, *pwbh, *pwbl;
    int *pHist;
    cudaGetSymbolAddress((void**)&pFeats,  g_feats);
    cudaGetSymbolAddress((void**)&pFeatsS, g_featsS);
    cudaGetSymbolAddress((void**)&pPQ,  g_PQ);
    cudaGetSymbolAddress((void**)&pPQs, g_PQs);
    cudaGetSymbolAddress((void**)&pBig, g_big);
    cudaGetSymbolAddress((void**)&pH1,  g_h1);
    cudaGetSymbolAddress((void**)&pH2,  g_h2);
    cudaGetSymbolAddress((void**)&pWcn, g_Wcn);
    cudaGetSymbolAddress((void**)&pWcs, g_Wcs);
    cudaGetSymbolAddress((void**)&pb256h, g_b256h);
    cudaGetSymbolAddress((void**)&pb256, g_b256);
    cudaGetSymbolAddress((void**)&pHist, g_hist);
    cudaGetSymbolAddress((void**)&pAh, g_Ah);
    cudaGetSymbolAddress((void**)&pAl, g_Al);
    cudaGetSymbolAddress((void**)&pSh, g_Sh);
    cudaGetSymbolAddress((void**)&pSl, g_Sl);
    cudaGetSymbolAddress((void**)&pMh, g_Mh);
    cudaGetSymbolAddress((void**)&pMl, g_Ml);
    cudaGetSymbolAddress((void**)&pBfh, g_Bfh);
    cudaGetSymbolAddress((void**)&pBfl, g_Bfl);
    cudaGetSymbolAddress((void**)&pBfsh, g_Bfsh);
    cudaGetSymbolAddress((void**)&pBfsl, g_Bfsl);
    cudaGetSymbolAddress((void**)&pB1h, g_B1h);
    cudaGetSymbolAddress((void**)&pB1l, g_B1l);
    cudaGetSymbolAddress((void**)&pwbh, g_wbh);
    cudaGetSymbolAddress((void**)&pwbl, g_wbl);

    cudaFuncSetAttribute(k_mma_gemm<true, false>, cudaFuncAttributeMaxDynamicSharedMemorySize, TCSM);
    cudaFuncSetAttribute(k_mma_gemm<true, true>,  cudaFuncAttributeMaxDynamicSharedMemorySize, TCSM);
    cudaFuncSetAttribute(k_mma_gemm_dual,         cudaFuncAttributeMaxDynamicSharedMemorySize, TCSM);
    cudaFuncSetAttribute(k_mma_gemm_split,        cudaFuncAttributeMaxDynamicSharedMemorySize, TCSM);
    cudaFuncSetAttribute(k_mma_gemm_pool,         cudaFuncAttributeMaxDynamicSharedMemorySize, TCSM);

    // zero-init hist + g_big (fusion-max atomic targets need 0; rest overwritten later)
    cudaMemsetAsync(pHist, 0, NN * sizeof(int), 0);
    cudaMemsetAsync(pBig, 0, (size_t)NBB * 2816 * sizeof(float), 0);

    // CSR by dst + bbox ranges (bboxptr folded into scan3)
    k_count<<<(NE + 255) / 256, 256>>>(dst);
    int nblk = (NN + 255) / 256;
    k_scan1<<<nblk, 256>>>();
    k_scan2<<<1, 256>>>(nblk);
    k_scan3<<<nblk, 256>>>(bbox);
    k_fill<<<(NE + 255) / 256, 256>>>(src, dst);

    // merged weight preps (3 launches total)
    {
        dim3 gw(5632, 1, 3);
        k_wsplit3<<<gw, 256>>>(W_f, W_fs, W1);
        dim3 gp(128, 1, 4);
        k_prep_layerW_all<<<gp, 256>>>(Wb, bb, Wbs, bbs);
        dim3 gh(8, 1, 2);
        k_prep_head_dual<<<gh, 256>>>(W_h, b_h, Ws_h, bs_h);
    }

    // ---- layer 0 (inC=8) ----
    {
        dim3 g1(2, (NN + 127) / 128, 2);
        k_gemm128_dual<<<g1, 256>>>(x, 8, pWcn, pWcs, 256, pb256h, pb256h + 256,
                                    pPQ, pPQs, 256, NN, 256, 8);
        k_edgeconv<<<(NN + 7) / 8, 256>>>(eat, W_h + 2048, Ws_h + 2048,
                                          pPQ, pPQs, nullptr, nullptr,
                                          pFeats, pFeatsS,
                                          pAh, pAl, pSh, pSl);
    }

    // ---- layers 1,2: split-bf16 HMMA (node+super merged) ----
    for (int i = 1; i < 3; i++) {
        const float* W  = Wb  + (size_t)(i - 1) * 262 * 128;
        const float* Ws = Wbs + (size_t)(i - 1) * 262 * 128;
        const int nW = 256 * 128;
        int z0 = 2 * (i - 1);

        dim3 gl(2, (NN + 127) / 128, 2);
        k_mma_gemm_dual<<<gl, 256, TCSM>>>(
            pAh + (i - 1) * 128, pAl + (i - 1) * 128,
            pSh + (i - 1) * 128, pSl + (i - 1) * 128, 384,
            pwbh + (size_t)z0 * nW, pwbl + (size_t)z0 * nW,
            pwbh + (size_t)(z0 + 1) * nW, pwbl + (size_t)(z0 + 1) * nW,
            pb256 + z0 * 256, pb256 + (z0 + 1) * 256,
            pPQ, pPQs, 256, NN, 128);

        k_edgeconv<<<(NN + 7) / 8, 256>>>(eat, W + 2 * 128 * 128, Ws + 2 * 128 * 128,
                                          pPQ, pPQs,
                                          pFeats + (i - 1) * 128, pFeatsS + (i - 1) * 128,
                                          pFeats + i * 128, pFeatsS + i * 128,
                                          pAh + i * 128, pAl + i * 128,
                                          pSh + i * 128, pSl + i * 128);
    }

    // ---- fusion GEMM + fused bbox max (no [NN,1024] buffer) ----
    {
        dim3 g(8, (NN + 127) / 128);
        k_mma_gemm_pool<<<g, 256, TCSM>>>(pAh, pAl, 384, pBfh, pBfl, b_f, bbox, NN, 384);
    }

    // ---- bbox pooling: super mean + fusion-max convert + feats max ----
    k_pool_both<<<2 * NBB, 384>>>();

    // ---- fusion_super (split epilogue feeds MLP input cols [1408, 2432)) ----
    {
        dim3 g(8, (NBB + 127) / 128);
        k_mma_gemm_split<<<g, 256, TCSM>>>(pSh, pSl, 384, pBfsh, pBfsl, b_fs,
                                           pBig + 1408, 2816, NBB, 384,
                                           pMh, pMl, 2816, 1408);
    }

    // ---- MLP head ----
    {
        dim3 g(4, (NBB + 127) / 128);
        k_mma_gemm<true, true><<<g, 256, TCSM>>>(pMh, pMl, 2816, pB1h, pB1l, b1, pH1, 512, NBB, 2816);
    }
    dim3 gm2(4, (NBB + 63) / 64);
    k_gemm64<true, true><<<gm2, 256>>>(pH1, 512, W2, 256, b2, pH2, 256, NBB, 256, 512);
    dim3 gm3(1, (NBB + 63) / 64);
    k_gemm64<true, false><<<gm3, 256>>>(pH2, 256, W3c, 32, b3, out, 32, NBB, 32, 256);
}

// round 16
// speedup vs baseline: 1.1521x; 1.0448x over previous
#include <cuda_runtime.h>
#include <cuda_bf16.h>
#include <math.h>
#include <float.h>
#include <cstdint>

#define NN 50000
#define NE 800000
#define NBB 2000

// ---------------- scratch (static device globals; no allocation) ----------------
__device__ float g_feats [NN * 384];
__device__ float g_featsS[NN * 384];
__device__ float g_PQ [NN * 256];        // [P(128) | Q(128)] node stream
__device__ float g_PQs[NN * 256];        // super stream
__device__ float g_big[NBB * 2816];      // [pooled(1408) | fusionS(1024) | superFeats(384)]
__device__ float g_h1[NBB * 512];
__device__ float g_h2[NBB * 256];
__device__ float g_part[4 * NBB * 512];  // split-K partials for MLP W1
__device__ float g_Wcn[8 * 256];         // layer0 combined weights [8, 256]
__device__ float g_Wcs[8 * 256];
__device__ float g_b256h[512];           // layer0 biases [node | super]
__device__ float g_b256[4 * 256];        // layer1,2 biases [L1n, L1s, L2n, L2s]
__device__ int   g_hist[NN];
__device__ int   g_rowptr[NN + 1];
__device__ int   g_wcur[NN];
__device__ int   g_csr_src[NE];
__device__ int   g_csr_eid[NE];
__device__ int   g_bboxptr[NBB + 1];
__device__ int   g_bsum[256];
__device__ int   g_boff[256];
// bf16 split buffers
__device__ __align__(16) __nv_bfloat16 g_Ah[NN * 384];
__device__ __align__(16) __nv_bfloat16 g_Al[NN * 384];
__device__ __align__(16) __nv_bfloat16 g_Sh[NN * 384];   // conv super splits; reused post-conv as fusion_super input
__device__ __align__(16) __nv_bfloat16 g_Sl[NN * 384];
__device__ __align__(16) __nv_bfloat16 g_Mh[NBB * 2816]; // MLP head split input
__device__ __align__(16) __nv_bfloat16 g_Ml[NBB * 2816];
__device__ __align__(16) __nv_bfloat16 g_Bfh[1024 * 384];
__device__ __align__(16) __nv_bfloat16 g_Bfl[1024 * 384];
__device__ __align__(16) __nv_bfloat16 g_Bfsh[1024 * 384];
__device__ __align__(16) __nv_bfloat16 g_Bfsl[1024 * 384];
__device__ __align__(16) __nv_bfloat16 g_B1h[512 * 2816];
__device__ __align__(16) __nv_bfloat16 g_B1l[512 * 2816];
__device__ __align__(16) __nv_bfloat16 g_wbh[4 * 256 * 128];  // [L1n, L1s, L2n, L2s]
__device__ __align__(16) __nv_bfloat16 g_wbl[4 * 256 * 128];

// ---------------- CSR build ----------------
__global__ void k_count(const int* __restrict__ dst) {
    int e = blockIdx.x * blockDim.x + threadIdx.x;
    if (e < NE) atomicAdd(&g_hist[dst[e]], 1);
}

__device__ __forceinline__ int block_incl_scan256(int v, int tid) {
    __shared__ int ws[8];
    int x = v;
    #pragma unroll
    for (int o = 1; o < 32; o <<= 1) {
        int t = __shfl_up_sync(0xFFFFFFFFu, x, o);
        if ((tid & 31) >= o) x += t;
    }
    if ((tid & 31) == 31) ws[tid >> 5] = x;
    __syncthreads();
    if (tid < 8) {
        int w = ws[tid];
        #pragma unroll
        for (int o = 1; o < 8; o <<= 1) {
            int t = __shfl_up_sync(0xFFu, w, o);
            if (tid >= o) w += t;
        }
        ws[tid] = w;
    }
    __syncthreads();
    return x + ((tid >= 32) ? ws[(tid >> 5) - 1] : 0);
}

__global__ void k_scan1() {
    int tid = threadIdx.x;
    int i = blockIdx.x * 256 + tid;
    int v = (i < NN) ? g_hist[i] : 0;
    int incl = block_incl_scan256(v, tid);
    if (i < NN) g_rowptr[i + 1] = incl;
    if (tid == 255) g_bsum[blockIdx.x] = incl;
}
__global__ void k_scan2(int nblk) {
    int tid = threadIdx.x;
    int v = (tid < nblk) ? g_bsum[tid] : 0;
    int incl = block_incl_scan256(v, tid);
    if (tid < nblk) g_boff[tid] = incl - v;
}
// scan3 + bbox range search folded together
__global__ void k_scan3(const int* __restrict__ bbox_idx) {
    int i = blockIdx.x * 256 + threadIdx.x;
    if (i < NN) {
        int r = g_rowptr[i + 1] + g_boff[blockIdx.x];
        g_rowptr[i + 1] = r;
        g_wcur[i] = r - g_hist[i];
    }
    if (i == 0) g_rowptr[0] = 0;
    if (i <= NBB) {
        int lo = 0, hi = NN;
        while (lo < hi) {
            int mid = (lo + hi) >> 1;
            if (bbox_idx[mid] < i) lo = mid + 1; else hi = mid;
        }
        g_bboxptr[i] = lo;
    }
}

__global__ void k_fill(const int* __restrict__ src, const int* __restrict__ dst) {
    int e = blockIdx.x * blockDim.x + threadIdx.x;
    if (e < NE) {
        int d = dst[e];
        int pos = atomicAdd(&g_wcur[d], 1);
        g_csr_src[pos] = src[e];
        g_csr_eid[pos] = e;
    }
}

// layer0 combined weights, both streams in one launch (z selects)
__global__ void k_prep_head_dual(const float* __restrict__ Wn, const float* __restrict__ bn,
                                 const float* __restrict__ Ws, const float* __restrict__ bs) {
    const float* W    = blockIdx.z ? Ws : Wn;
    const float* bias = blockIdx.z ? bs : bn;
    float* Wc   = blockIdx.z ? g_Wcs : g_Wcn;
    float* b256 = g_b256h + blockIdx.z * 256;
    int idx = blockIdx.x * blockDim.x + threadIdx.x;
    if (idx < 8 * 256) {
        int k = idx >> 8, n = idx & 255;
        float v = (n < 128) ? (W[k * 128 + n] - W[(8 + k) * 128 + n])
                            : W[(8 + k) * 128 + (n - 128)];
        Wc[idx] = v;
    }
    if (idx < 256) b256[idx] = (idx < 128) ? 0.f : bias[idx - 128];
}

// all 4 layer-weight preps in one launch: z = 2*(layer-1) + stream
__global__ void k_prep_layerW_all(const float* __restrict__ Wb, const float* __restrict__ bb,
                                  const float* __restrict__ Wbs, const float* __restrict__ bbs) {
    int z = blockIdx.z;
    int li = z >> 1, st = z & 1;
    const float* W    = (st ? Wbs : Wb)  + (size_t)li * 262 * 128;
    const float* bias = (st ? bbs : bb)  + li * 128;
    __nv_bfloat16* hi = g_wbh + (size_t)z * 256 * 128;
    __nv_bfloat16* lo = g_wbl + (size_t)z * 256 * 128;
    float* bias256 = g_b256 + z * 256;
    int idx = blockIdx.x * blockDim.x + threadIdx.x;
    if (idx < 256 * 128) {
        int n = idx >> 7, k = idx & 127;
        float v;
        if (n < 128) v = W[k * 128 + n] - W[(128 + k) * 128 + n];
        else         v = W[(128 + k) * 128 + (n - 128)];
        __nv_bfloat16 h = __float2bfloat16(v);
        hi[idx] = h;
        lo[idx] = __float2bfloat16(v - __bfloat162float(h));
    }
    if (idx < 256) bias256[idx] = (idx < 128) ? 0.f : bias[idx - 128];
}

// 3 big weight transpose+splits in one launch: z = {W_f, W_fs, W1}
__global__ void k_wsplit3(const float* __restrict__ W_f,
                          const float* __restrict__ W_fs,
                          const float* __restrict__ W1) {
    int z = blockIdx.z;
    const float* W;
    __nv_bfloat16 *hi, *lo;
    int K, N;
    if (z == 0)      { W = W_f;  hi = g_Bfh;  lo = g_Bfl;  K = 384;  N = 1024; }
    else if (z == 1) { W = W_fs; hi = g_Bfsh; lo = g_Bfsl; K = 384;  N = 1024; }
    else             { W = W1;   hi = g_B1h;  lo = g_B1l;  K = 2816; N = 512; }
    int idx = blockIdx.x * blockDim.x + threadIdx.x;
    if (idx < K * N) {
        int nn = idx / K, kk = idx - nn * K;
        float a = W[(size_t)kk * N + nn];
        __nv_bfloat16 h = __float2bfloat16(a);
        hi[idx] = h;
        lo[idx] = __float2bfloat16(a - __bfloat162float(h));
    }
}

// ---------------- split-bf16 HMMA GEMM (cp.async pipeline + ldmatrix) ----------------
__device__ __forceinline__ void mma16816(float* c, const uint32_t* a, const uint32_t* b) {
    asm volatile(
        "mma.sync.aligned.m16n8k16.row.col.f32.bf16.bf16.f32 "
        "{%0,%1,%2,%3}, {%4,%5,%6,%7}, {%8,%9}, {%0,%1,%2,%3};"
        : "+f"(c[0]), "+f"(c[1]), "+f"(c[2]), "+f"(c[3])
        : "r"(a[0]), "r"(a[1]), "r"(a[2]), "r"(a[3]), "r"(b[0]), "r"(b[1]));
}
__device__ __forceinline__ void ldm4(uint32_t* r, uint32_t addr) {
    asm volatile("ldmatrix.sync.aligned.m8n8.x4.shared.b16 {%0,%1,%2,%3}, [%4];"
                 : "=r"(r[0]), "=r"(r[1]), "=r"(r[2]), "=r"(r[3]) : "r"(addr));
}
__device__ __forceinline__ void cp16(uint32_t dst, const void* src, int nbytes) {
    asm volatile("cp.async.cg.shared.global [%0], [%1], 16, %2;"
                 :: "r"(dst), "l"(src), "r"(nbytes));
}
__device__ __forceinline__ uint32_t smem_u32(const void* p) {
    uint32_t a;
    asm("{ .reg .u64 t; cvta.to.shared.u64 t, %1; cvt.u32.u64 %0, t; }" : "=r"(a) : "l"(p));
    return a;
}
__device__ __forceinline__ uint32_t bfpack(float a, float b) {
    return (uint32_t)__bfloat16_as_ushort(__float2bfloat16(a)) |
           ((uint32_t)__bfloat16_as_ushort(__float2bfloat16(b)) << 16);
}

#define SAS 40                   // smem row stride in halves
#define TILE_B (128 * SAS * 2)   // 10240 bytes per tile
#define STAGE_B (4 * TILE_B)     // 40960 bytes per stage
#define TCSM (2 * STAGE_B)       // 81920 dynamic smem

// shared mainloop: accumulates the 128x128 tile into acc; ldb = B row stride (>= K)
__device__ __forceinline__ void mma_mainloop(
    const __nv_bfloat16* __restrict__ Ahi, const __nv_bfloat16* __restrict__ Alo, int lda,
    const __nv_bfloat16* __restrict__ Bhi, const __nv_bfloat16* __restrict__ Blo, int ldb,
    int M, int K, char* smem, int m0, int n0, float acc[4][4][4])
{
    uint32_t sb = smem_u32(smem);
    int tid = threadIdx.x;
    int warp = tid >> 5, lane = tid & 31;
    int wm = warp & 1, wn = warp >> 1;
    int g = lane >> 2, q = lane & 3;

    int nchunks = K >> 5;
    int lrow = tid >> 2, lseg = tid & 3;
    auto load_chunk = [&](int stg, int k0) {
        #pragma unroll
        for (int it = 0; it < 2; it++) {
            int row = lrow + it * 64;
            uint32_t soff = sb + stg * STAGE_B + (uint32_t)(row * SAS + lseg * 8) * 2;
            int gm = m0 + row;
            int pa = (gm < M) ? 16 : 0;
            int gmc = (gm < M) ? gm : (M - 1);
            cp16(soff,              Ahi + (size_t)gmc * lda + k0 + lseg * 8, pa);
            cp16(soff + TILE_B,     Alo + (size_t)gmc * lda + k0 + lseg * 8, pa);
            int gn = n0 + row;
            cp16(soff + 2 * TILE_B, Bhi + (size_t)gn * ldb + k0 + lseg * 8, 16);
            cp16(soff + 3 * TILE_B, Blo + (size_t)gn * ldb + k0 + lseg * 8, 16);
        }
        asm volatile("cp.async.commit_group;" ::: "memory");
    };

    uint32_t lm_off = (uint32_t)((wm * 64 + (lane & 15)) * SAS + (lane >> 4) * 8) * 2;

    load_chunk(0, 0);
    for (int c = 0; c < nchunks; c++) {
        if (c + 1 < nchunks) {
            load_chunk((c + 1) & 1, (c + 1) << 5);
            asm volatile("cp.async.wait_group 1;" ::: "memory");
        } else {
            asm volatile("cp.async.wait_group 0;" ::: "memory");
        }
        __syncthreads();

        uint32_t stage_u = sb + (c & 1) * STAGE_B;
        const __nv_bfloat16* sBh = (const __nv_bfloat16*)(smem + (c & 1) * STAGE_B + 2 * TILE_B);
        const __nv_bfloat16* sBl = sBh + 128 * SAS;

        #pragma unroll
        for (int ks = 0; ks < 2; ks++) {
            int kb = ks * 16;
            uint32_t a[4][4], bh[4][2], bl[2];
            #pragma unroll
            for (int mf = 0; mf < 4; mf++)
                ldm4(a[mf], stage_u + lm_off + (uint32_t)(mf * 16 * SAS + kb) * 2);
            #pragma unroll
            for (int nf = 0; nf < 4; nf++) {
                const __nv_bfloat16* bb = sBh + (wn * 32 + nf * 8 + g) * SAS + kb + q * 2;
                bh[nf][0] = *(const uint32_t*)bb;
                bh[nf][1] = *(const uint32_t*)(bb + 8);
            }
            #pragma unroll
            for (int nf = 0; nf < 4; nf++)
                #pragma unroll
                for (int mf = 0; mf < 4; mf++) mma16816(acc[mf][nf], a[mf], bh[nf]);
            #pragma unroll
            for (int nf = 0; nf < 4; nf++) {
                const __nv_bfloat16* bb = sBl + (wn * 32 + nf * 8 + g) * SAS + kb + q * 2;
                bl[0] = *(const uint32_t*)bb;
                bl[1] = *(const uint32_t*)(bb + 8);
                #pragma unroll
                for (int mf = 0; mf < 4; mf++) mma16816(acc[mf][nf], a[mf], bl);
            }
            #pragma unroll
            for (int mf = 0; mf < 4; mf++)
                ldm4(a[mf], stage_u + TILE_B + lm_off + (uint32_t)(mf * 16 * SAS + kb) * 2);
            #pragma unroll
            for (int nf = 0; nf < 4; nf++)
                #pragma unroll
                for (int mf = 0; mf < 4; mf++) mma16816(acc[mf][nf], a[mf], bh[nf]);
        }
        __syncthreads();
    }
}

// GEMM body with store epilogue; optional split output
template <bool BIAS, bool RELU, bool SPLIT>
__device__ __forceinline__ void mma_gemm_body(
    const __nv_bfloat16* __restrict__ Ahi, const __nv_bfloat16* __restrict__ Alo, int lda,
    const __nv_bfloat16* __restrict__ Bhi, const __nv_bfloat16* __restrict__ Blo,
    const float* __restrict__ bias, float* __restrict__ C, int ldc,
    int M, int K, char* smem,
    __nv_bfloat16* SplitH, __nv_bfloat16* SplitL, int lds, int scol)
{
    int tid = threadIdx.x;
    int warp = tid >> 5, lane = tid & 31;
    int wm = warp & 1, wn = warp >> 1;
    int g = lane >> 2, q = lane & 3;
    int m0 = blockIdx.y * 128, n0 = blockIdx.x * 128;

    float acc[4][4][4];
    #pragma unroll
    for (int i = 0; i < 4; i++)
        #pragma unroll
        for (int j = 0; j < 4; j++)
            #pragma unroll
            for (int t = 0; t < 4; t++) acc[i][j][t] = 0.f;

    mma_mainloop(Ahi, Alo, lda, Bhi, Blo, K, M, K, smem, m0, n0, acc);

    #pragma unroll
    for (int nf = 0; nf < 4; nf++) {
        int col = n0 + wn * 32 + nf * 8 + q * 2;
        float bv0 = 0.f, bv1 = 0.f;
        if (BIAS) { bv0 = __ldg(bias + col); bv1 = __ldg(bias + col + 1); }
        #pragma unroll
        for (int mf = 0; mf < 4; mf++) {
            int r = m0 + wm * 64 + mf * 16 + g;
            float v0 = acc[mf][nf][0] + bv0, v1 = acc[mf][nf][1] + bv1;
            float v2 = acc[mf][nf][2] + bv0, v3 = acc[mf][nf][3] + bv1;
            if (RELU) {
                v0 = fmaxf(v0, 0.f); v1 = fmaxf(v1, 0.f);
                v2 = fmaxf(v2, 0.f); v3 = fmaxf(v3, 0.f);
            }
            if (r < M) {
                *(float2*)&C[(size_t)r * ldc + col] = make_float2(v0, v1);
                if (SPLIT) {
                    SplitH[(size_t)r * lds + scol + col]     = __float2bfloat16(v0);
                    SplitH[(size_t)r * lds + scol + col + 1] = __float2bfloat16(v1);
                    float l0 = v0 - __bfloat162float(__float2bfloat16(v0));
                    float l1 = v1 - __bfloat162float(__float2bfloat16(v1));
                    SplitL[(size_t)r * lds + scol + col]     = __float2bfloat16(l0);
                    SplitL[(size_t)r * lds + scol + col + 1] = __float2bfloat16(l1);
                }
            }
            if (r + 8 < M) {
                *(float2*)&C[(size_t)(r + 8) * ldc + col] = make_float2(v2, v3);
                if (SPLIT) {
                    SplitH[(size_t)(r + 8) * lds + scol + col]     = __float2bfloat16(v2);
                    SplitH[(size_t)(r + 8) * lds + scol + col + 1] = __float2bfloat16(v3);
                    float l2 = v2 - __bfloat162float(__float2bfloat16(v2));
                    float l3 = v3 - __bfloat162float(__float2bfloat16(v3));
                    SplitL[(size_t)(r + 8) * lds + scol + col]     = __float2bfloat16(l2);
                    SplitL[(size_t)(r + 8) * lds + scol + col + 1] = __float2bfloat16(l3);
                }
            }
        }
    }
}

template <bool BIAS, bool RELU>
__global__ __launch_bounds__(256, 2) void k_mma_gemm(
    const __nv_bfloat16* __restrict__ Ahi, const __nv_bfloat16* __restrict__ Alo, int lda,
    const __nv_bfloat16* __restrict__ Bhi, const __nv_bfloat16* __restrict__ Blo,
    const float* __restrict__ bias, float* __restrict__ C, int ldc,
    int M, int K)
{
    extern __shared__ char smem[];
    mma_gemm_body<BIAS, RELU, false>(Ahi, Alo, lda, Bhi, Blo, bias, C, ldc, M, K, smem,
                                     nullptr, nullptr, 0, 0);
}

__global__ __launch_bounds__(256, 2) void k_mma_gemm_split(
    const __nv_bfloat16* __restrict__ Ahi, const __nv_bfloat16* __restrict__ Alo, int lda,
    const __nv_bfloat16* __restrict__ Bhi, const __nv_bfloat16* __restrict__ Blo,
    const float* __restrict__ bias, float* __restrict__ C, int ldc,
    int M, int K,
    __nv_bfloat16* SplitH, __nv_bfloat16* SplitL, int lds, int scol)
{
    extern __shared__ char smem[];
    mma_gemm_body<true, true, true>(Ahi, Alo, lda, Bhi, Blo, bias, C, ldc, M, K, smem,
                                    SplitH, SplitL, lds, scol);
}

__global__ __launch_bounds__(256, 2) void k_mma_gemm_dual(
    const __nv_bfloat16* __restrict__ Ahi0, const __nv_bfloat16* __restrict__ Alo0,
    const __nv_bfloat16* __restrict__ Ahi1, const __nv_bfloat16* __restrict__ Alo1, int lda,
    const __nv_bfloat16* __restrict__ Bhi0, const __nv_bfloat16* __restrict__ Blo0,
    const __nv_bfloat16* __restrict__ Bhi1, const __nv_bfloat16* __restrict__ Blo1,
    const float* __restrict__ bias0, const float* __restrict__ bias1,
    float* __restrict__ C0, float* __restrict__ C1, int ldc,
    int M, int K)
{
    extern __shared__ char smem[];
    if (blockIdx.z == 0)
        mma_gemm_body<true, false, false>(Ahi0, Alo0, lda, Bhi0, Blo0, bias0, C0, ldc, M, K, smem,
                                          nullptr, nullptr, 0, 0);
    else
        mma_gemm_body<true, false, false>(Ahi1, Alo1, lda, Bhi1, Blo1, bias1, C1, ldc, M, K, smem,
                                          nullptr, nullptr, 0, 0);
}

// split-K GEMM: z-slice computes partial over K window [z*Kloc, (z+1)*Kloc), stores fp32 partials
__global__ __launch_bounds__(256, 2) void k_mma_gemm_splitk(
    const __nv_bfloat16* __restrict__ Ahi, const __nv_bfloat16* __restrict__ Alo, int lda,
    const __nv_bfloat16* __restrict__ Bhi, const __nv_bfloat16* __restrict__ Blo, int ldb,
    float* __restrict__ part, int M, int N, int Kloc)
{
    extern __shared__ char smem[];
    int z = blockIdx.z;
    const __nv_bfloat16* Ah = Ahi + (size_t)z * Kloc;
    const __nv_bfloat16* Al = Alo + (size_t)z * Kloc;
    const __nv_bfloat16* Bh = Bhi + (size_t)z * Kloc;
    const __nv_bfloat16* Bl = Blo + (size_t)z * Kloc;
    float* C = part + (size_t)z * M * N;

    int tid = threadIdx.x;
    int warp = tid >> 5, lane = tid & 31;
    int wm = warp & 1, wn = warp >> 1;
    int g = lane >> 2, q = lane & 3;
    int m0 = blockIdx.y * 128, n0 = blockIdx.x * 128;

    float acc[4][4][4];
    #pragma unroll
    for (int i = 0; i < 4; i++)
        #pragma unroll
        for (int j = 0; j < 4; j++)
            #pragma unroll
            for (int t = 0; t < 4; t++) acc[i][j][t] = 0.f;

    mma_mainloop(Ah, Al, lda, Bh, Bl, ldb, M, Kloc, smem, m0, n0, acc);

    #pragma unroll
    for (int nf = 0; nf < 4; nf++) {
        int col = n0 + wn * 32 + nf * 8 + q * 2;
        #pragma unroll
        for (int mf = 0; mf < 4; mf++) {
            int r = m0 + wm * 64 + mf * 16 + g;
            if (r < M)
                *(float2*)&C[(size_t)r * N + col] = make_float2(acc[mf][nf][0], acc[mf][nf][1]);
            if (r + 8 < M)
                *(float2*)&C[(size_t)(r + 8) * N + col] = make_float2(acc[mf][nf][2], acc[mf][nf][3]);
        }
    }
}

// reduce 4 split-K partials + bias + relu
__global__ void k_red_splitk(const float* __restrict__ part, const float* __restrict__ bias,
                             float* __restrict__ C, int M, int N) {
    int idx = blockIdx.x * blockDim.x + threadIdx.x;
    if (idx < M * N) {
        int col = idx % N;
        size_t MN = (size_t)M * N;
        float s = part[idx] + part[MN + idx] + part[2 * MN + idx] + part[3 * MN + idx]
                + bias[col];
        C[idx] = fmaxf(s, 0.f);
    }
}

// fusion GEMM with fused per-bbox max epilogue (no [NN,1024] materialization).
__global__ __launch_bounds__(256, 2) void k_mma_gemm_pool(
    const __nv_bfloat16* __restrict__ Ahi, const __nv_bfloat16* __restrict__ Alo, int lda,
    const __nv_bfloat16* __restrict__ Bhi, const __nv_bfloat16* __restrict__ Blo,
    const float* __restrict__ bias, const int* __restrict__ bbox_idx,
    int M, int K)
{
    extern __shared__ char smem[];
    int tid = threadIdx.x;
    int warp = tid >> 5, lane = tid & 31;
    int wm = warp & 1, wn = warp >> 1;
    int g = lane >> 2, q = lane & 3;
    int m0 = blockIdx.y * 128, n0 = blockIdx.x * 128;

    float acc[4][4][4];
    #pragma unroll
    for (int i = 0; i < 4; i++)
        #pragma unroll
        for (int j = 0; j < 4; j++)
            #pragma unroll
            for (int t = 0; t < 4; t++) acc[i][j][t] = 0.f;

    mma_mainloop(Ahi, Alo, lda, Bhi, Blo, K, M, K, smem, m0, n0, acc);

    float v[4][4][4];
    #pragma unroll
    for (int nf = 0; nf < 4; nf++) {
        int col = n0 + wn * 32 + nf * 8 + q * 2;
        float bv0 = __ldg(bias + col), bv1 = __ldg(bias + col + 1);
        #pragma unroll
        for (int mf = 0; mf < 4; mf++) {
            v[mf][nf][0] = fmaxf(acc[mf][nf][0] + bv0, 0.f);
            v[mf][nf][1] = fmaxf(acc[mf][nf][1] + bv1, 0.f);
            v[mf][nf][2] = fmaxf(acc[mf][nf][2] + bv0, 0.f);
            v[mf][nf][3] = fmaxf(acc[mf][nf][3] + bv1, 0.f);
        }
    }

    int* segbuf = (int*)smem;
    __shared__ int s_blo, s_bhi;
    int mmax = min(m0 + 127, M - 1);
    if (tid == 0) { s_blo = bbox_idx[m0]; s_bhi = bbox_idx[mmax]; }
    __syncthreads();
    int blo = s_blo, bhi = s_bhi;

    int rb[4][2];
    #pragma unroll
    for (int mf = 0; mf < 4; mf++) {
        int r = m0 + wm * 64 + mf * 16 + g;
        rb[mf][0] = (r < M) ? bbox_idx[r] : -1;
        rb[mf][1] = (r + 8 < M) ? bbox_idx[r + 8] : -1;
    }

    for (int base = blo; base <= bhi; base += 128) {
        int wlen = min(128, bhi - base + 1);
        for (int i = tid; i < wlen * 128; i += 256) segbuf[i] = 0;
        __syncthreads();
        #pragma unroll
        for (int mf = 0; mf < 4; mf++) {
            #pragma unroll
            for (int half = 0; half < 2; half++) {
                int s = rb[mf][half] - base;
                if (s >= 0 && s < wlen) {
                    #pragma unroll
                    for (int nf = 0; nf < 4; nf++) {
                        int j = wn * 32 + nf * 8 + q * 2;
                        atomicMax(&segbuf[s * 128 + j],     __float_as_int(v[mf][nf][half * 2]));
                        atomicMax(&segbuf[s * 128 + j + 1], __float_as_int(v[mf][nf][half * 2 + 1]));
                    }
                }
            }
        }
        __syncthreads();
        for (int i = tid; i < wlen * 128; i += 256) {
            int bits = segbuf[i];
            if (bits != 0) {
                int b = base + (i >> 7);
                int col = n0 + (i & 127);
                atomicMax((unsigned int*)&g_big[(size_t)b * 2816 + col], (unsigned int)bits);
            }
        }
        __syncthreads();
    }
}

// ---------------- fp32 SIMT GEMMs ----------------
template <bool BIAS, bool RELU>
__device__ __forceinline__ void gemm128_body(
    const float* __restrict__ A, int lda, const float* __restrict__ B, int ldb,
    const float* __restrict__ bias, float* __restrict__ C, int ldc,
    int M, int N, int K)
{
    __shared__ float As[8][128];
    __shared__ float Bs[8][128];
    int tid = threadIdx.x;
    int m0 = blockIdx.y * 128, n0 = blockIdx.x * 128;
    int ar = tid >> 1, ac = (tid & 1) * 4;
    int bk = tid >> 5, bn = (tid & 31) * 4;
    int ty = tid >> 4, tx = tid & 15;
    float acc[8][8] = {};
    for (int k0 = 0; k0 < K; k0 += 8) {
        float4 av = make_float4(0.f, 0.f, 0.f, 0.f);
        if (m0 + ar < M) av = *(const float4*)&A[(size_t)(m0 + ar) * lda + k0 + ac];
        As[ac + 0][ar] = av.x; As[ac + 1][ar] = av.y; As[ac + 2][ar] = av.z; As[ac + 3][ar] = av.w;
        float4 bv = make_float4(0.f, 0.f, 0.f, 0.f);
        if (n0 + bn < N) bv = *(const float4*)&B[(size_t)(k0 + bk) * ldb + n0 + bn];
        *(float4*)&Bs[bk][bn] = bv;
        __syncthreads();
        #pragma unroll
        for (int kk = 0; kk < 8; kk++) {
            float a[8], b[8];
            #pragma unroll
            for (int i = 0; i < 8; i++) a[i] = As[kk][ty * 8 + i];
            #pragma unroll
            for (int j = 0; j < 8; j++) b[j] = Bs[kk][tx * 8 + j];
            #pragma unroll
            for (int i = 0; i < 8; i++)
                #pragma unroll
                for (int j = 0; j < 8; j++)
                    acc[i][j] += a[i] * b[j];
        }
        __syncthreads();
    }
    #pragma unroll
    for (int i = 0; i < 8; i++) {
        int m = m0 + ty * 8 + i;
        if (m < M) {
            #pragma unroll
            for (int j = 0; j < 8; j++) {
                int n = n0 + tx * 8 + j;
                if (n < N) {
                    float v = acc[i][j];
                    if (BIAS) v += bias[n];
                    if (RELU) v = fmaxf(v, 0.f);
                    C[(size_t)m * ldc + n] = v;
                }
            }
        }
    }
}

// layer0 dual: z selects weight/bias/output set (same A)
__global__ __launch_bounds__(256) void k_gemm128_dual(
    const float* __restrict__ A, int lda,
    const float* __restrict__ B0, const float* __restrict__ B1, int ldb,
    const float* __restrict__ bias0, const float* __restrict__ bias1,
    float* __restrict__ C0, float* __restrict__ C1, int ldc,
    int M, int N, int K)
{
    if (blockIdx.z == 0)
        gemm128_body<true, false>(A, lda, B0, ldb, bias0, C0, ldc, M, N, K);
    else
        gemm128_body<true, false>(A, lda, B1, ldb, bias1, C1, ldc, M, N, K);
}

template <bool BIAS, bool RELU>
__global__ __launch_bounds__(256) void k_gemm64(
    const float* __restrict__ A, int lda, const float* __restrict__ B, int ldb,
    const float* __restrict__ bias, float* __restrict__ C, int ldc,
    int M, int N, int K)
{
    __shared__ float As[16][64];
    __shared__ float Bs[16][64];
    int tid = threadIdx.x;
    int m0 = blockIdx.y * 64, n0 = blockIdx.x * 64;
    int ar = tid >> 2, ac = (tid & 3) * 4;
    int bk = tid >> 4, bn = (tid & 15) * 4;
    int ty = tid >> 4, tx = tid & 15;
    float acc[4][4] = {};
    for (int k0 = 0; k0 < K; k0 += 16) {
        float4 av = make_float4(0.f, 0.f, 0.f, 0.f);
        if (m0 + ar < M) av = *(const float4*)&A[(size_t)(m0 + ar) * lda + k0 + ac];
        As[ac + 0][ar] = av.x; As[ac + 1][ar] = av.y; As[ac + 2][ar] = av.z; As[ac + 3][ar] = av.w;
        float4 bv = make_float4(0.f, 0.f, 0.f, 0.f);
        if (n0 + bn < N) bv = *(const float4*)&B[(size_t)(k0 + bk) * ldb + n0 + bn];
        *(float4*)&Bs[bk][bn] = bv;
        __syncthreads();
        #pragma unroll
        for (int kk = 0; kk < 16; kk++) {
            float a[4], b[4];
            #pragma unroll
            for (int i = 0; i < 4; i++) a[i] = As[kk][ty * 4 + i];
            #pragma unroll
            for (int j = 0; j < 4; j++) b[j] = Bs[kk][tx * 4 + j];
            #pragma unroll
            for (int i = 0; i < 4; i++)
                #pragma unroll
                for (int j = 0; j < 4; j++)
                    acc[i][j] += a[i] * b[j];
        }
        __syncthreads();
    }
    #pragma unroll
    for (int i = 0; i < 4; i++) {
        int m = m0 + ty * 4 + i;
        if (m < M) {
            #pragma unroll
            for (int j = 0; j < 4; j++) {
                int n = n0 + tx * 4 + j;
                if (n < N) {
                    float v = acc[i][j];
                    if (BIAS) v += bias[n];
                    if (RELU) v = fmaxf(v, 0.f);
                    C[(size_t)m * ldc + n] = v;
                }
            }
        }
    }
}

// ---------------- fused edge conv (frozen body) + residual + bf16 split ----------------
__global__ __launch_bounds__(256) void k_edgeconv(
    const float* __restrict__ e_attr,
    const float* __restrict__ W3n, const float* __restrict__ W3s,
    const float* __restrict__ PQ, const float* __restrict__ PQs,
    const float* __restrict__ prevN, const float* __restrict__ prevS,
    float* __restrict__ outN, float* __restrict__ outS,
    __nv_bfloat16* __restrict__ outNh, __nv_bfloat16* __restrict__ outNl,
    __nv_bfloat16* __restrict__ outSh, __nv_bfloat16* __restrict__ outSl)
{
    __shared__ float sW3n[768];
    __shared__ float sW3s[768];
    for (int i = threadIdx.x; i < 768; i += blockDim.x) { sW3n[i] = W3n[i]; sW3s[i] = W3s[i]; }
    __syncthreads();
    int warp = threadIdx.x >> 5, lane = threadIdx.x & 31;
    int node = blockIdx.x * (blockDim.x >> 5) + warp;
    if (node >= NN) return;
    int r0 = g_rowptr[node], r1 = g_rowptr[node + 1];
    int c = lane * 4;
    float4 qn = *(const float4*)(PQ  + node * 256 + 128 + c);
    float4 qs = *(const float4*)(PQs + node * 256 + 128 + c);
    float mx0 = 0.f, mx1 = 0.f, mx2 = 0.f, mx3 = 0.f;
    float sm0 = 0.f, sm1 = 0.f, sm2 = 0.f, sm3 = 0.f;
    for (int e = r0; e < r1; ++e) {
        int s  = g_csr_src[e];
        int id = g_csr_eid[e];
        float4 p  = *(const float4*)(PQ  + s * 256 + c);
        float4 ps = *(const float4*)(PQs + s * 256 + c);
        float a0 = p.x + qn.x, a1 = p.y + qn.y, a2 = p.z + qn.z, a3 = p.w + qn.w;
        float b0 = ps.x + qs.x, b1 = ps.y + qs.y, b2 = ps.z + qs.z, b3 = ps.w + qs.w;
        #pragma unroll
        for (int k = 0; k < 6; k++) {
            float ev = __ldg(e_attr + (size_t)id * 6 + k);
            const float* wn = sW3n + k * 128 + c;
            const float* ws = sW3s + k * 128 + c;
            a0 += ev * wn[0]; a1 += ev * wn[1]; a2 += ev * wn[2]; a3 += ev * wn[3];
            b0 += ev * ws[0]; b1 += ev * ws[1]; b2 += ev * ws[2]; b3 += ev * ws[3];
        }
        a0 = fmaxf(a0, 0.f); a1 = fmaxf(a1, 0.f); a2 = fmaxf(a2, 0.f); a3 = fmaxf(a3, 0.f);
        mx0 = fmaxf(mx0, a0); mx1 = fmaxf(mx1, a1); mx2 = fmaxf(mx2, a2); mx3 = fmaxf(mx3, a3);
        b0 = fmaxf(b0, 0.f); b1 = fmaxf(b1, 0.f); b2 = fmaxf(b2, 0.f); b3 = fmaxf(b3, 0.f);
        sm0 += b0; sm1 += b1; sm2 += b2; sm3 += b3;
    }
    int deg = r1 - r0;
    float inv = 1.f / (float)(deg > 0 ? deg : 1);
    float f0 = mx0, f1 = mx1, f2 = mx2, f3 = mx3;
    float s0 = sm0 * inv, s1 = sm1 * inv, s2 = sm2 * inv, s3 = sm3 * inv;
    if (prevN) {
        float4 pn = *(const float4*)(prevN + node * 384 + c);
        f0 += pn.x; f1 += pn.y; f2 += pn.z; f3 += pn.w;
        float4 pv = *(const float4*)(prevS + node * 384 + c);
        s0 += pv.x; s1 += pv.y; s2 += pv.z; s3 += pv.w;
    }
    *(float4*)(outN + node * 384 + c) = make_float4(f0, f1, f2, f3);
    *(float4*)(outS + node * 384 + c) = make_float4(s0, s1, s2, s3);
    uint2 u;
    u.x = bfpack(f0, f1); u.y = bfpack(f2, f3);
    *(uint2*)(outNh + node * 384 + c) = u;
    float r0f = f0 - __bfloat162float(__float2bfloat16(f0));
    float r1f = f1 - __bfloat162float(__float2bfloat16(f1));
    float r2f = f2 - __bfloat162float(__float2bfloat16(f2));
    float r3f = f3 - __bfloat162float(__float2bfloat16(f3));
    u.x = bfpack(r0f, r1f); u.y = bfpack(r2f, r3f);
    *(uint2*)(outNl + node * 384 + c) = u;
    u.x = bfpack(s0, s1); u.y = bfpack(s2, s3);
    *(uint2*)(outSh + node * 384 + c) = u;
    r0f = s0 - __bfloat162float(__float2bfloat16(s0));
    r1f = s1 - __bfloat162float(__float2bfloat16(s1));
    r2f = s2 - __bfloat162float(__float2bfloat16(s2));
    r3f = s3 - __bfloat162float(__float2bfloat16(s3));
    u.x = bfpack(r0f, r1f); u.y = bfpack(r2f, r3f);
    *(uint2*)(outSl + node * 384 + c) = u;
}

// ---------------- combined bbox pooling ----------------
__global__ void k_pool_both() {
    int blk = blockIdx.x;
    if (blk < NBB) {
        int b = blk;
        int c = threadIdx.x;            // blockDim = 384
        int r0 = g_bboxptr[b], r1 = g_bboxptr[b + 1];
        float s = 0.f;
        for (int n = r0; n < r1; n++) s += g_featsS[n * 384 + c];
        int cnt = r1 - r0;
        float v = s / (float)(cnt > 0 ? cnt : 1);
        g_big[b * 2816 + 2432 + c] = v;
        __nv_bfloat16 h = __float2bfloat16(v);
        __nv_bfloat16 l = __float2bfloat16(v - __bfloat162float(h));
        g_Sh[b * 384 + c] = h;
        g_Sl[b * 384 + c] = l;
        g_Mh[b * 2816 + 2432 + c] = h;
        g_Ml[b * 2816 + 2432 + c] = l;
    } else {
        int b = blk - NBB;
        int r0 = g_bboxptr[b], r1 = g_bboxptr[b + 1];
        for (int c = threadIdx.x; c < 1408; c += blockDim.x) {
            float m;
            if (c < 1024) {
                m = g_big[b * 2816 + c];    // atomicMax result (0 if empty)
            } else {
                m = -FLT_MAX;
                int cc = c - 1024;
                for (int n = r0; n < r1; n++) m = fmaxf(m, g_feats[n * 384 + cc]);
                if (r1 == r0) m = 0.f;
                g_big[b * 2816 + c] = m;
            }
            __nv_bfloat16 h = __float2bfloat16(m);
            g_Mh[b * 2816 + c] = h;
            g_Ml[b * 2816 + c] = __float2bfloat16(m - __bfloat162float(h));
        }
    }
}

// ---------------- launch ----------------
extern "C" void kernel_launch(void* const* d_in, const int* in_sizes, int n_in,
                              void* d_out, int out_size)
{
    const float* x     = (const float*)d_in[0];
    const float* eat   = (const float*)d_in[1];
    const float* W_h   = (const float*)d_in[2];
    const float* b_h   = (const float*)d_in[3];
    const float* Ws_h  = (const float*)d_in[4];
    const float* bs_h  = (const float*)d_in[5];
    const float* Wb    = (const float*)d_in[6];
    const float* bb    = (const float*)d_in[7];
    const float* Wbs   = (const float*)d_in[8];
    const float* bbs   = (const float*)d_in[9];
    const float* W_f   = (const float*)d_in[10];
    const float* b_f   = (const float*)d_in[11];
    const float* W_fs  = (const float*)d_in[12];
    const float* b_fs  = (const float*)d_in[13];
    const float* W1    = (const float*)d_in[14];
    const float* b1    = (const float*)d_in[15];
    const float* W2    = (const float*)d_in[16];
    const float* b2    = (const float*)d_in[17];
    const float* W3c   = (const float*)d_in[18];
    const float* b3    = (const float*)d_in[19];
    const int*   edge  = (const int*)d_in[20];
    const int*   bbox  = (const int*)d_in[21];
    const int* src = edge;
    const int* dst = edge + NE;
    float* out = (float*)d_out;

    float *pFeats, *pFeatsS, *pPQ, *pPQs, *pBig, *pH1, *pH2, *pPart, *pWcn, *pWcs, *pb256h, *pb256;
    __nv_bfloat16 *pAh, *pAl, *pSh, *pSl, *pMh, *pMl;
    __nv_bfloat16 *pBfh, *pBfl, *pBfsh, *pBfsl, *pB1h, *pB1l, *pwbh, *pwbl;
    int *pHist;
    cudaGetSymbolAddress((void**)&pFeats,  g_feats);
    cudaGetSymbolAddress((void**)&pFeatsS, g_featsS);
    cudaGetSymbolAddress((void**)&pPQ,  g_PQ);
    cudaGetSymbolAddress((void**)&pPQs, g_PQs);
    cudaGetSymbolAddress((void**)&pBig, g_big);
    cudaGetSymbolAddress((void**)&pH1,  g_h1);
    cudaGetSymbolAddress((void**)&pH2,  g_h2);
    cudaGetSymbolAddress((void**)&pPart, g_part);
    cudaGetSymbolAddress((void**)&pWcn, g_Wcn);
    cudaGetSymbolAddress((void**)&pWcs, g_Wcs);
    cudaGetSymbolAddress((void**)&pb256h, g_b256h);
    cudaGetSymbolAddress((void**)&pb256, g_b256);
    cudaGetSymbolAddress((void**)&pHist, g_hist);
    cudaGetSymbolAddress((void**)&pAh, g_Ah);
    cudaGetSymbolAddress((void**)&pAl, g_Al);
    cudaGetSymbolAddress((void**)&pSh, g_Sh);
    cudaGetSymbolAddress((void**)&pSl, g_Sl);
    cudaGetSymbolAddress((void**)&pMh, g_Mh);
    cudaGetSymbolAddress((void**)&pMl, g_Ml);
    cudaGetSymbolAddress((void**)&pBfh, g_Bfh);
    cudaGetSymbolAddress((void**)&pBfl, g_Bfl);
    cudaGetSymbolAddress((void**)&pBfsh, g_Bfsh);
    cudaGetSymbolAddress((void**)&pBfsl, g_Bfsl);
    cudaGetSymbolAddress((void**)&pB1h, g_B1h);
    cudaGetSymbolAddress((void**)&pB1l, g_B1l);
    cudaGetSymbolAddress((void**)&pwbh, g_wbh);
    cudaGetSymbolAddress((void**)&pwbl, g_wbl);

    cudaFuncSetAttribute(k_mma_gemm<true, false>, cudaFuncAttributeMaxDynamicSharedMemorySize, TCSM);
    cudaFuncSetAttribute(k_mma_gemm<true, true>,  cudaFuncAttributeMaxDynamicSharedMemorySize, TCSM);
    cudaFuncSetAttribute(k_mma_gemm_dual,         cudaFuncAttributeMaxDynamicSharedMemorySize, TCSM);
    cudaFuncSetAttribute(k_mma_gemm_split,        cudaFuncAttributeMaxDynamicSharedMemorySize, TCSM);
    cudaFuncSetAttribute(k_mma_gemm_pool,         cudaFuncAttributeMaxDynamicSharedMemorySize, TCSM);
    cudaFuncSetAttribute(k_mma_gemm_splitk,       cudaFuncAttributeMaxDynamicSharedMemorySize, TCSM);

    // zero-init hist + g_big (fusion-max atomic targets need 0)
    cudaMemsetAsync(pHist, 0, NN * sizeof(int), 0);
    cudaMemsetAsync(pBig, 0, (size_t)NBB * 2816 * sizeof(float), 0);

    // CSR by dst + bbox ranges (bboxptr folded into scan3)
    k_count<<<(NE + 255) / 256, 256>>>(dst);
    int nblk = (NN + 255) / 256;
    k_scan1<<<nblk, 256>>>();
    k_scan2<<<1, 256>>>(nblk);
    k_scan3<<<nblk, 256>>>(bbox);
    k_fill<<<(NE + 255) / 256, 256>>>(src, dst);

    // merged weight preps (3 launches total)
    {
        dim3 gw(5632, 1, 3);
        k_wsplit3<<<gw, 256>>>(W_f, W_fs, W1);
        dim3 gp(128, 1, 4);
        k_prep_layerW_all<<<gp, 256>>>(Wb, bb, Wbs, bbs);
        dim3 gh(8, 1, 2);
        k_prep_head_dual<<<gh, 256>>>(W_h, b_h, Ws_h, bs_h);
    }

    // ---- layer 0 (inC=8) ----
    {
        dim3 g1(2, (NN + 127) / 128, 2);
        k_gemm128_dual<<<g1, 256>>>(x, 8, pWcn, pWcs, 256, pb256h, pb256h + 256,
                                    pPQ, pPQs, 256, NN, 256, 8);
        k_edgeconv<<<(NN + 7) / 8, 256>>>(eat, W_h + 2048, Ws_h + 2048,
                                          pPQ, pPQs, nullptr, nullptr,
                                          pFeats, pFeatsS,
                                          pAh, pAl, pSh, pSl);
    }

    // ---- layers 1,2: split-bf16 HMMA (node+super merged) ----
    for (int i = 1; i < 3; i++) {
        const float* W  = Wb  + (size_t)(i - 1) * 262 * 128;
        const float* Ws = Wbs + (size_t)(i - 1) * 262 * 128;
        const int nW = 256 * 128;
        int z0 = 2 * (i - 1);

        dim3 gl(2, (NN + 127) / 128, 2);
        k_mma_gemm_dual<<<gl, 256, TCSM>>>(
            pAh + (i - 1) * 128, pAl + (i - 1) * 128,
            pSh + (i - 1) * 128, pSl + (i - 1) * 128, 384,
            pwbh + (size_t)z0 * nW, pwbl + (size_t)z0 * nW,
            pwbh + (size_t)(z0 + 1) * nW, pwbl + (size_t)(z0 + 1) * nW,
            pb256 + z0 * 256, pb256 + (z0 + 1) * 256,
            pPQ, pPQs, 256, NN, 128);

        k_edgeconv<<<(NN + 7) / 8, 256>>>(eat, W + 2 * 128 * 128, Ws + 2 * 128 * 128,
                                          pPQ, pPQs,
                                          pFeats + (i - 1) * 128, pFeatsS + (i - 1) * 128,
                                          pFeats + i * 128, pFeatsS + i * 128,
                                          pAh + i * 128, pAl + i * 128,
                                          pSh + i * 128, pSl + i * 128);
    }

    // ---- fusion GEMM + fused bbox max (no [NN,1024] buffer) ----
    {
        dim3 g(8, (NN + 127) / 128);
        k_mma_gemm_pool<<<g, 256, TCSM>>>(pAh, pAl, 384, pBfh, pBfl, b_f, bbox, NN, 384);
    }

    // ---- bbox pooling: super mean + fusion-max convert + feats max ----
    k_pool_both<<<2 * NBB, 384>>>();

    // ---- fusion_super (split epilogue feeds MLP input cols [1408, 2432)) ----
    {
        dim3 g(8, (NBB + 127) / 128);
        k_mma_gemm_split<<<g, 256, TCSM>>>(pSh, pSl, 384, pBfsh, pBfsl, b_fs,
                                           pBig + 1408, 2816, NBB, 384,
                                           pMh, pMl, 2816, 1408);
    }

    // ---- MLP head: W1 via split-K=4 (K=2816 -> 4 x 704), then reduce ----
    {
        dim3 g(4, (NBB + 127) / 128, 4);
        k_mma_gemm_splitk<<<g, 256, TCSM>>>(pMh, pMl, 2816, pB1h, pB1l, 2816,
                                            pPart, NBB, 512, 704);
        k_red_splitk<<<(NBB * 512 + 255) / 256, 256>>>(pPart, b1, pH1, NBB, 512);
    }
    dim3 gm2(4, (NBB + 63) / 64);
    k_gemm64<true, true><<<gm2, 256>>>(pH1, 512, W2, 256, b2, pH2, 256, NBB, 256, 512);
    dim3 gm3(1, (NBB + 63) / 64);
    k_gemm64<true, false><<<gm3, 256>>>(pH2, 256, W3c, 32, b3, out, 32, NBB, 32, 256);
}